// round 1
// baseline (speedup 1.0000x reference)
#include <cuda_runtime.h>
#include <math.h>

#define BB 2
#define SS 2048
#define DD 2048
#define H 16
#define HK 8
#define HD 128
#define MTOT (BB*SS)   // 4096

// ---------------- scratch (allocation-free: device globals) ----------------
__device__ float g_q[(size_t)MTOT * H * HD];   // 33.5 MB
__device__ float g_k[(size_t)MTOT * HK * HD];  // 16.8 MB
__device__ float g_v[(size_t)MTOT * HK * HD];  // 16.8 MB
__device__ float g_o[(size_t)MTOT * H * HD];   // 33.5 MB
__device__ float g_cos[SS * 64];
__device__ float g_sin[SS * 64];

// ---------------- SGEMM: C[m][n] = sum_k A[m][k] * W[n][k] -----------------
// A: (M,K) row-major, W: (N,K) row-major, C: (M,N) row-major.
// 128x128 tile, BK=16, 256 threads, 8x8 per thread (2x2 quadrants of 4x4).
__global__ __launch_bounds__(256, 2)
void sgemm_nt(const float* __restrict__ A, const float* __restrict__ W,
              float* __restrict__ C, int M, int N, int K)
{
    __shared__ float As[16][132];
    __shared__ float Bs[16][132];

    const int t   = threadIdx.x;
    const int txx = t & 15;
    const int tyy = t >> 4;
    const int lr  = t >> 2;          // 0..63
    const int lc  = (t & 3) << 2;    // 0,4,8,12

    const int m0 = blockIdx.y * 128;
    const int n0 = blockIdx.x * 128;

    const float* Aptr = A + (size_t)(m0 + lr) * K + lc;
    const float* Wptr = W + (size_t)(n0 + lr) * K + lc;

    float acc[8][8];
    #pragma unroll
    for (int i = 0; i < 8; i++)
        #pragma unroll
        for (int j = 0; j < 8; j++) acc[i][j] = 0.f;

    for (int k0 = 0; k0 < K; k0 += 16) {
        float4 a0 = *(const float4*)(Aptr + k0);
        float4 a1 = *(const float4*)(Aptr + (size_t)64 * K + k0);
        float4 b0 = *(const float4*)(Wptr + k0);
        float4 b1 = *(const float4*)(Wptr + (size_t)64 * K + k0);
        __syncthreads();
        As[lc+0][lr]    = a0.x; As[lc+1][lr]    = a0.y; As[lc+2][lr]    = a0.z; As[lc+3][lr]    = a0.w;
        As[lc+0][lr+64] = a1.x; As[lc+1][lr+64] = a1.y; As[lc+2][lr+64] = a1.z; As[lc+3][lr+64] = a1.w;
        Bs[lc+0][lr]    = b0.x; Bs[lc+1][lr]    = b0.y; Bs[lc+2][lr]    = b0.z; Bs[lc+3][lr]    = b0.w;
        Bs[lc+0][lr+64] = b1.x; Bs[lc+1][lr+64] = b1.y; Bs[lc+2][lr+64] = b1.z; Bs[lc+3][lr+64] = b1.w;
        __syncthreads();
        #pragma unroll
        for (int kk = 0; kk < 16; kk++) {
            float4 av0 = *(const float4*)&As[kk][tyy*4];
            float4 av1 = *(const float4*)&As[kk][tyy*4+64];
            float4 bv0 = *(const float4*)&Bs[kk][txx*4];
            float4 bv1 = *(const float4*)&Bs[kk][txx*4+64];
            float av[8] = {av0.x,av0.y,av0.z,av0.w,av1.x,av1.y,av1.z,av1.w};
            float bv[8] = {bv0.x,bv0.y,bv0.z,bv0.w,bv1.x,bv1.y,bv1.z,bv1.w};
            #pragma unroll
            for (int i = 0; i < 8; i++)
                #pragma unroll
                for (int j = 0; j < 8; j++)
                    acc[i][j] += av[i] * bv[j];
        }
    }

    #pragma unroll
    for (int i = 0; i < 8; i++) {
        int row = m0 + tyy*4 + (i & 3) + ((i >= 4) ? 64 : 0);
        float4 s0 = make_float4(acc[i][0], acc[i][1], acc[i][2], acc[i][3]);
        float4 s1 = make_float4(acc[i][4], acc[i][5], acc[i][6], acc[i][7]);
        *(float4*)(C + (size_t)row * N + n0 + txx*4)      = s0;
        *(float4*)(C + (size_t)row * N + n0 + txx*4 + 64) = s1;
    }
}

// ---------------- RoPE table: cos/sin[s][j], j=0..63 -----------------------
__global__ void rope_table()
{
    int s = blockIdx.x;
    int j = threadIdx.x;  // 0..63
    double invd = pow(1.0e6, -(double)j / 64.0);
    float  invf = (float)invd;
    float  ang  = (float)s * invf;      // fp32 multiply, matching reference
    float  c, sn;
    sincosf(ang, &sn, &c);
    g_cos[s*64 + j] = c;
    g_sin[s*64 + j] = sn;
}

// ---------------- fused RMSNorm + RoPE (one warp per (token, head)) --------
__global__ __launch_bounds__(256)
void norm_rope(float* __restrict__ buf, const float* __restrict__ w, int nheads)
{
    int gw   = (blockIdx.x * blockDim.x + threadIdx.x) >> 5;
    int lane = threadIdx.x & 31;
    int m = gw / nheads;
    int h = gw - m * nheads;
    int s = m & (SS - 1);

    float* p = buf + ((size_t)m * nheads + h) * HD;
    float4 v = *(float4*)(p + lane*4);
    float ss = v.x*v.x + v.y*v.y + v.z*v.z + v.w*v.w;
    #pragma unroll
    for (int o = 16; o; o >>= 1) ss += __shfl_xor_sync(0xffffffffu, ss, o);
    float r = rsqrtf(ss * (1.f/128.f) + 1e-6f);

    const float4 wv = *(const float4*)(w + lane*4);
    v.x *= r * wv.x; v.y *= r * wv.y; v.z *= r * wv.z; v.w *= r * wv.w;

    float4 pr;
    pr.x = __shfl_xor_sync(0xffffffffu, v.x, 16);
    pr.y = __shfl_xor_sync(0xffffffffu, v.y, 16);
    pr.z = __shfl_xor_sync(0xffffffffu, v.z, 16);
    pr.w = __shfl_xor_sync(0xffffffffu, v.w, 16);

    int jbase = (lane & 15) * 4;
    const float* cb = g_cos + s*64 + jbase;
    const float* sb = g_sin + s*64 + jbase;
    float sgn = (lane < 16) ? -1.f : 1.f;

    float4 ov;
    ov.x = v.x * cb[0] + sgn * pr.x * sb[0];
    ov.y = v.y * cb[1] + sgn * pr.y * sb[1];
    ov.z = v.z * cb[2] + sgn * pr.z * sb[2];
    ov.w = v.w * cb[3] + sgn * pr.w * sb[3];
    *(float4*)(p + lane*4) = ov;
}

// ---------------- fp32 flash attention (causal, GQA rep=2) -----------------
// Block: (qtile of 64, h, b). 256 threads = 8 warps; warp w owns q rows
// w*8..w*8+7; lane owns dims lane*4..lane*4+3 of the output accumulator.
#define SM_ATT ((64*128 + 32*132 + 32*132 + 64*33) * 4)

__global__ __launch_bounds__(256)
void flash_attn(const float* __restrict__ Q, const float* __restrict__ Kg,
                const float* __restrict__ Vg, float* __restrict__ O)
{
    extern __shared__ float sm[];
    float* Qs = sm;                  // [64][128]
    float* Ks = Qs + 64*128;         // [32][132]
    float* Vs = Ks + 32*132;         // [32][132]
    float* Ps = Vs + 32*132;         // [64][33]

    const int b = blockIdx.z, h = blockIdx.y, qt = blockIdx.x;
    const int hk = h >> 1;           // H/HK = 2
    const int q0 = qt * 64;
    const int t = threadIdx.x;
    const int lane = t & 31, w = t >> 5;

    const float* qbase = Q + ((size_t)(b*SS + q0) * H + h) * HD;
    for (int idx = t; idx < 64*32; idx += 256) {
        int r = idx >> 5, c4 = (idx & 31) << 2;
        *(float4*)(Qs + r*128 + c4) = *(const float4*)(qbase + (size_t)r * (H*HD) + c4);
    }

    float m_run[8], l_run[8], acc[8][4];
    #pragma unroll
    for (int i = 0; i < 8; i++) {
        m_run[i] = -1e30f; l_run[i] = 0.f;
        acc[i][0] = acc[i][1] = acc[i][2] = acc[i][3] = 0.f;
    }

    const float* kb = Kg + ((size_t)(b*SS) * HK + hk) * HD;
    const float* vb = Vg + ((size_t)(b*SS) * HK + hk) * HD;
    const int ntiles = (q0 + 64) >> 5;
    const float scale = 0.08838834764831845f;   // 1/sqrt(128)

    for (int kt = 0; kt < ntiles; kt++) {
        __syncthreads();
        for (int idx = t; idx < 32*32; idx += 256) {
            int r = idx >> 5, c4 = (idx & 31) << 2;
            size_t g = (size_t)(kt*32 + r) * (HK*HD) + c4;
            *(float4*)(Ks + r*132 + c4) = *(const float4*)(kb + g);
            *(float4*)(Vs + r*132 + c4) = *(const float4*)(vb + g);
        }
        __syncthreads();

        // scores: lane = key column within tile
        float sc[8] = {0,0,0,0,0,0,0,0};
        #pragma unroll
        for (int db = 0; db < 32; db++) {
            float4 k4 = *(const float4*)(Ks + lane*132 + db*4);
            #pragma unroll
            for (int i = 0; i < 8; i++) {
                float4 q4 = *(const float4*)(Qs + (w*8+i)*128 + db*4);
                sc[i] += q4.x*k4.x + q4.y*k4.y + q4.z*k4.z + q4.w*k4.w;
            }
        }

        const int kidx = kt*32 + lane;
        #pragma unroll
        for (int i = 0; i < 8; i++) {
            const int qi = q0 + w*8 + i;
            bool valid = (kidx <= qi);
            float s_ = valid ? sc[i] * scale : -1e30f;
            float mt = s_;
            #pragma unroll
            for (int o = 16; o; o >>= 1) mt = fmaxf(mt, __shfl_xor_sync(0xffffffffu, mt, o));
            float mnew = fmaxf(m_run[i], mt);
            float corr = __expf(m_run[i] - mnew);
            float p = valid ? __expf(s_ - mnew) : 0.f;
            float psum = p;
            #pragma unroll
            for (int o = 16; o; o >>= 1) psum += __shfl_xor_sync(0xffffffffu, psum, o);
            l_run[i] = l_run[i] * corr + psum;
            m_run[i] = mnew;
            acc[i][0] *= corr; acc[i][1] *= corr; acc[i][2] *= corr; acc[i][3] *= corr;
            Ps[(w*8+i)*33 + lane] = p;
        }
        __syncwarp();

        // PV: lane = output dim group
        #pragma unroll
        for (int kk = 0; kk < 32; kk++) {
            float4 v4 = *(const float4*)(Vs + kk*132 + lane*4);
            #pragma unroll
            for (int i = 0; i < 8; i++) {
                float p = Ps[(w*8+i)*33 + kk];
                acc[i][0] += p * v4.x; acc[i][1] += p * v4.y;
                acc[i][2] += p * v4.z; acc[i][3] += p * v4.w;
            }
        }
        __syncwarp();
    }

    float* ob = O + ((size_t)(b*SS + q0) * H + h) * HD;
    #pragma unroll
    for (int i = 0; i < 8; i++) {
        float inv = 1.f / l_run[i];
        float4 ov = make_float4(acc[i][0]*inv, acc[i][1]*inv, acc[i][2]*inv, acc[i][3]*inv);
        *(float4*)(ob + (size_t)(w*8+i) * (H*HD) + lane*4) = ov;
    }
}

// ---------------- launch ----------------------------------------------------
extern "C" void kernel_launch(void* const* d_in, const int* in_sizes, int n_in,
                              void* d_out, int out_size)
{
    (void)in_sizes; (void)n_in; (void)out_size;
    const float* x  = (const float*)d_in[0];
    const float* wq = (const float*)d_in[1];
    const float* wk = (const float*)d_in[2];
    const float* wv = (const float*)d_in[3];
    const float* wo = (const float*)d_in[4];
    const float* qw = (const float*)d_in[5];
    const float* kw = (const float*)d_in[6];
    float* out = (float*)d_out;

    float *q, *k, *v, *o;
    cudaGetSymbolAddress((void**)&q, g_q);
    cudaGetSymbolAddress((void**)&k, g_k);
    cudaGetSymbolAddress((void**)&v, g_v);
    cudaGetSymbolAddress((void**)&o, g_o);

    rope_table<<<SS, 64>>>();

    // QKV projections
    sgemm_nt<<<dim3(16, 32), 256>>>(x, wq, q, MTOT, H*HD,  DD);
    sgemm_nt<<<dim3( 8, 32), 256>>>(x, wk, k, MTOT, HK*HD, DD);
    sgemm_nt<<<dim3( 8, 32), 256>>>(x, wv, v, MTOT, HK*HD, DD);

    // RMSNorm + RoPE
    norm_rope<<<(MTOT*H )/8, 256>>>(q, qw, H);
    norm_rope<<<(MTOT*HK)/8, 256>>>(k, kw, HK);

    // causal flash attention
    cudaFuncSetAttribute(flash_attn, cudaFuncAttributeMaxDynamicSharedMemorySize, SM_ATT);
    flash_attn<<<dim3(SS/64, H, BB), 256, SM_ATT>>>(q, k, v, o);

    // output projection
    sgemm_nt<<<dim3(16, 32), 256>>>(o, wo, out, MTOT, DD, DD);
}

// round 2
// speedup vs baseline: 1.0063x; 1.0063x over previous
#include <cuda_runtime.h>
#include <math.h>

#define BB 2
#define SS 2048
#define DD 2048
#define H 16
#define HK 8
#define HD 128
#define MTOT (BB*SS)   // 4096

// ---------------- scratch (allocation-free: device globals) ----------------
__device__ float g_q[(size_t)MTOT * H * HD];   // 33.5 MB
__device__ float g_k[(size_t)MTOT * HK * HD];  // 16.8 MB
__device__ float g_v[(size_t)MTOT * HK * HD];  // 16.8 MB
__device__ float g_o[(size_t)MTOT * H * HD];   // 33.5 MB
__device__ float g_cos[SS * 64];
__device__ float g_sin[SS * 64];

// ---------------- SGEMM: C[m][n] = sum_k A[m][k] * W[n][k] -----------------
// A: (M,K) row-major, W: (N,K) row-major, C: (M,N) row-major.
// 128x128 tile, BK=16, 256 threads, 8x8 per thread (2x2 quadrants of 4x4).
__global__ __launch_bounds__(256, 2)
void sgemm_nt(const float* __restrict__ A, const float* __restrict__ W,
              float* __restrict__ C, int M, int N, int K)
{
    __shared__ float As[16][132];
    __shared__ float Bs[16][132];

    const int t   = threadIdx.x;
    const int txx = t & 15;
    const int tyy = t >> 4;
    const int lr  = t >> 2;          // 0..63
    const int lc  = (t & 3) << 2;    // 0,4,8,12

    const int m0 = blockIdx.y * 128;
    const int n0 = blockIdx.x * 128;

    const float* Aptr = A + (size_t)(m0 + lr) * K + lc;
    const float* Wptr = W + (size_t)(n0 + lr) * K + lc;

    float acc[8][8];
    #pragma unroll
    for (int i = 0; i < 8; i++)
        #pragma unroll
        for (int j = 0; j < 8; j++) acc[i][j] = 0.f;

    for (int k0 = 0; k0 < K; k0 += 16) {
        float4 a0 = *(const float4*)(Aptr + k0);
        float4 a1 = *(const float4*)(Aptr + (size_t)64 * K + k0);
        float4 b0 = *(const float4*)(Wptr + k0);
        float4 b1 = *(const float4*)(Wptr + (size_t)64 * K + k0);
        __syncthreads();
        As[lc+0][lr]    = a0.x; As[lc+1][lr]    = a0.y; As[lc+2][lr]    = a0.z; As[lc+3][lr]    = a0.w;
        As[lc+0][lr+64] = a1.x; As[lc+1][lr+64] = a1.y; As[lc+2][lr+64] = a1.z; As[lc+3][lr+64] = a1.w;
        Bs[lc+0][lr]    = b0.x; Bs[lc+1][lr]    = b0.y; Bs[lc+2][lr]    = b0.z; Bs[lc+3][lr]    = b0.w;
        Bs[lc+0][lr+64] = b1.x; Bs[lc+1][lr+64] = b1.y; Bs[lc+2][lr+64] = b1.z; Bs[lc+3][lr+64] = b1.w;
        __syncthreads();
        #pragma unroll
        for (int kk = 0; kk < 16; kk++) {
            float4 av0 = *(const float4*)&As[kk][tyy*4];
            float4 av1 = *(const float4*)&As[kk][tyy*4+64];
            float4 bv0 = *(const float4*)&Bs[kk][txx*4];
            float4 bv1 = *(const float4*)&Bs[kk][txx*4+64];
            float av[8] = {av0.x,av0.y,av0.z,av0.w,av1.x,av1.y,av1.z,av1.w};
            float bv[8] = {bv0.x,bv0.y,bv0.z,bv0.w,bv1.x,bv1.y,bv1.z,bv1.w};
            #pragma unroll
            for (int i = 0; i < 8; i++)
                #pragma unroll
                for (int j = 0; j < 8; j++)
                    acc[i][j] += av[i] * bv[j];
        }
    }

    #pragma unroll
    for (int i = 0; i < 8; i++) {
        int row = m0 + tyy*4 + (i & 3) + ((i >= 4) ? 64 : 0);
        float4 s0 = make_float4(acc[i][0], acc[i][1], acc[i][2], acc[i][3]);
        float4 s1 = make_float4(acc[i][4], acc[i][5], acc[i][6], acc[i][7]);
        *(float4*)(C + (size_t)row * N + n0 + txx*4)      = s0;
        *(float4*)(C + (size_t)row * N + n0 + txx*4 + 64) = s1;
    }
}

// ---------------- RoPE table: cos/sin[s][j], j=0..63 -----------------------
__global__ void rope_table()
{
    int s = blockIdx.x;
    int j = threadIdx.x;  // 0..63
    double invd = pow(1.0e6, -(double)j / 64.0);
    float  invf = (float)invd;
    float  ang  = (float)s * invf;      // fp32 multiply, matching reference
    float  c, sn;
    sincosf(ang, &sn, &c);
    g_cos[s*64 + j] = c;
    g_sin[s*64 + j] = sn;
}

// ---------------- fused RMSNorm + RoPE (one warp per (token, head)) --------
__global__ __launch_bounds__(256)
void norm_rope(float* __restrict__ buf, const float* __restrict__ w, int nheads)
{
    int gw   = (blockIdx.x * blockDim.x + threadIdx.x) >> 5;
    int lane = threadIdx.x & 31;
    int m = gw / nheads;
    int h = gw - m * nheads;
    int s = m & (SS - 1);

    float* p = buf + ((size_t)m * nheads + h) * HD;
    float4 v = *(float4*)(p + lane*4);
    float ss = v.x*v.x + v.y*v.y + v.z*v.z + v.w*v.w;
    #pragma unroll
    for (int o = 16; o; o >>= 1) ss += __shfl_xor_sync(0xffffffffu, ss, o);
    float r = rsqrtf(ss * (1.f/128.f) + 1e-6f);

    const float4 wv = *(const float4*)(w + lane*4);
    v.x *= r * wv.x; v.y *= r * wv.y; v.z *= r * wv.z; v.w *= r * wv.w;

    float4 pr;
    pr.x = __shfl_xor_sync(0xffffffffu, v.x, 16);
    pr.y = __shfl_xor_sync(0xffffffffu, v.y, 16);
    pr.z = __shfl_xor_sync(0xffffffffu, v.z, 16);
    pr.w = __shfl_xor_sync(0xffffffffu, v.w, 16);

    int jbase = (lane & 15) * 4;
    const float* cb = g_cos + s*64 + jbase;
    const float* sb = g_sin + s*64 + jbase;
    float sgn = (lane < 16) ? -1.f : 1.f;

    float4 ov;
    ov.x = v.x * cb[0] + sgn * pr.x * sb[0];
    ov.y = v.y * cb[1] + sgn * pr.y * sb[1];
    ov.z = v.z * cb[2] + sgn * pr.z * sb[2];
    ov.w = v.w * cb[3] + sgn * pr.w * sb[3];
    *(float4*)(p + lane*4) = ov;
}

// ---------------- fp32 flash attention (causal, GQA rep=2) -----------------
// Block: (qtile of 64, h, b). 256 threads = 8 warps; warp w owns q rows
// w*8..w*8+7; lane owns dims lane*4..lane*4+3 of the output accumulator.
#define SM_ATT ((64*128 + 32*132 + 32*132 + 64*33) * 4)

__global__ __launch_bounds__(256)
void flash_attn(const float* __restrict__ Q, const float* __restrict__ Kg,
                const float* __restrict__ Vg, float* __restrict__ O)
{
    extern __shared__ float sm[];
    float* Qs = sm;                  // [64][128]
    float* Ks = Qs + 64*128;         // [32][132]
    float* Vs = Ks + 32*132;         // [32][132]
    float* Ps = Vs + 32*132;         // [64][33]

    const int b = blockIdx.z, h = blockIdx.y, qt = blockIdx.x;
    const int hk = h >> 1;           // H/HK = 2
    const int q0 = qt * 64;
    const int t = threadIdx.x;
    const int lane = t & 31, w = t >> 5;

    const float* qbase = Q + ((size_t)(b*SS + q0) * H + h) * HD;
    for (int idx = t; idx < 64*32; idx += 256) {
        int r = idx >> 5, c4 = (idx & 31) << 2;
        *(float4*)(Qs + r*128 + c4) = *(const float4*)(qbase + (size_t)r * (H*HD) + c4);
    }

    float m_run[8], l_run[8], acc[8][4];
    #pragma unroll
    for (int i = 0; i < 8; i++) {
        m_run[i] = -1e30f; l_run[i] = 0.f;
        acc[i][0] = acc[i][1] = acc[i][2] = acc[i][3] = 0.f;
    }

    const float* kb = Kg + ((size_t)(b*SS) * HK + hk) * HD;
    const float* vb = Vg + ((size_t)(b*SS) * HK + hk) * HD;
    const int ntiles = (q0 + 64) >> 5;
    const float scale = 0.08838834764831845f;   // 1/sqrt(128)

    for (int kt = 0; kt < ntiles; kt++) {
        __syncthreads();
        for (int idx = t; idx < 32*32; idx += 256) {
            int r = idx >> 5, c4 = (idx & 31) << 2;
            size_t g = (size_t)(kt*32 + r) * (HK*HD) + c4;
            *(float4*)(Ks + r*132 + c4) = *(const float4*)(kb + g);
            *(float4*)(Vs + r*132 + c4) = *(const float4*)(vb + g);
        }
        __syncthreads();

        // scores: lane = key column within tile
        float sc[8] = {0,0,0,0,0,0,0,0};
        #pragma unroll
        for (int db = 0; db < 32; db++) {
            float4 k4 = *(const float4*)(Ks + lane*132 + db*4);
            #pragma unroll
            for (int i = 0; i < 8; i++) {
                float4 q4 = *(const float4*)(Qs + (w*8+i)*128 + db*4);
                sc[i] += q4.x*k4.x + q4.y*k4.y + q4.z*k4.z + q4.w*k4.w;
            }
        }

        const int kidx = kt*32 + lane;
        #pragma unroll
        for (int i = 0; i < 8; i++) {
            const int qi = q0 + w*8 + i;
            bool valid = (kidx <= qi);
            float s_ = valid ? sc[i] * scale : -1e30f;
            float mt = s_;
            #pragma unroll
            for (int o = 16; o; o >>= 1) mt = fmaxf(mt, __shfl_xor_sync(0xffffffffu, mt, o));
            float mnew = fmaxf(m_run[i], mt);
            float corr = __expf(m_run[i] - mnew);
            float p = valid ? __expf(s_ - mnew) : 0.f;
            float psum = p;
            #pragma unroll
            for (int o = 16; o; o >>= 1) psum += __shfl_xor_sync(0xffffffffu, psum, o);
            l_run[i] = l_run[i] * corr + psum;
            m_run[i] = mnew;
            acc[i][0] *= corr; acc[i][1] *= corr; acc[i][2] *= corr; acc[i][3] *= corr;
            Ps[(w*8+i)*33 + lane] = p;
        }
        __syncwarp();

        // PV: lane = output dim group
        #pragma unroll
        for (int kk = 0; kk < 32; kk++) {
            float4 v4 = *(const float4*)(Vs + kk*132 + lane*4);
            #pragma unroll
            for (int i = 0; i < 8; i++) {
                float p = Ps[(w*8+i)*33 + kk];
                acc[i][0] += p * v4.x; acc[i][1] += p * v4.y;
                acc[i][2] += p * v4.z; acc[i][3] += p * v4.w;
            }
        }
        __syncwarp();
    }

    float* ob = O + ((size_t)(b*SS + q0) * H + h) * HD;
    #pragma unroll
    for (int i = 0; i < 8; i++) {
        float inv = 1.f / l_run[i];
        float4 ov = make_float4(acc[i][0]*inv, acc[i][1]*inv, acc[i][2]*inv, acc[i][3]*inv);
        *(float4*)(ob + (size_t)(w*8+i) * (H*HD) + lane*4) = ov;
    }
}

// ---------------- launch ----------------------------------------------------
extern "C" void kernel_launch(void* const* d_in, const int* in_sizes, int n_in,
                              void* d_out, int out_size)
{
    (void)in_sizes; (void)n_in; (void)out_size;
    const float* x  = (const float*)d_in[0];
    const float* wq = (const float*)d_in[1];
    const float* wk = (const float*)d_in[2];
    const float* wv = (const float*)d_in[3];
    const float* wo = (const float*)d_in[4];
    const float* qw = (const float*)d_in[5];
    const float* kw = (const float*)d_in[6];
    float* out = (float*)d_out;

    float *q, *k, *v, *o;
    cudaGetSymbolAddress((void**)&q, g_q);
    cudaGetSymbolAddress((void**)&k, g_k);
    cudaGetSymbolAddress((void**)&v, g_v);
    cudaGetSymbolAddress((void**)&o, g_o);

    rope_table<<<SS, 64>>>();

    // QKV projections
    sgemm_nt<<<dim3(16, 32), 256>>>(x, wq, q, MTOT, H*HD,  DD);
    sgemm_nt<<<dim3( 8, 32), 256>>>(x, wk, k, MTOT, HK*HD, DD);
    sgemm_nt<<<dim3( 8, 32), 256>>>(x, wv, v, MTOT, HK*HD, DD);

    // RMSNorm + RoPE
    norm_rope<<<(MTOT*H )/8, 256>>>(q, qw, H);
    norm_rope<<<(MTOT*HK)/8, 256>>>(k, kw, HK);

    // causal flash attention
    cudaFuncSetAttribute(flash_attn, cudaFuncAttributeMaxDynamicSharedMemorySize, SM_ATT);
    flash_attn<<<dim3(SS/64, H, BB), 256, SM_ATT>>>(q, k, v, o);

    // output projection
    sgemm_nt<<<dim3(16, 32), 256>>>(o, wo, out, MTOT, DD, DD);
}

// round 5
// speedup vs baseline: 1.4665x; 1.4572x over previous
#include <cuda_runtime.h>
#include <cuda_bf16.h>
#include <math.h>
#include <stdint.h>

#define BB 2
#define SS 2048
#define DD 2048
#define H 16
#define HK 8
#define HD 128
#define MTOT (BB*SS)   // 4096

// ---------------- scratch (allocation-free: device globals) ----------------
__device__ float g_q[(size_t)MTOT * H * HD];
__device__ float g_k[(size_t)MTOT * HK * HD];
__device__ float g_v[(size_t)MTOT * HK * HD];
__device__ float g_o[(size_t)MTOT * H * HD];
__device__ float g_cos[SS * 64];
__device__ float g_sin[SS * 64];

// bf16 hi/lo split copies
__device__ __align__(16) __nv_bfloat16 g_xh[(size_t)MTOT * DD];
__device__ __align__(16) __nv_bfloat16 g_xl[(size_t)MTOT * DD];
__device__ __align__(16) __nv_bfloat16 g_wqh[(size_t)(H*HD) * DD];
__device__ __align__(16) __nv_bfloat16 g_wql[(size_t)(H*HD) * DD];
__device__ __align__(16) __nv_bfloat16 g_wkh[(size_t)(HK*HD) * DD];
__device__ __align__(16) __nv_bfloat16 g_wkl[(size_t)(HK*HD) * DD];
__device__ __align__(16) __nv_bfloat16 g_wvh[(size_t)(HK*HD) * DD];
__device__ __align__(16) __nv_bfloat16 g_wvl[(size_t)(HK*HD) * DD];
__device__ __align__(16) __nv_bfloat16 g_woh[(size_t)DD * (H*HD)];
__device__ __align__(16) __nv_bfloat16 g_wol[(size_t)DD * (H*HD)];
__device__ __align__(16) __nv_bfloat16 g_oh[(size_t)MTOT * (H*HD)];
__device__ __align__(16) __nv_bfloat16 g_ol[(size_t)MTOT * (H*HD)];

// ---------------- asm helpers ----------------------------------------------
__device__ __forceinline__ uint32_t smem_u32(const void* p) {
    uint32_t a;
    asm("{ .reg .u64 t; cvta.to.shared.u64 t, %1; cvt.u32.u64 %0, t; }" : "=r"(a) : "l"(p));
    return a;
}

#define CP_ASYNC16(dst, src) \
    asm volatile("cp.async.cg.shared.global [%0], [%1], 16;" :: "r"(dst), "l"(src))
#define CP_COMMIT() asm volatile("cp.async.commit_group;" ::: "memory")
#define CP_WAIT2()  asm volatile("cp.async.wait_group 2;" ::: "memory")

__device__ __forceinline__ void ldsm4(uint32_t* r, uint32_t a) {
    asm volatile("ldmatrix.sync.aligned.m8n8.x4.shared.b16 {%0,%1,%2,%3}, [%4];"
        : "=r"(r[0]), "=r"(r[1]), "=r"(r[2]), "=r"(r[3]) : "r"(a));
}
__device__ __forceinline__ void ldsm2(uint32_t* r, uint32_t a) {
    asm volatile("ldmatrix.sync.aligned.m8n8.x2.shared.b16 {%0,%1}, [%2];"
        : "=r"(r[0]), "=r"(r[1]) : "r"(a));
}
__device__ __forceinline__ void mma_bf16(float* c, const uint32_t* a, const uint32_t* b) {
    asm volatile("mma.sync.aligned.m16n8k16.row.col.f32.bf16.bf16.f32 "
        "{%0,%1,%2,%3}, {%4,%5,%6,%7}, {%8,%9}, {%0,%1,%2,%3};"
        : "+f"(c[0]), "+f"(c[1]), "+f"(c[2]), "+f"(c[3])
        : "r"(a[0]), "r"(a[1]), "r"(a[2]), "r"(a[3]), "r"(b[0]), "r"(b[1]));
}

// ---------------- split-bf16 GEMM via mma.sync ------------------------------
// C[m][n] = sum_k A[m][k]*W[n][k];  A≈Ah+Al, W≈Wh+Wl in bf16.
// CTA tile 128x128, BK=32, 256 threads (2x4 warps, 64x32 per warp).
// 4-stage cp.async pipeline. Smem matrix stride 40 bf16 (conflict-free ldmatrix).
#define SST 40
#define MATB (128 * SST * 2)      // 10240 B per matrix buffer
#define STAGEB (4 * MATB)         // 40960 B per stage
#define GEMM_SMEM (4 * STAGEB)    // 163840 B

__device__ __forceinline__ void gemm_load_stage(
    uint32_t sbase, int slot,
    const __nv_bfloat16* __restrict__ Ah, const __nv_bfloat16* __restrict__ Al,
    const __nv_bfloat16* __restrict__ Bh, const __nv_bfloat16* __restrict__ Bl,
    int m0, int n0, int K, int k0, int t)
{
    uint32_t st = sbase + slot * STAGEB;
    const __nv_bfloat16* gp[4] = {
        Ah + (size_t)m0 * K + k0, Al + (size_t)m0 * K + k0,
        Bh + (size_t)n0 * K + k0, Bl + (size_t)n0 * K + k0 };
    #pragma unroll
    for (int mat = 0; mat < 4; mat++) {
        #pragma unroll
        for (int h = 0; h < 2; h++) {
            int c = t + h * 256;          // 0..511
            int row = c >> 2, col16 = c & 3;
            uint32_t dst = st + mat * MATB + row * (SST*2) + col16 * 16;
            const __nv_bfloat16* src = gp[mat] + (size_t)row * K + col16 * 8;
            CP_ASYNC16(dst, src);
        }
    }
}

__global__ __launch_bounds__(256, 1)
void gemm_split(const __nv_bfloat16* __restrict__ Ah, const __nv_bfloat16* __restrict__ Al,
                const __nv_bfloat16* __restrict__ Bh, const __nv_bfloat16* __restrict__ Bl,
                float* __restrict__ C, int N, int K)
{
    extern __shared__ char smem[];
    const uint32_t sb = smem_u32(smem);
    const int t = threadIdx.x;
    const int lane = t & 31, wid = t >> 5;
    const int warp_m = wid >> 2;          // 0..1
    const int warp_n = wid & 3;           // 0..3
    const int m0 = blockIdx.y * 128, n0 = blockIdx.x * 128;
    const int niter = K >> 5;

    float acc[4][4][4];
    #pragma unroll
    for (int i = 0; i < 4; i++)
        #pragma unroll
        for (int j = 0; j < 4; j++) {
            acc[i][j][0] = acc[i][j][1] = acc[i][j][2] = acc[i][j][3] = 0.f;
        }

    // prologue: stages 0..2
    #pragma unroll
    for (int s = 0; s < 3; s++) {
        if (s < niter) gemm_load_stage(sb, s, Ah, Al, Bh, Bl, m0, n0, K, s * 32, t);
        CP_COMMIT();
    }

    // ldmatrix lane addressing (within stage/matrix, bytes)
    const int arow = warp_m * 64 + (lane & 15);
    const int acolh = (lane >> 4) * 8;
    const int l2 = lane & 15;
    const int brow = warp_n * 32 + (l2 & 7);
    const int bcolh = (l2 >> 3) * 8;

    for (int it = 0; it < niter; it++) {
        int ps = it + 3;
        if (ps < niter)
            gemm_load_stage(sb, ps & 3, Ah, Al, Bh, Bl, m0, n0, K, ps * 32, t);
        CP_COMMIT();
        CP_WAIT2();
        __syncthreads();

        uint32_t st = sb + (it & 3) * STAGEB;
        #pragma unroll
        for (int ks = 0; ks < 2; ks++) {
            uint32_t ah[4][4], al[4][4], bh[4][2], bl[4][2];
            #pragma unroll
            for (int mt = 0; mt < 4; mt++) {
                uint32_t off = ((arow + mt * 16) * SST + ks * 16 + acolh) * 2;
                ldsm4(ah[mt], st + off);            // Ah = mat 0
                ldsm4(al[mt], st + MATB + off);     // Al = mat 1
            }
            #pragma unroll
            for (int nt = 0; nt < 4; nt++) {
                uint32_t off = ((brow + nt * 8) * SST + ks * 16 + bcolh) * 2;
                ldsm2(bh[nt], st + 2 * MATB + off); // Bh = mat 2
                ldsm2(bl[nt], st + 3 * MATB + off); // Bl = mat 3
            }
            #pragma unroll
            for (int mt = 0; mt < 4; mt++)
                #pragma unroll
                for (int nt = 0; nt < 4; nt++)
                    mma_bf16(acc[mt][nt], ah[mt], bh[nt]);
            #pragma unroll
            for (int mt = 0; mt < 4; mt++)
                #pragma unroll
                for (int nt = 0; nt < 4; nt++)
                    mma_bf16(acc[mt][nt], ah[mt], bl[nt]);
            #pragma unroll
            for (int mt = 0; mt < 4; mt++)
                #pragma unroll
                for (int nt = 0; nt < 4; nt++)
                    mma_bf16(acc[mt][nt], al[mt], bh[nt]);
        }
        __syncthreads();
    }

    // epilogue
    const int r0 = lane >> 2, c0 = (lane & 3) * 2;
    #pragma unroll
    for (int mt = 0; mt < 4; mt++) {
        #pragma unroll
        for (int nt = 0; nt < 4; nt++) {
            int row = m0 + warp_m * 64 + mt * 16 + r0;
            int col = n0 + warp_n * 32 + nt * 8 + c0;
            *(float2*)(C + (size_t)row * N + col) =
                make_float2(acc[mt][nt][0], acc[mt][nt][1]);
            *(float2*)(C + (size_t)(row + 8) * N + col) =
                make_float2(acc[mt][nt][2], acc[mt][nt][3]);
        }
    }
}

// ---------------- fp32 -> bf16 hi/lo split ---------------------------------
__global__ __launch_bounds__(256)
void split_bf16(const float* __restrict__ in, __nv_bfloat16* __restrict__ hi,
                __nv_bfloat16* __restrict__ lo, int n4)
{
    int i = blockIdx.x * blockDim.x + threadIdx.x;
    if (i >= n4) return;
    float4 v = ((const float4*)in)[i];
    __nv_bfloat16 h0 = __float2bfloat16(v.x), h1 = __float2bfloat16(v.y);
    __nv_bfloat16 h2 = __float2bfloat16(v.z), h3 = __float2bfloat16(v.w);
    __nv_bfloat16 l0 = __float2bfloat16(v.x - __bfloat162float(h0));
    __nv_bfloat16 l1 = __float2bfloat16(v.y - __bfloat162float(h1));
    __nv_bfloat16 l2 = __float2bfloat16(v.z - __bfloat162float(h2));
    __nv_bfloat16 l3 = __float2bfloat16(v.w - __bfloat162float(h3));
    __nv_bfloat162* hp = (__nv_bfloat162*)(hi + i * 4);
    __nv_bfloat162* lp = (__nv_bfloat162*)(lo + i * 4);
    hp[0] = __nv_bfloat162(h0, h1); hp[1] = __nv_bfloat162(h2, h3);
    lp[0] = __nv_bfloat162(l0, l1); lp[1] = __nv_bfloat162(l2, l3);
}

// ---------------- RoPE table ------------------------------------------------
__global__ void rope_table()
{
    int s = blockIdx.x;
    int j = threadIdx.x;  // 0..63
    double invd = pow(1.0e6, -(double)j / 64.0);
    float  ang  = (float)s * (float)invd;
    float  c, sn;
    sincosf(ang, &sn, &c);
    g_cos[s*64 + j] = c;
    g_sin[s*64 + j] = sn;
}

// ---------------- fused RMSNorm + RoPE --------------------------------------
__global__ __launch_bounds__(256)
void norm_rope(float* __restrict__ buf, const float* __restrict__ w, int nheads)
{
    int gw   = (blockIdx.x * blockDim.x + threadIdx.x) >> 5;
    int lane = threadIdx.x & 31;
    int m = gw / nheads;
    int h = gw - m * nheads;
    int s = m & (SS - 1);

    float* p = buf + ((size_t)m * nheads + h) * HD;
    float4 v = *(float4*)(p + lane*4);
    float ss = v.x*v.x + v.y*v.y + v.z*v.z + v.w*v.w;
    #pragma unroll
    for (int o = 16; o; o >>= 1) ss += __shfl_xor_sync(0xffffffffu, ss, o);
    float r = rsqrtf(ss * (1.f/128.f) + 1e-6f);

    const float4 wv = *(const float4*)(w + lane*4);
    v.x *= r * wv.x; v.y *= r * wv.y; v.z *= r * wv.z; v.w *= r * wv.w;

    float4 pr;
    pr.x = __shfl_xor_sync(0xffffffffu, v.x, 16);
    pr.y = __shfl_xor_sync(0xffffffffu, v.y, 16);
    pr.z = __shfl_xor_sync(0xffffffffu, v.z, 16);
    pr.w = __shfl_xor_sync(0xffffffffu, v.w, 16);

    int jbase = (lane & 15) * 4;
    const float* cb = g_cos + s*64 + jbase;
    const float* sb = g_sin + s*64 + jbase;
    float sgn = (lane < 16) ? -1.f : 1.f;

    float4 ov;
    ov.x = v.x * cb[0] + sgn * pr.x * sb[0];
    ov.y = v.y * cb[1] + sgn * pr.y * sb[1];
    ov.z = v.z * cb[2] + sgn * pr.z * sb[2];
    ov.w = v.w * cb[3] + sgn * pr.w * sb[3];
    *(float4*)(p + lane*4) = ov;
}

// ---------------- fp32 flash attention (causal, GQA rep=2) -----------------
#define SM_ATT ((64*128 + 32*132 + 32*132 + 64*33) * 4)

__global__ __launch_bounds__(256)
void flash_attn(const float* __restrict__ Q, const float* __restrict__ Kg,
                const float* __restrict__ Vg, float* __restrict__ O)
{
    extern __shared__ float sm[];
    float* Qs = sm;
    float* Ks = Qs + 64*128;
    float* Vs = Ks + 32*132;
    float* Ps = Vs + 32*132;

    const int b = blockIdx.z, h = blockIdx.y, qt = blockIdx.x;
    const int hk = h >> 1;
    const int q0 = qt * 64;
    const int t = threadIdx.x;
    const int lane = t & 31, w = t >> 5;

    const float* qbase = Q + ((size_t)(b*SS + q0) * H + h) * HD;
    for (int idx = t; idx < 64*32; idx += 256) {
        int r = idx >> 5, c4 = (idx & 31) << 2;
        *(float4*)(Qs + r*128 + c4) = *(const float4*)(qbase + (size_t)r * (H*HD) + c4);
    }

    float m_run[8], l_run[8], acc[8][4];
    #pragma unroll
    for (int i = 0; i < 8; i++) {
        m_run[i] = -1e30f; l_run[i] = 0.f;
        acc[i][0] = acc[i][1] = acc[i][2] = acc[i][3] = 0.f;
    }

    const float* kb = Kg + ((size_t)(b*SS) * HK + hk) * HD;
    const float* vb = Vg + ((size_t)(b*SS) * HK + hk) * HD;
    const int ntiles = (q0 + 64) >> 5;
    const float scale = 0.08838834764831845f;

    for (int kt = 0; kt < ntiles; kt++) {
        __syncthreads();
        for (int idx = t; idx < 32*32; idx += 256) {
            int r = idx >> 5, c4 = (idx & 31) << 2;
            size_t g = (size_t)(kt*32 + r) * (HK*HD) + c4;
            *(float4*)(Ks + r*132 + c4) = *(const float4*)(kb + g);
            *(float4*)(Vs + r*132 + c4) = *(const float4*)(vb + g);
        }
        __syncthreads();

        float sc[8] = {0,0,0,0,0,0,0,0};
        #pragma unroll
        for (int db = 0; db < 32; db++) {
            float4 k4 = *(const float4*)(Ks + lane*132 + db*4);
            #pragma unroll
            for (int i = 0; i < 8; i++) {
                float4 q4 = *(const float4*)(Qs + (w*8+i)*128 + db*4);
                sc[i] += q4.x*k4.x + q4.y*k4.y + q4.z*k4.z + q4.w*k4.w;
            }
        }

        const int kidx = kt*32 + lane;
        #pragma unroll
        for (int i = 0; i < 8; i++) {
            const int qi = q0 + w*8 + i;
            bool valid = (kidx <= qi);
            float s_ = valid ? sc[i] * scale : -1e30f;
            float mt = s_;
            #pragma unroll
            for (int o = 16; o; o >>= 1) mt = fmaxf(mt, __shfl_xor_sync(0xffffffffu, mt, o));
            float mnew = fmaxf(m_run[i], mt);
            float corr = __expf(m_run[i] - mnew);
            float p = valid ? __expf(s_ - mnew) : 0.f;
            float psum = p;
            #pragma unroll
            for (int o = 16; o; o >>= 1) psum += __shfl_xor_sync(0xffffffffu, psum, o);
            l_run[i] = l_run[i] * corr + psum;
            m_run[i] = mnew;
            acc[i][0] *= corr; acc[i][1] *= corr; acc[i][2] *= corr; acc[i][3] *= corr;
            Ps[(w*8+i)*33 + lane] = p;
        }
        __syncwarp();

        #pragma unroll
        for (int kk = 0; kk < 32; kk++) {
            float4 v4 = *(const float4*)(Vs + kk*132 + lane*4);
            #pragma unroll
            for (int i = 0; i < 8; i++) {
                float p = Ps[(w*8+i)*33 + kk];
                acc[i][0] += p * v4.x; acc[i][1] += p * v4.y;
                acc[i][2] += p * v4.z; acc[i][3] += p * v4.w;
            }
        }
        __syncwarp();
    }

    float* ob = O + ((size_t)(b*SS + q0) * H + h) * HD;
    #pragma unroll
    for (int i = 0; i < 8; i++) {
        float inv = 1.f / l_run[i];
        float4 ov = make_float4(acc[i][0]*inv, acc[i][1]*inv, acc[i][2]*inv, acc[i][3]*inv);
        *(float4*)(ob + (size_t)(w*8+i) * (H*HD) + lane*4) = ov;
    }
}

// ---------------- launch ----------------------------------------------------
extern "C" void kernel_launch(void* const* d_in, const int* in_sizes, int n_in,
                              void* d_out, int out_size)
{
    (void)in_sizes; (void)n_in; (void)out_size;
    const float* x  = (const float*)d_in[0];
    const float* wq = (const float*)d_in[1];
    const float* wk = (const float*)d_in[2];
    const float* wv = (const float*)d_in[3];
    const float* wo = (const float*)d_in[4];
    const float* qw = (const float*)d_in[5];
    const float* kw = (const float*)d_in[6];
    float* out = (float*)d_out;

    float *q, *k, *v, *o;
    cudaGetSymbolAddress((void**)&q, g_q);
    cudaGetSymbolAddress((void**)&k, g_k);
    cudaGetSymbolAddress((void**)&v, g_v);
    cudaGetSymbolAddress((void**)&o, g_o);

    __nv_bfloat16 *xh, *xl, *wqh, *wql, *wkh, *wkl, *wvh, *wvl, *woh, *wol, *oh, *ol;
    cudaGetSymbolAddress((void**)&xh,  g_xh);  cudaGetSymbolAddress((void**)&xl,  g_xl);
    cudaGetSymbolAddress((void**)&wqh, g_wqh); cudaGetSymbolAddress((void**)&wql, g_wql);
    cudaGetSymbolAddress((void**)&wkh, g_wkh); cudaGetSymbolAddress((void**)&wkl, g_wkl);
    cudaGetSymbolAddress((void**)&wvh, g_wvh); cudaGetSymbolAddress((void**)&wvl, g_wvl);
    cudaGetSymbolAddress((void**)&woh, g_woh); cudaGetSymbolAddress((void**)&wol, g_wol);
    cudaGetSymbolAddress((void**)&oh,  g_oh);  cudaGetSymbolAddress((void**)&ol,  g_ol);

    cudaFuncSetAttribute(gemm_split, cudaFuncAttributeMaxDynamicSharedMemorySize, GEMM_SMEM);
    cudaFuncSetAttribute(flash_attn, cudaFuncAttributeMaxDynamicSharedMemorySize, SM_ATT);

    // hi/lo splits
    split_bf16<<<(MTOT*DD/4 + 255)/256, 256>>>(x,  xh,  xl,  MTOT*DD/4);
    split_bf16<<<(H*HD*DD/4 + 255)/256, 256>>>(wq, wqh, wql, H*HD*DD/4);
    split_bf16<<<(HK*HD*DD/4 + 255)/256, 256>>>(wk, wkh, wkl, HK*HD*DD/4);
    split_bf16<<<(HK*HD*DD/4 + 255)/256, 256>>>(wv, wvh, wvl, HK*HD*DD/4);
    split_bf16<<<(DD*H*HD/4 + 255)/256, 256>>>(wo, woh, wol, DD*H*HD/4);

    rope_table<<<SS, 64>>>();

    // QKV projections (bf16 split, mma.sync)
    gemm_split<<<dim3((H*HD)/128,  MTOT/128), 256, GEMM_SMEM>>>(xh, xl, wqh, wql, q, H*HD,  DD);
    gemm_split<<<dim3((HK*HD)/128, MTOT/128), 256, GEMM_SMEM>>>(xh, xl, wkh, wkl, k, HK*HD, DD);
    gemm_split<<<dim3((HK*HD)/128, MTOT/128), 256, GEMM_SMEM>>>(xh, xl, wvh, wvl, v, HK*HD, DD);

    // RMSNorm + RoPE
    norm_rope<<<(MTOT*H )/8, 256>>>(q, qw, H);
    norm_rope<<<(MTOT*HK)/8, 256>>>(k, kw, HK);

    // causal flash attention (fp32)
    flash_attn<<<dim3(SS/64, H, BB), 256, SM_ATT>>>(q, k, v, o);

    // output projection
    split_bf16<<<(MTOT*H*HD/4 + 255)/256, 256>>>(o, oh, ol, MTOT*H*HD/4);
    gemm_split<<<dim3(DD/128, MTOT/128), 256, GEMM_SMEM>>>(oh, ol, woh, wol, out, DD, H*HD);
}

// round 7
// speedup vs baseline: 2.4017x; 1.6377x over previous
#include <cuda_runtime.h>
#include <cuda_bf16.h>
#include <math.h>
#include <stdint.h>

#define BB 2
#define SS 2048
#define DD 2048
#define H 16
#define HK 8
#define HD 128
#define MTOT (BB*SS)   // 4096

// ---------------- scratch (allocation-free: device globals) ----------------
__device__ float g_q[(size_t)MTOT * H * HD];
__device__ float g_k[(size_t)MTOT * HK * HD];
__device__ float g_v[(size_t)MTOT * HK * HD];
__device__ float g_cos[SS * 64];
__device__ float g_sin[SS * 64];

__device__ __align__(16) __nv_bfloat16 g_xh[(size_t)MTOT * DD];
__device__ __align__(16) __nv_bfloat16 g_xl[(size_t)MTOT * DD];
__device__ __align__(16) __nv_bfloat16 g_wqh[(size_t)(H*HD) * DD];
__device__ __align__(16) __nv_bfloat16 g_wql[(size_t)(H*HD) * DD];
__device__ __align__(16) __nv_bfloat16 g_wkh[(size_t)(HK*HD) * DD];
__device__ __align__(16) __nv_bfloat16 g_wkl[(size_t)(HK*HD) * DD];
__device__ __align__(16) __nv_bfloat16 g_wvh[(size_t)(HK*HD) * DD];
__device__ __align__(16) __nv_bfloat16 g_wvl[(size_t)(HK*HD) * DD];
__device__ __align__(16) __nv_bfloat16 g_woh[(size_t)DD * (H*HD)];
__device__ __align__(16) __nv_bfloat16 g_wol[(size_t)DD * (H*HD)];
__device__ __align__(16) __nv_bfloat16 g_oh[(size_t)MTOT * (H*HD)];
__device__ __align__(16) __nv_bfloat16 g_ol[(size_t)MTOT * (H*HD)];

// attention operands
__device__ __align__(16) __nv_bfloat16 g_qah[(size_t)MTOT * H * HD];
__device__ __align__(16) __nv_bfloat16 g_qal[(size_t)MTOT * H * HD];
__device__ __align__(16) __nv_bfloat16 g_kah[(size_t)MTOT * HK * HD];
__device__ __align__(16) __nv_bfloat16 g_kal[(size_t)MTOT * HK * HD];
__device__ __align__(16) __nv_bfloat16 g_vth[(size_t)MTOT * HK * HD];  // [b][hk][d][tok]
__device__ __align__(16) __nv_bfloat16 g_vtl[(size_t)MTOT * HK * HD];

// ---------------- asm helpers ----------------------------------------------
__device__ __forceinline__ uint32_t smem_u32(const void* p) {
    uint32_t a;
    asm("{ .reg .u64 t; cvta.to.shared.u64 t, %1; cvt.u32.u64 %0, t; }" : "=r"(a) : "l"(p));
    return a;
}

#define CP_ASYNC16(dst, src) \
    asm volatile("cp.async.cg.shared.global [%0], [%1], 16;" :: "r"(dst), "l"(src))
#define CP_COMMIT() asm volatile("cp.async.commit_group;" ::: "memory")
#define CP_WAIT2()  asm volatile("cp.async.wait_group 2;" ::: "memory")
#define CP_WAIT1()  asm volatile("cp.async.wait_group 1;" ::: "memory")
#define CP_WAIT0()  asm volatile("cp.async.wait_group 0;" ::: "memory")

__device__ __forceinline__ void ldsm4(uint32_t* r, uint32_t a) {
    asm volatile("ldmatrix.sync.aligned.m8n8.x4.shared.b16 {%0,%1,%2,%3}, [%4];"
        : "=r"(r[0]), "=r"(r[1]), "=r"(r[2]), "=r"(r[3]) : "r"(a));
}
__device__ __forceinline__ void ldsm2(uint32_t* r, uint32_t a) {
    asm volatile("ldmatrix.sync.aligned.m8n8.x2.shared.b16 {%0,%1}, [%2];"
        : "=r"(r[0]), "=r"(r[1]) : "r"(a));
}
__device__ __forceinline__ void mma_bf16(float* c, const uint32_t* a, const uint32_t* b) {
    asm volatile("mma.sync.aligned.m16n8k16.row.col.f32.bf16.bf16.f32 "
        "{%0,%1,%2,%3}, {%4,%5,%6,%7}, {%8,%9}, {%0,%1,%2,%3};"
        : "+f"(c[0]), "+f"(c[1]), "+f"(c[2]), "+f"(c[3])
        : "r"(a[0]), "r"(a[1]), "r"(a[2]), "r"(a[3]), "r"(b[0]), "r"(b[1]));
}

__device__ __forceinline__ uint32_t pack_bf2(float a, float b) {
    __nv_bfloat162 t(__float2bfloat16(a), __float2bfloat16(b));
    return *(uint32_t*)&t;
}

// ---------------- split-bf16 GEMM via mma.sync (unchanged, passing) ---------
#define SST 40
#define MATB (128 * SST * 2)
#define STAGEB (4 * MATB)
#define GEMM_SMEM (4 * STAGEB)

__device__ __forceinline__ void gemm_load_stage(
    uint32_t sbase, int slot,
    const __nv_bfloat16* __restrict__ Ah, const __nv_bfloat16* __restrict__ Al,
    const __nv_bfloat16* __restrict__ Bh, const __nv_bfloat16* __restrict__ Bl,
    int m0, int n0, int K, int k0, int t)
{
    uint32_t st = sbase + slot * STAGEB;
    const __nv_bfloat16* gp[4] = {
        Ah + (size_t)m0 * K + k0, Al + (size_t)m0 * K + k0,
        Bh + (size_t)n0 * K + k0, Bl + (size_t)n0 * K + k0 };
    #pragma unroll
    for (int mat = 0; mat < 4; mat++) {
        #pragma unroll
        for (int h = 0; h < 2; h++) {
            int c = t + h * 256;
            int row = c >> 2, col16 = c & 3;
            uint32_t dst = st + mat * MATB + row * (SST*2) + col16 * 16;
            const __nv_bfloat16* src = gp[mat] + (size_t)row * K + col16 * 8;
            CP_ASYNC16(dst, src);
        }
    }
}

__global__ __launch_bounds__(256, 1)
void gemm_split(const __nv_bfloat16* __restrict__ Ah, const __nv_bfloat16* __restrict__ Al,
                const __nv_bfloat16* __restrict__ Bh, const __nv_bfloat16* __restrict__ Bl,
                float* __restrict__ C, int N, int K)
{
    extern __shared__ char smem[];
    const uint32_t sb = smem_u32(smem);
    const int t = threadIdx.x;
    const int lane = t & 31, wid = t >> 5;
    const int warp_m = wid >> 2;
    const int warp_n = wid & 3;
    const int m0 = blockIdx.y * 128, n0 = blockIdx.x * 128;
    const int niter = K >> 5;

    float acc[4][4][4];
    #pragma unroll
    for (int i = 0; i < 4; i++)
        #pragma unroll
        for (int j = 0; j < 4; j++)
            acc[i][j][0] = acc[i][j][1] = acc[i][j][2] = acc[i][j][3] = 0.f;

    #pragma unroll
    for (int s = 0; s < 3; s++) {
        if (s < niter) gemm_load_stage(sb, s, Ah, Al, Bh, Bl, m0, n0, K, s * 32, t);
        CP_COMMIT();
    }

    const int arow = warp_m * 64 + (lane & 15);
    const int acolh = (lane >> 4) * 8;
    const int l2 = lane & 15;
    const int brow = warp_n * 32 + (l2 & 7);
    const int bcolh = (l2 >> 3) * 8;

    for (int it = 0; it < niter; it++) {
        int ps = it + 3;
        if (ps < niter)
            gemm_load_stage(sb, ps & 3, Ah, Al, Bh, Bl, m0, n0, K, ps * 32, t);
        CP_COMMIT();
        CP_WAIT2();
        __syncthreads();

        uint32_t st = sb + (it & 3) * STAGEB;
        #pragma unroll
        for (int ks = 0; ks < 2; ks++) {
            uint32_t ah[4][4], al[4][4], bh[4][2], bl[4][2];
            #pragma unroll
            for (int mt = 0; mt < 4; mt++) {
                uint32_t off = ((arow + mt * 16) * SST + ks * 16 + acolh) * 2;
                ldsm4(ah[mt], st + off);
                ldsm4(al[mt], st + MATB + off);
            }
            #pragma unroll
            for (int nt = 0; nt < 4; nt++) {
                uint32_t off = ((brow + nt * 8) * SST + ks * 16 + bcolh) * 2;
                ldsm2(bh[nt], st + 2 * MATB + off);
                ldsm2(bl[nt], st + 3 * MATB + off);
            }
            #pragma unroll
            for (int mt = 0; mt < 4; mt++)
                #pragma unroll
                for (int nt = 0; nt < 4; nt++)
                    mma_bf16(acc[mt][nt], ah[mt], bh[nt]);
            #pragma unroll
            for (int mt = 0; mt < 4; mt++)
                #pragma unroll
                for (int nt = 0; nt < 4; nt++)
                    mma_bf16(acc[mt][nt], ah[mt], bl[nt]);
            #pragma unroll
            for (int mt = 0; mt < 4; mt++)
                #pragma unroll
                for (int nt = 0; nt < 4; nt++)
                    mma_bf16(acc[mt][nt], al[mt], bh[nt]);
        }
        __syncthreads();
    }

    const int r0 = lane >> 2, c0 = (lane & 3) * 2;
    #pragma unroll
    for (int mt = 0; mt < 4; mt++) {
        #pragma unroll
        for (int nt = 0; nt < 4; nt++) {
            int row = m0 + warp_m * 64 + mt * 16 + r0;
            int col = n0 + warp_n * 32 + nt * 8 + c0;
            *(float2*)(C + (size_t)row * N + col) =
                make_float2(acc[mt][nt][0], acc[mt][nt][1]);
            *(float2*)(C + (size_t)(row + 8) * N + col) =
                make_float2(acc[mt][nt][2], acc[mt][nt][3]);
        }
    }
}

// ---------------- fp32 -> bf16 hi/lo split ---------------------------------
__global__ __launch_bounds__(256)
void split_bf16(const float* __restrict__ in, __nv_bfloat16* __restrict__ hi,
                __nv_bfloat16* __restrict__ lo, int n4)
{
    int i = blockIdx.x * blockDim.x + threadIdx.x;
    if (i >= n4) return;
    float4 v = ((const float4*)in)[i];
    __nv_bfloat16 h0 = __float2bfloat16(v.x), h1 = __float2bfloat16(v.y);
    __nv_bfloat16 h2 = __float2bfloat16(v.z), h3 = __float2bfloat16(v.w);
    __nv_bfloat16 l0 = __float2bfloat16(v.x - __bfloat162float(h0));
    __nv_bfloat16 l1 = __float2bfloat16(v.y - __bfloat162float(h1));
    __nv_bfloat16 l2 = __float2bfloat16(v.z - __bfloat162float(h2));
    __nv_bfloat16 l3 = __float2bfloat16(v.w - __bfloat162float(h3));
    __nv_bfloat162* hp = (__nv_bfloat162*)(hi + i * 4);
    __nv_bfloat162* lp = (__nv_bfloat162*)(lo + i * 4);
    hp[0] = __nv_bfloat162(h0, h1); hp[1] = __nv_bfloat162(h2, h3);
    lp[0] = __nv_bfloat162(l0, l1); lp[1] = __nv_bfloat162(l2, l3);
}

// ---------------- RoPE table ------------------------------------------------
__global__ void rope_table()
{
    int s = blockIdx.x;
    int j = threadIdx.x;
    double invd = pow(1.0e6, -(double)j / 64.0);
    float  ang  = (float)s * (float)invd;
    float  c, sn;
    sincosf(ang, &sn, &c);
    g_cos[s*64 + j] = c;
    g_sin[s*64 + j] = sn;
}

// -------- fused RMSNorm + RoPE, emitting bf16 hi/lo directly ---------------
__global__ __launch_bounds__(256)
void norm_rope_split(const float* __restrict__ buf, __nv_bfloat16* __restrict__ outh,
                     __nv_bfloat16* __restrict__ outl, const float* __restrict__ w, int nheads)
{
    int gw   = (blockIdx.x * blockDim.x + threadIdx.x) >> 5;
    int lane = threadIdx.x & 31;
    int m = gw / nheads;
    int h = gw - m * nheads;
    int s = m & (SS - 1);

    size_t base = ((size_t)m * nheads + h) * HD + lane * 4;
    float4 v = *(const float4*)(buf + base);
    float ss = v.x*v.x + v.y*v.y + v.z*v.z + v.w*v.w;
    #pragma unroll
    for (int o = 16; o; o >>= 1) ss += __shfl_xor_sync(0xffffffffu, ss, o);
    float r = rsqrtf(ss * (1.f/128.f) + 1e-6f);

    const float4 wv = *(const float4*)(w + lane*4);
    v.x *= r * wv.x; v.y *= r * wv.y; v.z *= r * wv.z; v.w *= r * wv.w;

    float4 pr;
    pr.x = __shfl_xor_sync(0xffffffffu, v.x, 16);
    pr.y = __shfl_xor_sync(0xffffffffu, v.y, 16);
    pr.z = __shfl_xor_sync(0xffffffffu, v.z, 16);
    pr.w = __shfl_xor_sync(0xffffffffu, v.w, 16);

    int jbase = (lane & 15) * 4;
    const float* cb = g_cos + s*64 + jbase;
    const float* sb = g_sin + s*64 + jbase;
    float sgn = (lane < 16) ? -1.f : 1.f;

    float o0 = v.x * cb[0] + sgn * pr.x * sb[0];
    float o1 = v.y * cb[1] + sgn * pr.y * sb[1];
    float o2 = v.z * cb[2] + sgn * pr.z * sb[2];
    float o3 = v.w * cb[3] + sgn * pr.w * sb[3];

    __nv_bfloat16 h0 = __float2bfloat16(o0), h1 = __float2bfloat16(o1);
    __nv_bfloat16 h2 = __float2bfloat16(o2), h3 = __float2bfloat16(o3);
    __nv_bfloat162* hp = (__nv_bfloat162*)(outh + base);
    __nv_bfloat162* lp = (__nv_bfloat162*)(outl + base);
    hp[0] = __nv_bfloat162(h0, h1); hp[1] = __nv_bfloat162(h2, h3);
    lp[0] = __nv_bfloat162(__float2bfloat16(o0 - __bfloat162float(h0)),
                           __float2bfloat16(o1 - __bfloat162float(h1)));
    lp[1] = __nv_bfloat162(__float2bfloat16(o2 - __bfloat162float(h2)),
                           __float2bfloat16(o3 - __bfloat162float(h3)));
}

// ---- V transpose + split: [tok][hk][d] fp32 -> [b][hk][d][tok] bf16 x2 ----
__global__ __launch_bounds__(256)
void transp_split_v(const float* __restrict__ v, __nv_bfloat16* __restrict__ vth,
                    __nv_bfloat16* __restrict__ vtl)
{
    __shared__ float tile[32][33];
    int t = threadIdx.x;
    int tx = t & 31, ty = t >> 5;
    int tok0 = blockIdx.x * 32, d0 = blockIdx.y * 32;
    int bh = blockIdx.z;
    int b = bh >> 3, hk = bh & 7;

    #pragma unroll
    for (int r = 0; r < 4; r++) {
        int tok = ty + r * 8;
        tile[tok][tx] = v[((size_t)(b*SS + tok0 + tok) * HK + hk) * HD + d0 + tx];
    }
    __syncthreads();
    #pragma unroll
    for (int r = 0; r < 4; r++) {
        int d = ty + r * 8;
        float val = tile[tx][d];
        size_t idx = ((size_t)(b*HK + hk) * HD + d0 + d) * SS + tok0 + tx;
        __nv_bfloat16 h = __float2bfloat16(val);
        vth[idx] = h;
        vtl[idx] = __float2bfloat16(val - __bfloat162float(h));
    }
}

// ---------------- mma.sync flash attention (causal, GQA rep=2) -------------
// 128 q rows / CTA, 8 warps x 16 rows; 64-key tiles; bf16 hi/lo 3-pass.
#define KST 136                    // K/Q smem stride (bf16)
#define VSTR 72                    // V^T smem stride (bf16)
#define KMAT (64 * KST * 2)        // 17408 B (64-row K tile)
#define QMAT (128 * KST * 2)       // 34816 B (128-row Q tile)   <-- FIX
#define VMAT (128 * VSTR * 2)      // 18432 B
#define ASTAGE (2*KMAT + 2*VMAT)   // 71680 B
#define ATT_SMEM (2 * ASTAGE)      // 143360 B

__global__ __launch_bounds__(256, 1)
void attn_mma(const __nv_bfloat16* __restrict__ qh, const __nv_bfloat16* __restrict__ ql,
              const __nv_bfloat16* __restrict__ kh, const __nv_bfloat16* __restrict__ kl,
              const __nv_bfloat16* __restrict__ vth, const __nv_bfloat16* __restrict__ vtl,
              __nv_bfloat16* __restrict__ oh, __nv_bfloat16* __restrict__ ol)
{
    extern __shared__ char smem[];
    const uint32_t sb = smem_u32(smem);
    const int t = threadIdx.x, lane = t & 31, w = t >> 5;
    const int b = blockIdx.z, h = blockIdx.y, qblk = blockIdx.x;
    const int hk = h >> 1, q0 = qblk * 128;
    const int ntiles = 2 * qblk + 2;
    const float scale = 0.08838834764831845f;

    const __nv_bfloat16* kbh_g = kh + ((size_t)(b*SS) * HK + hk) * HD;
    const __nv_bfloat16* kbl_g = kl + ((size_t)(b*SS) * HK + hk) * HD;
    const __nv_bfloat16* vbh_g = vth + (size_t)(b*HK + hk) * HD * SS;
    const __nv_bfloat16* vbl_g = vtl + (size_t)(b*HK + hk) * HD * SS;

    // ---- prologue: Q into stage1 area (Q-hi at qb, Q-lo at qb+QMAT) ----
    {
        const __nv_bfloat16* qsh = qh + ((size_t)(b*SS + q0) * H + h) * HD;
        const __nv_bfloat16* qsl = ql + ((size_t)(b*SS + q0) * H + h) * HD;
        uint32_t qb = sb + ASTAGE;
        #pragma unroll
        for (int i = 0; i < 8; i++) {
            int idx = t + i * 256;            // 0..2047
            int row = idx >> 4, c = idx & 15;
            CP_ASYNC16(qb + row * (KST*2) + c * 16, qsh + (size_t)row * (H*HD) + c * 8);
            CP_ASYNC16(qb + QMAT + row * (KST*2) + c * 16, qsl + (size_t)row * (H*HD) + c * 8);
        }
        CP_COMMIT();
    }
    // stage 0 (kt=0)
    {
        uint32_t st = sb;
        #pragma unroll
        for (int i = 0; i < 4; i++) {
            int idx = t + i * 256;            // 0..1023
            int row = idx >> 4, c = idx & 15;
            CP_ASYNC16(st + row * (KST*2) + c * 16, kbh_g + (size_t)row * (HK*HD) + c * 8);
            CP_ASYNC16(st + KMAT + row * (KST*2) + c * 16, kbl_g + (size_t)row * (HK*HD) + c * 8);
            int vrow = idx >> 3, vc = idx & 7;
            CP_ASYNC16(st + 2*KMAT + vrow * (VSTR*2) + vc * 16, vbh_g + (size_t)vrow * SS + vc * 8);
            CP_ASYNC16(st + 2*KMAT + VMAT + vrow * (VSTR*2) + vc * 16, vbl_g + (size_t)vrow * SS + vc * 8);
        }
        CP_COMMIT();
    }
    CP_WAIT1();      // Q group done
    __syncthreads();

    // extract Q fragments
    uint32_t qfh[8][4], qfl[8][4];
    {
        uint32_t qb = sb + ASTAGE;
        uint32_t roff = (w * 16 + (lane & 15)) * (KST*2) + ((lane >> 4) & 1) * 16;
        #pragma unroll
        for (int ks = 0; ks < 8; ks++) {
            ldsm4(qfh[ks], qb + roff + ks * 32);
            ldsm4(qfl[ks], qb + QMAT + roff + ks * 32);
        }
    }
    __syncthreads();
    // stage 1 (kt=1) — overwrites Q area, safe: fragments already in registers
    {
        uint32_t st = sb + ASTAGE;
        const __nv_bfloat16* ksh = kbh_g + (size_t)64 * (HK*HD);
        const __nv_bfloat16* ksl = kbl_g + (size_t)64 * (HK*HD);
        #pragma unroll
        for (int i = 0; i < 4; i++) {
            int idx = t + i * 256;
            int row = idx >> 4, c = idx & 15;
            CP_ASYNC16(st + row * (KST*2) + c * 16, ksh + (size_t)row * (HK*HD) + c * 8);
            CP_ASYNC16(st + KMAT + row * (KST*2) + c * 16, ksl + (size_t)row * (HK*HD) + c * 8);
            int vrow = idx >> 3, vc = idx & 7;
            CP_ASYNC16(st + 2*KMAT + vrow * (VSTR*2) + vc * 16, vbh_g + (size_t)vrow * SS + 64 + vc * 8);
            CP_ASYNC16(st + 2*KMAT + VMAT + vrow * (VSTR*2) + vc * 16, vbl_g + (size_t)vrow * SS + 64 + vc * 8);
        }
        CP_COMMIT();
    }

    float oacc[16][4];
    #pragma unroll
    for (int i = 0; i < 16; i++) oacc[i][0] = oacc[i][1] = oacc[i][2] = oacc[i][3] = 0.f;
    float m0 = -1e30f, m1 = -1e30f, l0 = 0.f, l1 = 0.f;

    const int gr0 = q0 + w * 16 + (lane >> 2);
    const int gc_base = (lane & 3) * 2;

    for (int kt = 0; kt < ntiles; kt++) {
        if (kt + 1 < ntiles) { CP_WAIT1(); } else { CP_WAIT0(); }
        __syncthreads();
        uint32_t st = sb + (kt & 1) * ASTAGE;

        // ---- S = Q K^T (hi/lo 3-pass) ----
        float s[8][4];
        #pragma unroll
        for (int i = 0; i < 8; i++) s[i][0] = s[i][1] = s[i][2] = s[i][3] = 0.f;

        #pragma unroll
        for (int ks = 0; ks < 8; ks++) {
            uint32_t lrow = (lane & 7) + ((lane >> 4) << 3);
            uint32_t lcol = (ks * 16 + ((lane >> 3) & 1) * 8) * 2;
            #pragma unroll
            for (int p = 0; p < 4; p++) {
                uint32_t kb[4], klr[4];
                uint32_t addr = st + (p * 16 + lrow) * (KST*2) + lcol;
                ldsm4(kb, addr);
                ldsm4(klr, addr + KMAT);
                mma_bf16(s[2*p],   qfh[ks], &kb[0]);
                mma_bf16(s[2*p+1], qfh[ks], &kb[2]);
                mma_bf16(s[2*p],   qfh[ks], &klr[0]);
                mma_bf16(s[2*p+1], qfh[ks], &klr[2]);
                mma_bf16(s[2*p],   qfl[ks], &kb[0]);
                mma_bf16(s[2*p+1], qfl[ks], &kb[2]);
            }
        }

        // ---- softmax (fp32, warp-local rows) ----
        const int kc0 = kt * 64;
        bool fullok = (kc0 + 63 <= q0 + w * 16);
        #pragma unroll
        for (int nt = 0; nt < 8; nt++) {
            if (fullok) {
                s[nt][0] *= scale; s[nt][1] *= scale; s[nt][2] *= scale; s[nt][3] *= scale;
            } else {
                int gc = kc0 + nt * 8 + gc_base;
                s[nt][0] = (gc     <= gr0    ) ? s[nt][0] * scale : -1e30f;
                s[nt][1] = (gc + 1 <= gr0    ) ? s[nt][1] * scale : -1e30f;
                s[nt][2] = (gc     <= gr0 + 8) ? s[nt][2] * scale : -1e30f;
                s[nt][3] = (gc + 1 <= gr0 + 8) ? s[nt][3] * scale : -1e30f;
            }
        }
        float mx0 = -1e30f, mx1 = -1e30f;
        #pragma unroll
        for (int nt = 0; nt < 8; nt++) {
            mx0 = fmaxf(mx0, fmaxf(s[nt][0], s[nt][1]));
            mx1 = fmaxf(mx1, fmaxf(s[nt][2], s[nt][3]));
        }
        #pragma unroll
        for (int o = 1; o <= 2; o <<= 1) {
            mx0 = fmaxf(mx0, __shfl_xor_sync(0xffffffffu, mx0, o));
            mx1 = fmaxf(mx1, __shfl_xor_sync(0xffffffffu, mx1, o));
        }
        float mn0 = fmaxf(m0, mx0), mn1 = fmaxf(m1, mx1);
        float cr0 = __expf(m0 - mn0), cr1 = __expf(m1 - mn1);
        m0 = mn0; m1 = mn1;
        #pragma unroll
        for (int nt = 0; nt < 16; nt++) {
            oacc[nt][0] *= cr0; oacc[nt][1] *= cr0;
            oacc[nt][2] *= cr1; oacc[nt][3] *= cr1;
        }

        uint32_t pfh[4][4], pfl[4][4];
        float sum0 = 0.f, sum1 = 0.f;
        #pragma unroll
        for (int nt = 0; nt < 8; nt++) {
            float p0 = __expf(s[nt][0] - mn0);
            float p1 = __expf(s[nt][1] - mn0);
            float p2 = __expf(s[nt][2] - mn1);
            float p3 = __expf(s[nt][3] - mn1);
            sum0 += p0 + p1; sum1 += p2 + p3;
            __nv_bfloat16 b0 = __float2bfloat16(p0), b1 = __float2bfloat16(p1);
            __nv_bfloat16 b2 = __float2bfloat16(p2), b3 = __float2bfloat16(p3);
            int j = nt >> 1, hi2 = (nt & 1) * 2;
            __nv_bfloat162 ph0(b0, b1), ph1(b2, b3);
            pfh[j][hi2]     = *(uint32_t*)&ph0;
            pfh[j][hi2 + 1] = *(uint32_t*)&ph1;
            pfl[j][hi2]     = pack_bf2(p0 - __bfloat162float(b0), p1 - __bfloat162float(b1));
            pfl[j][hi2 + 1] = pack_bf2(p2 - __bfloat162float(b2), p3 - __bfloat162float(b3));
        }
        #pragma unroll
        for (int o = 1; o <= 2; o <<= 1) {
            sum0 += __shfl_xor_sync(0xffffffffu, sum0, o);
            sum1 += __shfl_xor_sync(0xffffffffu, sum1, o);
        }
        l0 = l0 * cr0 + sum0;
        l1 = l1 * cr1 + sum1;

        // ---- O += P V (hi/lo 3-pass); B = V^T tile [128 d][64 keys] ----
        uint32_t vst = st + 2 * KMAT;
        #pragma unroll
        for (int ks = 0; ks < 4; ks++) {
            uint32_t lrow = (lane & 7) + ((lane >> 4) << 3);
            uint32_t lcol = (ks * 16 + ((lane >> 3) & 1) * 8) * 2;
            #pragma unroll
            for (int p = 0; p < 8; p++) {
                uint32_t vb[4], vl[4];
                uint32_t addr = vst + (p * 16 + lrow) * (VSTR*2) + lcol;
                ldsm4(vb, addr);
                ldsm4(vl, addr + VMAT);
                mma_bf16(oacc[2*p],   pfh[ks], &vb[0]);
                mma_bf16(oacc[2*p+1], pfh[ks], &vb[2]);
                mma_bf16(oacc[2*p],   pfh[ks], &vl[0]);
                mma_bf16(oacc[2*p+1], pfh[ks], &vl[2]);
                mma_bf16(oacc[2*p],   pfl[ks], &vb[0]);
                mma_bf16(oacc[2*p+1], pfl[ks], &vb[2]);
            }
        }

        __syncthreads();
        // prefetch kt+2
        if (kt + 2 < ntiles) {
            uint32_t st2 = sb + (kt & 1) * ASTAGE;
            int kc = (kt + 2) * 64;
            const __nv_bfloat16* ksh = kbh_g + (size_t)kc * (HK*HD);
            const __nv_bfloat16* ksl = kbl_g + (size_t)kc * (HK*HD);
            #pragma unroll
            for (int i = 0; i < 4; i++) {
                int idx = t + i * 256;
                int row = idx >> 4, c = idx & 15;
                CP_ASYNC16(st2 + row * (KST*2) + c * 16, ksh + (size_t)row * (HK*HD) + c * 8);
                CP_ASYNC16(st2 + KMAT + row * (KST*2) + c * 16, ksl + (size_t)row * (HK*HD) + c * 8);
                int vrow = idx >> 3, vc = idx & 7;
                CP_ASYNC16(st2 + 2*KMAT + vrow * (VSTR*2) + vc * 16, vbh_g + (size_t)vrow * SS + kc + vc * 8);
                CP_ASYNC16(st2 + 2*KMAT + VMAT + vrow * (VSTR*2) + vc * 16, vbl_g + (size_t)vrow * SS + kc + vc * 8);
            }
        }
        CP_COMMIT();
    }

    // ---- epilogue: normalize, write bf16 hi/lo O ----
    float inv0 = 1.f / l0, inv1 = 1.f / l1;
    size_t obase = ((size_t)(b*SS + q0 + w*16 + (lane >> 2)) * H + h) * HD;
    #pragma unroll
    for (int nt = 0; nt < 16; nt++) {
        int d = nt * 8 + gc_base;
        float a0 = oacc[nt][0] * inv0, a1 = oacc[nt][1] * inv0;
        float a2 = oacc[nt][2] * inv1, a3 = oacc[nt][3] * inv1;
        __nv_bfloat16 h0 = __float2bfloat16(a0), h1 = __float2bfloat16(a1);
        __nv_bfloat16 h2 = __float2bfloat16(a2), h3 = __float2bfloat16(a3);
        __nv_bfloat162 hv0(h0, h1), hv1(h2, h3);
        *(uint32_t*)(oh + obase + d) = *(uint32_t*)&hv0;
        *(uint32_t*)(oh + obase + (size_t)8 * H * HD + d) = *(uint32_t*)&hv1;
        *(uint32_t*)(ol + obase + d) =
            pack_bf2(a0 - __bfloat162float(h0), a1 - __bfloat162float(h1));
        *(uint32_t*)(ol + obase + (size_t)8 * H * HD + d) =
            pack_bf2(a2 - __bfloat162float(h2), a3 - __bfloat162float(h3));
    }
}

// ---------------- launch ----------------------------------------------------
extern "C" void kernel_launch(void* const* d_in, const int* in_sizes, int n_in,
                              void* d_out, int out_size)
{
    (void)in_sizes; (void)n_in; (void)out_size;
    const float* x  = (const float*)d_in[0];
    const float* wq = (const float*)d_in[1];
    const float* wk = (const float*)d_in[2];
    const float* wv = (const float*)d_in[3];
    const float* wo = (const float*)d_in[4];
    const float* qw = (const float*)d_in[5];
    const float* kw = (const float*)d_in[6];
    float* out = (float*)d_out;

    float *q, *k, *v;
    cudaGetSymbolAddress((void**)&q, g_q);
    cudaGetSymbolAddress((void**)&k, g_k);
    cudaGetSymbolAddress((void**)&v, g_v);

    __nv_bfloat16 *xh, *xl, *wqh, *wql, *wkh, *wkl, *wvh, *wvl, *woh, *wol, *oh, *ol;
    __nv_bfloat16 *qah, *qal, *kah, *kal, *vth, *vtl;
    cudaGetSymbolAddress((void**)&xh,  g_xh);  cudaGetSymbolAddress((void**)&xl,  g_xl);
    cudaGetSymbolAddress((void**)&wqh, g_wqh); cudaGetSymbolAddress((void**)&wql, g_wql);
    cudaGetSymbolAddress((void**)&wkh, g_wkh); cudaGetSymbolAddress((void**)&wkl, g_wkl);
    cudaGetSymbolAddress((void**)&wvh, g_wvh); cudaGetSymbolAddress((void**)&wvl, g_wvl);
    cudaGetSymbolAddress((void**)&woh, g_woh); cudaGetSymbolAddress((void**)&wol, g_wol);
    cudaGetSymbolAddress((void**)&oh,  g_oh);  cudaGetSymbolAddress((void**)&ol,  g_ol);
    cudaGetSymbolAddress((void**)&qah, g_qah); cudaGetSymbolAddress((void**)&qal, g_qal);
    cudaGetSymbolAddress((void**)&kah, g_kah); cudaGetSymbolAddress((void**)&kal, g_kal);
    cudaGetSymbolAddress((void**)&vth, g_vth); cudaGetSymbolAddress((void**)&vtl, g_vtl);

    cudaFuncSetAttribute(gemm_split, cudaFuncAttributeMaxDynamicSharedMemorySize, GEMM_SMEM);
    cudaFuncSetAttribute(attn_mma, cudaFuncAttributeMaxDynamicSharedMemorySize, ATT_SMEM);

    // hi/lo splits of inputs
    split_bf16<<<(MTOT*DD/4 + 255)/256, 256>>>(x,  xh,  xl,  MTOT*DD/4);
    split_bf16<<<(H*HD*DD/4 + 255)/256, 256>>>(wq, wqh, wql, H*HD*DD/4);
    split_bf16<<<(HK*HD*DD/4 + 255)/256, 256>>>(wk, wkh, wkl, HK*HD*DD/4);
    split_bf16<<<(HK*HD*DD/4 + 255)/256, 256>>>(wv, wvh, wvl, HK*HD*DD/4);
    split_bf16<<<(DD*H*HD/4 + 255)/256, 256>>>(wo, woh, wol, DD*H*HD/4);

    rope_table<<<SS, 64>>>();

    // QKV projections
    gemm_split<<<dim3((H*HD)/128,  MTOT/128), 256, GEMM_SMEM>>>(xh, xl, wqh, wql, q, H*HD,  DD);
    gemm_split<<<dim3((HK*HD)/128, MTOT/128), 256, GEMM_SMEM>>>(xh, xl, wkh, wkl, k, HK*HD, DD);
    gemm_split<<<dim3((HK*HD)/128, MTOT/128), 256, GEMM_SMEM>>>(xh, xl, wvh, wvl, v, HK*HD, DD);

    // RMSNorm + RoPE -> bf16 hi/lo attention operands
    norm_rope_split<<<(MTOT*H )/8, 256>>>(q, qah, qal, qw, H);
    norm_rope_split<<<(MTOT*HK)/8, 256>>>(k, kah, kal, kw, HK);
    transp_split_v<<<dim3(SS/32, HD/32, BB*HK), 256>>>(v, vth, vtl);

    // causal attention on tensor cores
    attn_mma<<<dim3(SS/128, H, BB), 256, ATT_SMEM>>>(qah, qal, kah, kal, vth, vtl, oh, ol);

    // output projection
    gemm_split<<<dim3(DD/128, MTOT/128), 256, GEMM_SMEM>>>(oh, ol, woh, wol, out, DD, H*HD);
}

// round 8
// speedup vs baseline: 3.2120x; 1.3374x over previous
#include <cuda_runtime.h>
#include <cuda_fp16.h>
#include <math.h>
#include <stdint.h>

#define BB 2
#define SS 2048
#define DD 2048
#define H 16
#define HK 8
#define HD 128
#define MTOT (BB*SS)   // 4096

// ---------------- scratch (allocation-free: device globals) ----------------
__device__ float g_q[(size_t)MTOT * H * HD];
__device__ float g_k[(size_t)MTOT * HK * HD];
__device__ float g_v[(size_t)MTOT * HK * HD];
__device__ float g_cos[SS * 64];
__device__ float g_sin[SS * 64];

// fp16 operands: A-side split (hi+lo), B-side single
__device__ __align__(16) __half g_xh[(size_t)MTOT * DD];
__device__ __align__(16) __half g_xl[(size_t)MTOT * DD];
__device__ __align__(16) __half g_wq16[(size_t)(H*HD) * DD];
__device__ __align__(16) __half g_wk16[(size_t)(HK*HD) * DD];
__device__ __align__(16) __half g_wv16[(size_t)(HK*HD) * DD];
__device__ __align__(16) __half g_wo16[(size_t)DD * (H*HD)];
__device__ __align__(16) __half g_oh[(size_t)MTOT * (H*HD)];
__device__ __align__(16) __half g_ol[(size_t)MTOT * (H*HD)];
__device__ __align__(16) __half g_qah[(size_t)MTOT * H * HD];
__device__ __align__(16) __half g_qal[(size_t)MTOT * H * HD];
__device__ __align__(16) __half g_k16[(size_t)MTOT * HK * HD];
__device__ __align__(16) __half g_vt16[(size_t)MTOT * HK * HD];  // [b][hk][d][tok]

// ---------------- asm helpers ----------------------------------------------
__device__ __forceinline__ uint32_t smem_u32(const void* p) {
    uint32_t a;
    asm("{ .reg .u64 t; cvta.to.shared.u64 t, %1; cvt.u32.u64 %0, t; }" : "=r"(a) : "l"(p));
    return a;
}

#define CP_ASYNC16(dst, src) \
    asm volatile("cp.async.cg.shared.global [%0], [%1], 16;" :: "r"(dst), "l"(src))
#define CP_COMMIT() asm volatile("cp.async.commit_group;" ::: "memory")
#define CP_WAIT2()  asm volatile("cp.async.wait_group 2;" ::: "memory")
#define CP_WAIT1()  asm volatile("cp.async.wait_group 1;" ::: "memory")
#define CP_WAIT0()  asm volatile("cp.async.wait_group 0;" ::: "memory")

__device__ __forceinline__ void ldsm4(uint32_t* r, uint32_t a) {
    asm volatile("ldmatrix.sync.aligned.m8n8.x4.shared.b16 {%0,%1,%2,%3}, [%4];"
        : "=r"(r[0]), "=r"(r[1]), "=r"(r[2]), "=r"(r[3]) : "r"(a));
}
__device__ __forceinline__ void ldsm2(uint32_t* r, uint32_t a) {
    asm volatile("ldmatrix.sync.aligned.m8n8.x2.shared.b16 {%0,%1}, [%2];"
        : "=r"(r[0]), "=r"(r[1]) : "r"(a));
}
__device__ __forceinline__ void mma_f16(float* c, const uint32_t* a, const uint32_t* b) {
    asm volatile("mma.sync.aligned.m16n8k16.row.col.f32.f16.f16.f32 "
        "{%0,%1,%2,%3}, {%4,%5,%6,%7}, {%8,%9}, {%0,%1,%2,%3};"
        : "+f"(c[0]), "+f"(c[1]), "+f"(c[2]), "+f"(c[3])
        : "r"(a[0]), "r"(a[1]), "r"(a[2]), "r"(a[3]), "r"(b[0]), "r"(b[1]));
}

__device__ __forceinline__ uint32_t pack_hf2(float a, float b) {
    __half2 t;
    t.x = __float2half_rn(a);
    t.y = __float2half_rn(b);
    return *(uint32_t*)&t;
}

// --------- split-A fp16 GEMM via mma.sync: C = (Ah+Al) * B^T ---------------
// A (M,K): hi+lo fp16; W (N,K): single fp16. CTA 128x128, BK=32, 256 thr.
// 4-stage cp.async pipeline, smem stride 40 halves (conflict-free ldmatrix).
#define SST 40
#define MATB (128 * SST * 2)      // 10240 B per matrix
#define STG2 (3 * MATB)           // 30720 B per stage (Ah, Al, B)
#define GEMM_SMEM (4 * STG2)      // 122880 B

__device__ __forceinline__ void gemm_load_stage(
    uint32_t sbase, int slot,
    const __half* __restrict__ Ah, const __half* __restrict__ Al,
    const __half* __restrict__ B,
    int m0, int n0, int K, int k0, int t)
{
    uint32_t st = sbase + slot * STG2;
    const __half* gp[3] = {
        Ah + (size_t)m0 * K + k0, Al + (size_t)m0 * K + k0,
        B  + (size_t)n0 * K + k0 };
    #pragma unroll
    for (int mat = 0; mat < 3; mat++) {
        #pragma unroll
        for (int h = 0; h < 2; h++) {
            int c = t + h * 256;          // 0..511
            int row = c >> 2, col16 = c & 3;
            uint32_t dst = st + mat * MATB + row * (SST*2) + col16 * 16;
            const __half* src = gp[mat] + (size_t)row * K + col16 * 8;
            CP_ASYNC16(dst, src);
        }
    }
}

__global__ __launch_bounds__(256, 1)
void gemm_split(const __half* __restrict__ Ah, const __half* __restrict__ Al,
                const __half* __restrict__ B,
                float* __restrict__ C, int N, int K)
{
    extern __shared__ char smem[];
    const uint32_t sb = smem_u32(smem);
    const int t = threadIdx.x;
    const int lane = t & 31, wid = t >> 5;
    const int warp_m = wid >> 2;
    const int warp_n = wid & 3;
    const int m0 = blockIdx.y * 128, n0 = blockIdx.x * 128;
    const int niter = K >> 5;

    float acc[4][4][4];
    #pragma unroll
    for (int i = 0; i < 4; i++)
        #pragma unroll
        for (int j = 0; j < 4; j++)
            acc[i][j][0] = acc[i][j][1] = acc[i][j][2] = acc[i][j][3] = 0.f;

    #pragma unroll
    for (int s = 0; s < 3; s++) {
        if (s < niter) gemm_load_stage(sb, s, Ah, Al, B, m0, n0, K, s * 32, t);
        CP_COMMIT();
    }

    const int arow = warp_m * 64 + (lane & 15);
    const int acolh = (lane >> 4) * 8;
    const int l2 = lane & 15;
    const int brow = warp_n * 32 + (l2 & 7);
    const int bcolh = (l2 >> 3) * 8;

    for (int it = 0; it < niter; it++) {
        int ps = it + 3;
        if (ps < niter)
            gemm_load_stage(sb, ps & 3, Ah, Al, B, m0, n0, K, ps * 32, t);
        CP_COMMIT();
        CP_WAIT2();
        __syncthreads();

        uint32_t st = sb + (it & 3) * STG2;
        #pragma unroll
        for (int ks = 0; ks < 2; ks++) {
            uint32_t ah[4][4], al[4][4], bf[4][2];
            #pragma unroll
            for (int mt = 0; mt < 4; mt++) {
                uint32_t off = ((arow + mt * 16) * SST + ks * 16 + acolh) * 2;
                ldsm4(ah[mt], st + off);
                ldsm4(al[mt], st + MATB + off);
            }
            #pragma unroll
            for (int nt = 0; nt < 4; nt++) {
                uint32_t off = ((brow + nt * 8) * SST + ks * 16 + bcolh) * 2;
                ldsm2(bf[nt], st + 2 * MATB + off);
            }
            #pragma unroll
            for (int mt = 0; mt < 4; mt++)
                #pragma unroll
                for (int nt = 0; nt < 4; nt++)
                    mma_f16(acc[mt][nt], ah[mt], bf[nt]);
            #pragma unroll
            for (int mt = 0; mt < 4; mt++)
                #pragma unroll
                for (int nt = 0; nt < 4; nt++)
                    mma_f16(acc[mt][nt], al[mt], bf[nt]);
        }
        __syncthreads();
    }

    const int r0 = lane >> 2, c0 = (lane & 3) * 2;
    #pragma unroll
    for (int mt = 0; mt < 4; mt++) {
        #pragma unroll
        for (int nt = 0; nt < 4; nt++) {
            int row = m0 + warp_m * 64 + mt * 16 + r0;
            int col = n0 + warp_n * 32 + nt * 8 + c0;
            *(float2*)(C + (size_t)row * N + col) =
                make_float2(acc[mt][nt][0], acc[mt][nt][1]);
            *(float2*)(C + (size_t)(row + 8) * N + col) =
                make_float2(acc[mt][nt][2], acc[mt][nt][3]);
        }
    }
}

// ---------------- fp32 -> fp16 hi/lo split and single convert --------------
__global__ __launch_bounds__(256)
void split_fp16(const float* __restrict__ in, __half* __restrict__ hi,
                __half* __restrict__ lo, int n4)
{
    int i = blockIdx.x * blockDim.x + threadIdx.x;
    if (i >= n4) return;
    float4 v = ((const float4*)in)[i];
    __half h0 = __float2half_rn(v.x), h1 = __float2half_rn(v.y);
    __half h2 = __float2half_rn(v.z), h3 = __float2half_rn(v.w);
    __half2 hp0, hp1, lp0, lp1;
    hp0.x = h0; hp0.y = h1; hp1.x = h2; hp1.y = h3;
    lp0.x = __float2half_rn(v.x - __half2float(h0));
    lp0.y = __float2half_rn(v.y - __half2float(h1));
    lp1.x = __float2half_rn(v.z - __half2float(h2));
    lp1.y = __float2half_rn(v.w - __half2float(h3));
    ((__half2*)(hi + i * 4))[0] = hp0; ((__half2*)(hi + i * 4))[1] = hp1;
    ((__half2*)(lo + i * 4))[0] = lp0; ((__half2*)(lo + i * 4))[1] = lp1;
}

__global__ __launch_bounds__(256)
void conv_fp16(const float* __restrict__ in, __half* __restrict__ out, int n4)
{
    int i = blockIdx.x * blockDim.x + threadIdx.x;
    if (i >= n4) return;
    float4 v = ((const float4*)in)[i];
    __half2 p0, p1;
    p0.x = __float2half_rn(v.x); p0.y = __float2half_rn(v.y);
    p1.x = __float2half_rn(v.z); p1.y = __float2half_rn(v.w);
    ((__half2*)(out + i * 4))[0] = p0;
    ((__half2*)(out + i * 4))[1] = p1;
}

// ---------------- RoPE table ------------------------------------------------
__global__ void rope_table()
{
    int s = blockIdx.x;
    int j = threadIdx.x;
    double invd = pow(1.0e6, -(double)j / 64.0);
    float  ang  = (float)s * (float)invd;
    float  c, sn;
    sincosf(ang, &sn, &c);
    g_cos[s*64 + j] = c;
    g_sin[s*64 + j] = sn;
}

// -------- fused RMSNorm + RoPE --------------------------------------------
// emits fp16 hi/lo (Q) or fp16 single (K, lo==nullptr)
__global__ __launch_bounds__(256)
void norm_rope_f16(const float* __restrict__ buf, __half* __restrict__ outh,
                   __half* __restrict__ outl, const float* __restrict__ w, int nheads)
{
    int gw   = (blockIdx.x * blockDim.x + threadIdx.x) >> 5;
    int lane = threadIdx.x & 31;
    int m = gw / nheads;
    int h = gw - m * nheads;
    int s = m & (SS - 1);

    size_t base = ((size_t)m * nheads + h) * HD + lane * 4;
    float4 v = *(const float4*)(buf + base);
    float ss = v.x*v.x + v.y*v.y + v.z*v.z + v.w*v.w;
    #pragma unroll
    for (int o = 16; o; o >>= 1) ss += __shfl_xor_sync(0xffffffffu, ss, o);
    float r = rsqrtf(ss * (1.f/128.f) + 1e-6f);

    const float4 wv = *(const float4*)(w + lane*4);
    v.x *= r * wv.x; v.y *= r * wv.y; v.z *= r * wv.z; v.w *= r * wv.w;

    float4 pr;
    pr.x = __shfl_xor_sync(0xffffffffu, v.x, 16);
    pr.y = __shfl_xor_sync(0xffffffffu, v.y, 16);
    pr.z = __shfl_xor_sync(0xffffffffu, v.z, 16);
    pr.w = __shfl_xor_sync(0xffffffffu, v.w, 16);

    int jbase = (lane & 15) * 4;
    const float* cb = g_cos + s*64 + jbase;
    const float* sb = g_sin + s*64 + jbase;
    float sgn = (lane < 16) ? -1.f : 1.f;

    float o0 = v.x * cb[0] + sgn * pr.x * sb[0];
    float o1 = v.y * cb[1] + sgn * pr.y * sb[1];
    float o2 = v.z * cb[2] + sgn * pr.z * sb[2];
    float o3 = v.w * cb[3] + sgn * pr.w * sb[3];

    __half h0 = __float2half_rn(o0), h1 = __float2half_rn(o1);
    __half h2 = __float2half_rn(o2), h3 = __float2half_rn(o3);
    __half2 hp0, hp1;
    hp0.x = h0; hp0.y = h1; hp1.x = h2; hp1.y = h3;
    ((__half2*)(outh + base))[0] = hp0;
    ((__half2*)(outh + base))[1] = hp1;
    if (outl) {
        __half2 lp0, lp1;
        lp0.x = __float2half_rn(o0 - __half2float(h0));
        lp0.y = __float2half_rn(o1 - __half2float(h1));
        lp1.x = __float2half_rn(o2 - __half2float(h2));
        lp1.y = __float2half_rn(o3 - __half2float(h3));
        ((__half2*)(outl + base))[0] = lp0;
        ((__half2*)(outl + base))[1] = lp1;
    }
}

// ---- V transpose: [tok][hk][d] fp32 -> [b][hk][d][tok] fp16 single --------
__global__ __launch_bounds__(256)
void transp_v16(const float* __restrict__ v, __half* __restrict__ vt)
{
    __shared__ float tile[32][33];
    int t = threadIdx.x;
    int tx = t & 31, ty = t >> 5;
    int tok0 = blockIdx.x * 32, d0 = blockIdx.y * 32;
    int bh = blockIdx.z;
    int b = bh >> 3, hk = bh & 7;

    #pragma unroll
    for (int r = 0; r < 4; r++) {
        int tok = ty + r * 8;
        tile[tok][tx] = v[((size_t)(b*SS + tok0 + tok) * HK + hk) * HD + d0 + tx];
    }
    __syncthreads();
    #pragma unroll
    for (int r = 0; r < 4; r++) {
        int d = ty + r * 8;
        size_t idx = ((size_t)(b*HK + hk) * HD + d0 + d) * SS + tok0 + tx;
        vt[idx] = __float2half_rn(tile[tx][d]);
    }
}

// ---------------- mma.sync flash attention (causal, GQA rep=2) -------------
// Q split hi/lo + K single; P split hi/lo + V single. 2 MMA passes each.
#define KST 136                    // K/Q smem stride (halves)
#define VSTR 72                    // V^T smem stride (halves)
#define KMAT (64 * KST * 2)        // 17408 B (64-row K tile)
#define QMAT (128 * KST * 2)       // 34816 B
#define QAREA (2 * QMAT)           // 69632 B (Q hi + Q lo, dedicated)
#define VMAT (128 * VSTR * 2)      // 18432 B
#define ASTG (KMAT + VMAT)         // 35840 B per stage (K single + V single)
#define ATT_SMEM (QAREA + 2 * ASTG) // 141312 B

__global__ __launch_bounds__(256, 1)
void attn_mma(const __half* __restrict__ qh, const __half* __restrict__ ql,
              const __half* __restrict__ k16, const __half* __restrict__ vt16,
              __half* __restrict__ oh, __half* __restrict__ ol)
{
    extern __shared__ char smem[];
    const uint32_t sb = smem_u32(smem);
    const int t = threadIdx.x, lane = t & 31, w = t >> 5;
    const int b = blockIdx.z, h = blockIdx.y, qblk = blockIdx.x;
    const int hk = h >> 1, q0 = qblk * 128;
    const int ntiles = 2 * qblk + 2;
    const float scale = 0.08838834764831845f;

    const __half* kb_g = k16 + ((size_t)(b*SS) * HK + hk) * HD;
    const __half* vb_g = vt16 + (size_t)(b*HK + hk) * HD * SS;

    // ---- Q into dedicated area ----
    {
        const __half* qsh = qh + ((size_t)(b*SS + q0) * H + h) * HD;
        const __half* qsl = ql + ((size_t)(b*SS + q0) * H + h) * HD;
        #pragma unroll
        for (int i = 0; i < 8; i++) {
            int idx = t + i * 256;            // 0..2047
            int row = idx >> 4, c = idx & 15;
            CP_ASYNC16(sb + row * (KST*2) + c * 16, qsh + (size_t)row * (H*HD) + c * 8);
            CP_ASYNC16(sb + QMAT + row * (KST*2) + c * 16, qsl + (size_t)row * (H*HD) + c * 8);
        }
        CP_COMMIT();
    }
    // stage 0 (kt=0)
    {
        uint32_t st = sb + QAREA;
        #pragma unroll
        for (int i = 0; i < 4; i++) {
            int idx = t + i * 256;            // 0..1023
            int row = idx >> 4, c = idx & 15;
            CP_ASYNC16(st + row * (KST*2) + c * 16, kb_g + (size_t)row * (HK*HD) + c * 8);
            int vrow = idx >> 3, vc = idx & 7;
            CP_ASYNC16(st + KMAT + vrow * (VSTR*2) + vc * 16, vb_g + (size_t)vrow * SS + vc * 8);
        }
        CP_COMMIT();
    }
    CP_WAIT1();      // Q group done
    __syncthreads();

    // extract Q fragments
    uint32_t qfh[8][4], qfl[8][4];
    {
        uint32_t roff = (w * 16 + (lane & 15)) * (KST*2) + ((lane >> 4) & 1) * 16;
        #pragma unroll
        for (int ks = 0; ks < 8; ks++) {
            ldsm4(qfh[ks], sb + roff + ks * 32);
            ldsm4(qfl[ks], sb + QMAT + roff + ks * 32);
        }
    }
    // stage 1 (kt=1)
    {
        uint32_t st = sb + QAREA + ASTG;
        const __half* ksh = kb_g + (size_t)64 * (HK*HD);
        #pragma unroll
        for (int i = 0; i < 4; i++) {
            int idx = t + i * 256;
            int row = idx >> 4, c = idx & 15;
            CP_ASYNC16(st + row * (KST*2) + c * 16, ksh + (size_t)row * (HK*HD) + c * 8);
            int vrow = idx >> 3, vc = idx & 7;
            CP_ASYNC16(st + KMAT + vrow * (VSTR*2) + vc * 16, vb_g + (size_t)vrow * SS + 64 + vc * 8);
        }
        CP_COMMIT();
    }

    float oacc[16][4];
    #pragma unroll
    for (int i = 0; i < 16; i++) oacc[i][0] = oacc[i][1] = oacc[i][2] = oacc[i][3] = 0.f;
    float m0 = -1e30f, m1 = -1e30f, l0 = 0.f, l1 = 0.f;

    const int gr0 = q0 + w * 16 + (lane >> 2);
    const int gc_base = (lane & 3) * 2;

    for (int kt = 0; kt < ntiles; kt++) {
        if (kt + 1 < ntiles) { CP_WAIT1(); } else { CP_WAIT0(); }
        __syncthreads();
        uint32_t st = sb + QAREA + (kt & 1) * ASTG;

        // ---- S = Q K^T : (Qh + Ql) * K ----
        float s[8][4];
        #pragma unroll
        for (int i = 0; i < 8; i++) s[i][0] = s[i][1] = s[i][2] = s[i][3] = 0.f;

        #pragma unroll
        for (int ks = 0; ks < 8; ks++) {
            uint32_t lrow = (lane & 7) + ((lane >> 4) << 3);
            uint32_t lcol = (ks * 16 + ((lane >> 3) & 1) * 8) * 2;
            uint32_t kf[4][4];
            #pragma unroll
            for (int p = 0; p < 4; p++) {
                ldsm4(kf[p], st + (p * 16 + lrow) * (KST*2) + lcol);
                mma_f16(s[2*p],   qfh[ks], &kf[p][0]);
                mma_f16(s[2*p+1], qfh[ks], &kf[p][2]);
            }
            #pragma unroll
            for (int p = 0; p < 4; p++) {
                mma_f16(s[2*p],   qfl[ks], &kf[p][0]);
                mma_f16(s[2*p+1], qfl[ks], &kf[p][2]);
            }
        }

        // ---- softmax (fp32, warp-local rows) ----
        const int kc0 = kt * 64;
        bool fullok = (kc0 + 63 <= q0 + w * 16);
        #pragma unroll
        for (int nt = 0; nt < 8; nt++) {
            if (fullok) {
                s[nt][0] *= scale; s[nt][1] *= scale; s[nt][2] *= scale; s[nt][3] *= scale;
            } else {
                int gc = kc0 + nt * 8 + gc_base;
                s[nt][0] = (gc     <= gr0    ) ? s[nt][0] * scale : -1e30f;
                s[nt][1] = (gc + 1 <= gr0    ) ? s[nt][1] * scale : -1e30f;
                s[nt][2] = (gc     <= gr0 + 8) ? s[nt][2] * scale : -1e30f;
                s[nt][3] = (gc + 1 <= gr0 + 8) ? s[nt][3] * scale : -1e30f;
            }
        }
        float mx0 = -1e30f, mx1 = -1e30f;
        #pragma unroll
        for (int nt = 0; nt < 8; nt++) {
            mx0 = fmaxf(mx0, fmaxf(s[nt][0], s[nt][1]));
            mx1 = fmaxf(mx1, fmaxf(s[nt][2], s[nt][3]));
        }
        #pragma unroll
        for (int o = 1; o <= 2; o <<= 1) {
            mx0 = fmaxf(mx0, __shfl_xor_sync(0xffffffffu, mx0, o));
            mx1 = fmaxf(mx1, __shfl_xor_sync(0xffffffffu, mx1, o));
        }
        float mn0 = fmaxf(m0, mx0), mn1 = fmaxf(m1, mx1);
        float cr0 = __expf(m0 - mn0), cr1 = __expf(m1 - mn1);
        m0 = mn0; m1 = mn1;
        #pragma unroll
        for (int nt = 0; nt < 16; nt++) {
            oacc[nt][0] *= cr0; oacc[nt][1] *= cr0;
            oacc[nt][2] *= cr1; oacc[nt][3] *= cr1;
        }

        uint32_t pfh[4][4], pfl[4][4];
        float sum0 = 0.f, sum1 = 0.f;
        #pragma unroll
        for (int nt = 0; nt < 8; nt++) {
            float p0 = __expf(s[nt][0] - mn0);
            float p1 = __expf(s[nt][1] - mn0);
            float p2 = __expf(s[nt][2] - mn1);
            float p3 = __expf(s[nt][3] - mn1);
            sum0 += p0 + p1; sum1 += p2 + p3;
            __half b0 = __float2half_rn(p0), b1 = __float2half_rn(p1);
            __half b2 = __float2half_rn(p2), b3 = __float2half_rn(p3);
            int j = nt >> 1, hi2 = (nt & 1) * 2;
            __half2 ph0, ph1;
            ph0.x = b0; ph0.y = b1; ph1.x = b2; ph1.y = b3;
            pfh[j][hi2]     = *(uint32_t*)&ph0;
            pfh[j][hi2 + 1] = *(uint32_t*)&ph1;
            pfl[j][hi2]     = pack_hf2(p0 - __half2float(b0), p1 - __half2float(b1));
            pfl[j][hi2 + 1] = pack_hf2(p2 - __half2float(b2), p3 - __half2float(b3));
        }
        #pragma unroll
        for (int o = 1; o <= 2; o <<= 1) {
            sum0 += __shfl_xor_sync(0xffffffffu, sum0, o);
            sum1 += __shfl_xor_sync(0xffffffffu, sum1, o);
        }
        l0 = l0 * cr0 + sum0;
        l1 = l1 * cr1 + sum1;

        // ---- O += (Ph + Pl) V ; V^T tile [128 d][64 keys] single fp16 ----
        uint32_t vst = st + KMAT;
        #pragma unroll
        for (int ks = 0; ks < 4; ks++) {
            uint32_t lrow = (lane & 7) + ((lane >> 4) << 3);
            uint32_t lcol = (ks * 16 + ((lane >> 3) & 1) * 8) * 2;
            #pragma unroll
            for (int p = 0; p < 8; p++) {
                uint32_t vb[4];
                ldsm4(vb, vst + (p * 16 + lrow) * (VSTR*2) + lcol);
                mma_f16(oacc[2*p],   pfh[ks], &vb[0]);
                mma_f16(oacc[2*p+1], pfh[ks], &vb[2]);
                mma_f16(oacc[2*p],   pfl[ks], &vb[0]);
                mma_f16(oacc[2*p+1], pfl[ks], &vb[2]);
            }
        }

        __syncthreads();
        // prefetch kt+2
        if (kt + 2 < ntiles) {
            uint32_t st2 = sb + QAREA + (kt & 1) * ASTG;
            int kc = (kt + 2) * 64;
            const __half* ksh = kb_g + (size_t)kc * (HK*HD);
            #pragma unroll
            for (int i = 0; i < 4; i++) {
                int idx = t + i * 256;
                int row = idx >> 4, c = idx & 15;
                CP_ASYNC16(st2 + row * (KST*2) + c * 16, ksh + (size_t)row * (HK*HD) + c * 8);
                int vrow = idx >> 3, vc = idx & 7;
                CP_ASYNC16(st2 + KMAT + vrow * (VSTR*2) + vc * 16, vb_g + (size_t)vrow * SS + kc + vc * 8);
            }
        }
        CP_COMMIT();
    }

    // ---- epilogue: normalize, write fp16 hi/lo O ----
    float inv0 = 1.f / l0, inv1 = 1.f / l1;
    size_t obase = ((size_t)(b*SS + q0 + w*16 + (lane >> 2)) * H + h) * HD;
    #pragma unroll
    for (int nt = 0; nt < 16; nt++) {
        int d = nt * 8 + gc_base;
        float a0 = oacc[nt][0] * inv0, a1 = oacc[nt][1] * inv0;
        float a2 = oacc[nt][2] * inv1, a3 = oacc[nt][3] * inv1;
        __half h0 = __float2half_rn(a0), h1 = __float2half_rn(a1);
        __half h2 = __float2half_rn(a2), h3 = __float2half_rn(a3);
        __half2 hv0, hv1;
        hv0.x = h0; hv0.y = h1; hv1.x = h2; hv1.y = h3;
        *(uint32_t*)(oh + obase + d) = *(uint32_t*)&hv0;
        *(uint32_t*)(oh + obase + (size_t)8 * H * HD + d) = *(uint32_t*)&hv1;
        *(uint32_t*)(ol + obase + d) =
            pack_hf2(a0 - __half2float(h0), a1 - __half2float(h1));
        *(uint32_t*)(ol + obase + (size_t)8 * H * HD + d) =
            pack_hf2(a2 - __half2float(h2), a3 - __half2float(h3));
    }
}

// ---------------- launch ----------------------------------------------------
extern "C" void kernel_launch(void* const* d_in, const int* in_sizes, int n_in,
                              void* d_out, int out_size)
{
    (void)in_sizes; (void)n_in; (void)out_size;
    const float* x  = (const float*)d_in[0];
    const float* wq = (const float*)d_in[1];
    const float* wk = (const float*)d_in[2];
    const float* wv = (const float*)d_in[3];
    const float* wo = (const float*)d_in[4];
    const float* qw = (const float*)d_in[5];
    const float* kw = (const float*)d_in[6];
    float* out = (float*)d_out;

    float *q, *k, *v;
    cudaGetSymbolAddress((void**)&q, g_q);
    cudaGetSymbolAddress((void**)&k, g_k);
    cudaGetSymbolAddress((void**)&v, g_v);

    __half *xh, *xl, *wq16, *wk16, *wv16, *wo16, *oh, *ol, *qah, *qal, *k16, *vt16;
    cudaGetSymbolAddress((void**)&xh,   g_xh);   cudaGetSymbolAddress((void**)&xl,   g_xl);
    cudaGetSymbolAddress((void**)&wq16, g_wq16); cudaGetSymbolAddress((void**)&wk16, g_wk16);
    cudaGetSymbolAddress((void**)&wv16, g_wv16); cudaGetSymbolAddress((void**)&wo16, g_wo16);
    cudaGetSymbolAddress((void**)&oh,   g_oh);   cudaGetSymbolAddress((void**)&ol,   g_ol);
    cudaGetSymbolAddress((void**)&qah,  g_qah);  cudaGetSymbolAddress((void**)&qal,  g_qal);
    cudaGetSymbolAddress((void**)&k16,  g_k16);  cudaGetSymbolAddress((void**)&vt16, g_vt16);

    cudaFuncSetAttribute(gemm_split, cudaFuncAttributeMaxDynamicSharedMemorySize, GEMM_SMEM);
    cudaFuncSetAttribute(attn_mma, cudaFuncAttributeMaxDynamicSharedMemorySize, ATT_SMEM);

    // operand conversion
    split_fp16<<<(MTOT*DD/4 + 255)/256, 256>>>(x, xh, xl, MTOT*DD/4);
    conv_fp16<<<(H*HD*DD/4 + 255)/256, 256>>>(wq, wq16, H*HD*DD/4);
    conv_fp16<<<(HK*HD*DD/4 + 255)/256, 256>>>(wk, wk16, HK*HD*DD/4);
    conv_fp16<<<(HK*HD*DD/4 + 255)/256, 256>>>(wv, wv16, HK*HD*DD/4);
    conv_fp16<<<(DD*H*HD/4 + 255)/256, 256>>>(wo, wo16, DD*H*HD/4);

    rope_table<<<SS, 64>>>();

    // QKV projections: C = (xh + xl) @ w16^T
    gemm_split<<<dim3((H*HD)/128,  MTOT/128), 256, GEMM_SMEM>>>(xh, xl, wq16, q, H*HD,  DD);
    gemm_split<<<dim3((HK*HD)/128, MTOT/128), 256, GEMM_SMEM>>>(xh, xl, wk16, k, HK*HD, DD);
    gemm_split<<<dim3((HK*HD)/128, MTOT/128), 256, GEMM_SMEM>>>(xh, xl, wv16, v, HK*HD, DD);

    // RMSNorm + RoPE: Q -> hi/lo, K -> single
    norm_rope_f16<<<(MTOT*H )/8, 256>>>(q, qah, qal, qw, H);
    norm_rope_f16<<<(MTOT*HK)/8, 256>>>(k, k16, nullptr, kw, HK);
    transp_v16<<<dim3(SS/32, HD/32, BB*HK), 256>>>(v, vt16);

    // causal attention on tensor cores
    attn_mma<<<dim3(SS/128, H, BB), 256, ATT_SMEM>>>(qah, qal, k16, vt16, oh, ol);

    // output projection: out = (oh + ol) @ wo16^T
    gemm_split<<<dim3(DD/128, MTOT/128), 256, GEMM_SMEM>>>(oh, ol, wo16, out, DD, H*HD);
}

// round 9
// speedup vs baseline: 4.9044x; 1.5269x over previous
#include <cuda_runtime.h>
#include <cuda_fp16.h>
#include <math.h>
#include <stdint.h>

#define BB 2
#define SS 2048
#define DD 2048
#define H 16
#define HK 8
#define HD 128
#define MTOT (BB*SS)   // 4096

// ---------------- scratch (allocation-free: device globals) ----------------
__device__ float g_q[(size_t)MTOT * H * HD];
__device__ float g_k[(size_t)MTOT * HK * HD];
__device__ float g_v[(size_t)MTOT * HK * HD];
__device__ float g_cos[SS * 64];
__device__ float g_sin[SS * 64];

__device__ __align__(16) __half g_x16[(size_t)MTOT * DD];
__device__ __align__(16) __half g_wq16[(size_t)(H*HD) * DD];
__device__ __align__(16) __half g_wk16[(size_t)(HK*HD) * DD];
__device__ __align__(16) __half g_wv16[(size_t)(HK*HD) * DD];
__device__ __align__(16) __half g_wo16[(size_t)DD * (H*HD)];
__device__ __align__(16) __half g_o16[(size_t)MTOT * (H*HD)];
__device__ __align__(16) __half g_qah[(size_t)MTOT * H * HD];
__device__ __align__(16) __half g_qal[(size_t)MTOT * H * HD];
__device__ __align__(16) __half g_k16[(size_t)MTOT * HK * HD];
__device__ __align__(16) __half g_vt16[(size_t)MTOT * HK * HD];  // [b][hk][d][tok]

// ---------------- asm helpers ----------------------------------------------
__device__ __forceinline__ uint32_t smem_u32(const void* p) {
    uint32_t a;
    asm("{ .reg .u64 t; cvta.to.shared.u64 t, %1; cvt.u32.u64 %0, t; }" : "=r"(a) : "l"(p));
    return a;
}

#define CP_ASYNC16(dst, src) \
    asm volatile("cp.async.cg.shared.global [%0], [%1], 16;" :: "r"(dst), "l"(src))
#define CP_COMMIT() asm volatile("cp.async.commit_group;" ::: "memory")
#define CP_WAIT2()  asm volatile("cp.async.wait_group 2;" ::: "memory")
#define CP_WAIT1()  asm volatile("cp.async.wait_group 1;" ::: "memory")
#define CP_WAIT0()  asm volatile("cp.async.wait_group 0;" ::: "memory")

__device__ __forceinline__ void ldsm4(uint32_t* r, uint32_t a) {
    asm volatile("ldmatrix.sync.aligned.m8n8.x4.shared.b16 {%0,%1,%2,%3}, [%4];"
        : "=r"(r[0]), "=r"(r[1]), "=r"(r[2]), "=r"(r[3]) : "r"(a));
}
__device__ __forceinline__ void ldsm2(uint32_t* r, uint32_t a) {
    asm volatile("ldmatrix.sync.aligned.m8n8.x2.shared.b16 {%0,%1}, [%2];"
        : "=r"(r[0]), "=r"(r[1]) : "r"(a));
}
__device__ __forceinline__ void mma_f16(float* c, const uint32_t* a, const uint32_t* b) {
    asm volatile("mma.sync.aligned.m16n8k16.row.col.f32.f16.f16.f32 "
        "{%0,%1,%2,%3}, {%4,%5,%6,%7}, {%8,%9}, {%0,%1,%2,%3};"
        : "+f"(c[0]), "+f"(c[1]), "+f"(c[2]), "+f"(c[3])
        : "r"(a[0]), "r"(a[1]), "r"(a[2]), "r"(a[3]), "r"(b[0]), "r"(b[1]));
}

__device__ __forceinline__ uint32_t pack_hf2(float a, float b) {
    __half2 t;
    t.x = __float2half_rn(a);
    t.y = __float2half_rn(b);
    return *(uint32_t*)&t;
}

// --------- single-pass fp16 GEMM via mma.sync: C = A * B^T -----------------
// A (M,K) fp16, W (N,K) fp16, C (M,N) fp32. CTA 128x128, BK=32, 256 thr.
// 4-stage cp.async pipeline, smem stride 40 halves (conflict-free ldmatrix).
#define SST 40
#define MATB (128 * SST * 2)      // 10240 B per matrix
#define STG1 (2 * MATB)           // 20480 B per stage (A, B)
#define GEMM_SMEM (4 * STG1)      // 81920 B  -> 2 CTAs/SM

__device__ __forceinline__ void gemm_load_stage(
    uint32_t sbase, int slot,
    const __half* __restrict__ A, const __half* __restrict__ B,
    int m0, int n0, int K, int k0, int t)
{
    uint32_t st = sbase + slot * STG1;
    const __half* gp[2] = { A + (size_t)m0 * K + k0, B + (size_t)n0 * K + k0 };
    #pragma unroll
    for (int mat = 0; mat < 2; mat++) {
        #pragma unroll
        for (int h = 0; h < 2; h++) {
            int c = t + h * 256;          // 0..511
            int row = c >> 2, col16 = c & 3;
            uint32_t dst = st + mat * MATB + row * (SST*2) + col16 * 16;
            const __half* src = gp[mat] + (size_t)row * K + col16 * 8;
            CP_ASYNC16(dst, src);
        }
    }
}

__global__ __launch_bounds__(256, 2)
void gemm_f16(const __half* __restrict__ A, const __half* __restrict__ B,
              float* __restrict__ C, int N, int K)
{
    extern __shared__ char smem[];
    const uint32_t sb = smem_u32(smem);
    const int t = threadIdx.x;
    const int lane = t & 31, wid = t >> 5;
    const int warp_m = wid >> 2;
    const int warp_n = wid & 3;
    const int m0 = blockIdx.y * 128, n0 = blockIdx.x * 128;
    const int niter = K >> 5;

    float acc[4][4][4];
    #pragma unroll
    for (int i = 0; i < 4; i++)
        #pragma unroll
        for (int j = 0; j < 4; j++)
            acc[i][j][0] = acc[i][j][1] = acc[i][j][2] = acc[i][j][3] = 0.f;

    #pragma unroll
    for (int s = 0; s < 3; s++) {
        if (s < niter) gemm_load_stage(sb, s, A, B, m0, n0, K, s * 32, t);
        CP_COMMIT();
    }

    const int arow = warp_m * 64 + (lane & 15);
    const int acolh = (lane >> 4) * 8;
    const int l2 = lane & 15;
    const int brow = warp_n * 32 + (l2 & 7);
    const int bcolh = (l2 >> 3) * 8;

    for (int it = 0; it < niter; it++) {
        int ps = it + 3;
        if (ps < niter)
            gemm_load_stage(sb, ps & 3, A, B, m0, n0, K, ps * 32, t);
        CP_COMMIT();
        CP_WAIT2();
        __syncthreads();

        uint32_t st = sb + (it & 3) * STG1;
        #pragma unroll
        for (int ks = 0; ks < 2; ks++) {
            uint32_t af[4][4], bf[4][2];
            #pragma unroll
            for (int mt = 0; mt < 4; mt++) {
                uint32_t off = ((arow + mt * 16) * SST + ks * 16 + acolh) * 2;
                ldsm4(af[mt], st + off);
            }
            #pragma unroll
            for (int nt = 0; nt < 4; nt++) {
                uint32_t off = ((brow + nt * 8) * SST + ks * 16 + bcolh) * 2;
                ldsm2(bf[nt], st + MATB + off);
            }
            #pragma unroll
            for (int mt = 0; mt < 4; mt++)
                #pragma unroll
                for (int nt = 0; nt < 4; nt++)
                    mma_f16(acc[mt][nt], af[mt], bf[nt]);
        }
        __syncthreads();
    }

    const int r0 = lane >> 2, c0 = (lane & 3) * 2;
    #pragma unroll
    for (int mt = 0; mt < 4; mt++) {
        #pragma unroll
        for (int nt = 0; nt < 4; nt++) {
            int row = m0 + warp_m * 64 + mt * 16 + r0;
            int col = n0 + warp_n * 32 + nt * 8 + c0;
            *(float2*)(C + (size_t)row * N + col) =
                make_float2(acc[mt][nt][0], acc[mt][nt][1]);
            *(float2*)(C + (size_t)(row + 8) * N + col) =
                make_float2(acc[mt][nt][2], acc[mt][nt][3]);
        }
    }
}

// ---------------- fp32 -> fp16 convert -------------------------------------
__global__ __launch_bounds__(256)
void conv_fp16(const float* __restrict__ in, __half* __restrict__ out, int n4)
{
    int i = blockIdx.x * blockDim.x + threadIdx.x;
    if (i >= n4) return;
    float4 v = ((const float4*)in)[i];
    __half2 p0, p1;
    p0.x = __float2half_rn(v.x); p0.y = __float2half_rn(v.y);
    p1.x = __float2half_rn(v.z); p1.y = __float2half_rn(v.w);
    ((__half2*)(out + i * 4))[0] = p0;
    ((__half2*)(out + i * 4))[1] = p1;
}

// ---------------- RoPE table ------------------------------------------------
__global__ void rope_table()
{
    int s = blockIdx.x;
    int j = threadIdx.x;
    double invd = pow(1.0e6, -(double)j / 64.0);
    float  ang  = (float)s * (float)invd;
    float  c, sn;
    sincosf(ang, &sn, &c);
    g_cos[s*64 + j] = c;
    g_sin[s*64 + j] = sn;
}

// -------- fused RMSNorm + RoPE: fp16 hi/lo (Q) or single (K) ---------------
__global__ __launch_bounds__(256)
void norm_rope_f16(const float* __restrict__ buf, __half* __restrict__ outh,
                   __half* __restrict__ outl, const float* __restrict__ w, int nheads)
{
    int gw   = (blockIdx.x * blockDim.x + threadIdx.x) >> 5;
    int lane = threadIdx.x & 31;
    int m = gw / nheads;
    int h = gw - m * nheads;
    int s = m & (SS - 1);

    size_t base = ((size_t)m * nheads + h) * HD + lane * 4;
    float4 v = *(const float4*)(buf + base);
    float ss = v.x*v.x + v.y*v.y + v.z*v.z + v.w*v.w;
    #pragma unroll
    for (int o = 16; o; o >>= 1) ss += __shfl_xor_sync(0xffffffffu, ss, o);
    float r = rsqrtf(ss * (1.f/128.f) + 1e-6f);

    const float4 wv = *(const float4*)(w + lane*4);
    v.x *= r * wv.x; v.y *= r * wv.y; v.z *= r * wv.z; v.w *= r * wv.w;

    float4 pr;
    pr.x = __shfl_xor_sync(0xffffffffu, v.x, 16);
    pr.y = __shfl_xor_sync(0xffffffffu, v.y, 16);
    pr.z = __shfl_xor_sync(0xffffffffu, v.z, 16);
    pr.w = __shfl_xor_sync(0xffffffffu, v.w, 16);

    int jbase = (lane & 15) * 4;
    const float* cb = g_cos + s*64 + jbase;
    const float* sb = g_sin + s*64 + jbase;
    float sgn = (lane < 16) ? -1.f : 1.f;

    float o0 = v.x * cb[0] + sgn * pr.x * sb[0];
    float o1 = v.y * cb[1] + sgn * pr.y * sb[1];
    float o2 = v.z * cb[2] + sgn * pr.z * sb[2];
    float o3 = v.w * cb[3] + sgn * pr.w * sb[3];

    __half h0 = __float2half_rn(o0), h1 = __float2half_rn(o1);
    __half h2 = __float2half_rn(o2), h3 = __float2half_rn(o3);
    __half2 hp0, hp1;
    hp0.x = h0; hp0.y = h1; hp1.x = h2; hp1.y = h3;
    ((__half2*)(outh + base))[0] = hp0;
    ((__half2*)(outh + base))[1] = hp1;
    if (outl) {
        __half2 lp0, lp1;
        lp0.x = __float2half_rn(o0 - __half2float(h0));
        lp0.y = __float2half_rn(o1 - __half2float(h1));
        lp1.x = __float2half_rn(o2 - __half2float(h2));
        lp1.y = __float2half_rn(o3 - __half2float(h3));
        ((__half2*)(outl + base))[0] = lp0;
        ((__half2*)(outl + base))[1] = lp1;
    }
}

// ---- V transpose: [tok][hk][d] fp32 -> [b][hk][d][tok] fp16 ---------------
__global__ __launch_bounds__(256)
void transp_v16(const float* __restrict__ v, __half* __restrict__ vt)
{
    __shared__ float tile[32][33];
    int t = threadIdx.x;
    int tx = t & 31, ty = t >> 5;
    int tok0 = blockIdx.x * 32, d0 = blockIdx.y * 32;
    int bh = blockIdx.z;
    int b = bh >> 3, hk = bh & 7;

    #pragma unroll
    for (int r = 0; r < 4; r++) {
        int tok = ty + r * 8;
        tile[tok][tx] = v[((size_t)(b*SS + tok0 + tok) * HK + hk) * HD + d0 + tx];
    }
    __syncthreads();
    #pragma unroll
    for (int r = 0; r < 4; r++) {
        int d = ty + r * 8;
        size_t idx = ((size_t)(b*HK + hk) * HD + d0 + d) * SS + tok0 + tx;
        vt[idx] = __float2half_rn(tile[tx][d]);
    }
}

// ---------------- mma.sync flash attention (causal, GQA rep=2) -------------
// Q split hi/lo + K single; P split hi/lo + V single. Single fp16 O out.
#define KST 136                    // K/Q smem stride (halves)
#define VSTR 72                    // V^T smem stride (halves)
#define KMAT (64 * KST * 2)        // 17408 B (64-row K tile)
#define QMAT (128 * KST * 2)       // 34816 B
#define QAREA (2 * QMAT)           // 69632 B (Q hi + Q lo, dedicated)
#define VMAT (128 * VSTR * 2)      // 18432 B
#define ASTG (KMAT + VMAT)         // 35840 B per stage
#define ATT_SMEM (QAREA + 2 * ASTG) // 141312 B

__global__ __launch_bounds__(256, 1)
void attn_mma(const __half* __restrict__ qh, const __half* __restrict__ ql,
              const __half* __restrict__ k16, const __half* __restrict__ vt16,
              __half* __restrict__ o16)
{
    extern __shared__ char smem[];
    const uint32_t sb = smem_u32(smem);
    const int t = threadIdx.x, lane = t & 31, w = t >> 5;
    const int b = blockIdx.z, h = blockIdx.y, qblk = blockIdx.x;
    const int hk = h >> 1, q0 = qblk * 128;
    const int ntiles = 2 * qblk + 2;
    const float scale = 0.08838834764831845f;

    const __half* kb_g = k16 + ((size_t)(b*SS) * HK + hk) * HD;
    const __half* vb_g = vt16 + (size_t)(b*HK + hk) * HD * SS;

    // ---- Q into dedicated area ----
    {
        const __half* qsh = qh + ((size_t)(b*SS + q0) * H + h) * HD;
        const __half* qsl = ql + ((size_t)(b*SS + q0) * H + h) * HD;
        #pragma unroll
        for (int i = 0; i < 8; i++) {
            int idx = t + i * 256;            // 0..2047
            int row = idx >> 4, c = idx & 15;
            CP_ASYNC16(sb + row * (KST*2) + c * 16, qsh + (size_t)row * (H*HD) + c * 8);
            CP_ASYNC16(sb + QMAT + row * (KST*2) + c * 16, qsl + (size_t)row * (H*HD) + c * 8);
        }
        CP_COMMIT();
    }
    // stage 0 (kt=0)
    {
        uint32_t st = sb + QAREA;
        #pragma unroll
        for (int i = 0; i < 4; i++) {
            int idx = t + i * 256;            // 0..1023
            int row = idx >> 4, c = idx & 15;
            CP_ASYNC16(st + row * (KST*2) + c * 16, kb_g + (size_t)row * (HK*HD) + c * 8);
            int vrow = idx >> 3, vc = idx & 7;
            CP_ASYNC16(st + KMAT + vrow * (VSTR*2) + vc * 16, vb_g + (size_t)vrow * SS + vc * 8);
        }
        CP_COMMIT();
    }
    CP_WAIT1();      // Q group done
    __syncthreads();

    // extract Q fragments
    uint32_t qfh[8][4], qfl[8][4];
    {
        uint32_t roff = (w * 16 + (lane & 15)) * (KST*2) + ((lane >> 4) & 1) * 16;
        #pragma unroll
        for (int ks = 0; ks < 8; ks++) {
            ldsm4(qfh[ks], sb + roff + ks * 32);
            ldsm4(qfl[ks], sb + QMAT + roff + ks * 32);
        }
    }
    // stage 1 (kt=1)
    {
        uint32_t st = sb + QAREA + ASTG;
        const __half* ksh = kb_g + (size_t)64 * (HK*HD);
        #pragma unroll
        for (int i = 0; i < 4; i++) {
            int idx = t + i * 256;
            int row = idx >> 4, c = idx & 15;
            CP_ASYNC16(st + row * (KST*2) + c * 16, ksh + (size_t)row * (HK*HD) + c * 8);
            int vrow = idx >> 3, vc = idx & 7;
            CP_ASYNC16(st + KMAT + vrow * (VSTR*2) + vc * 16, vb_g + (size_t)vrow * SS + 64 + vc * 8);
        }
        CP_COMMIT();
    }

    float oacc[16][4];
    #pragma unroll
    for (int i = 0; i < 16; i++) oacc[i][0] = oacc[i][1] = oacc[i][2] = oacc[i][3] = 0.f;
    float m0 = -1e30f, m1 = -1e30f, l0 = 0.f, l1 = 0.f;

    const int gr0 = q0 + w * 16 + (lane >> 2);
    const int gc_base = (lane & 3) * 2;

    for (int kt = 0; kt < ntiles; kt++) {
        if (kt + 1 < ntiles) { CP_WAIT1(); } else { CP_WAIT0(); }
        __syncthreads();
        uint32_t st = sb + QAREA + (kt & 1) * ASTG;

        // ---- S = Q K^T : (Qh + Ql) * K ----
        float s[8][4];
        #pragma unroll
        for (int i = 0; i < 8; i++) s[i][0] = s[i][1] = s[i][2] = s[i][3] = 0.f;

        #pragma unroll
        for (int ks = 0; ks < 8; ks++) {
            uint32_t lrow = (lane & 7) + ((lane >> 4) << 3);
            uint32_t lcol = (ks * 16 + ((lane >> 3) & 1) * 8) * 2;
            uint32_t kf[4][4];
            #pragma unroll
            for (int p = 0; p < 4; p++) {
                ldsm4(kf[p], st + (p * 16 + lrow) * (KST*2) + lcol);
                mma_f16(s[2*p],   qfh[ks], &kf[p][0]);
                mma_f16(s[2*p+1], qfh[ks], &kf[p][2]);
            }
            #pragma unroll
            for (int p = 0; p < 4; p++) {
                mma_f16(s[2*p],   qfl[ks], &kf[p][0]);
                mma_f16(s[2*p+1], qfl[ks], &kf[p][2]);
            }
        }

        // ---- softmax (fp32, warp-local rows) ----
        const int kc0 = kt * 64;
        bool fullok = (kc0 + 63 <= q0 + w * 16);
        #pragma unroll
        for (int nt = 0; nt < 8; nt++) {
            if (fullok) {
                s[nt][0] *= scale; s[nt][1] *= scale; s[nt][2] *= scale; s[nt][3] *= scale;
            } else {
                int gc = kc0 + nt * 8 + gc_base;
                s[nt][0] = (gc     <= gr0    ) ? s[nt][0] * scale : -1e30f;
                s[nt][1] = (gc + 1 <= gr0    ) ? s[nt][1] * scale : -1e30f;
                s[nt][2] = (gc     <= gr0 + 8) ? s[nt][2] * scale : -1e30f;
                s[nt][3] = (gc + 1 <= gr0 + 8) ? s[nt][3] * scale : -1e30f;
            }
        }
        float mx0 = -1e30f, mx1 = -1e30f;
        #pragma unroll
        for (int nt = 0; nt < 8; nt++) {
            mx0 = fmaxf(mx0, fmaxf(s[nt][0], s[nt][1]));
            mx1 = fmaxf(mx1, fmaxf(s[nt][2], s[nt][3]));
        }
        #pragma unroll
        for (int o = 1; o <= 2; o <<= 1) {
            mx0 = fmaxf(mx0, __shfl_xor_sync(0xffffffffu, mx0, o));
            mx1 = fmaxf(mx1, __shfl_xor_sync(0xffffffffu, mx1, o));
        }
        float mn0 = fmaxf(m0, mx0), mn1 = fmaxf(m1, mx1);
        float cr0 = __expf(m0 - mn0), cr1 = __expf(m1 - mn1);
        m0 = mn0; m1 = mn1;
        #pragma unroll
        for (int nt = 0; nt < 16; nt++) {
            oacc[nt][0] *= cr0; oacc[nt][1] *= cr0;
            oacc[nt][2] *= cr1; oacc[nt][3] *= cr1;
        }

        uint32_t pfh[4][4], pfl[4][4];
        float sum0 = 0.f, sum1 = 0.f;
        #pragma unroll
        for (int nt = 0; nt < 8; nt++) {
            float p0 = __expf(s[nt][0] - mn0);
            float p1 = __expf(s[nt][1] - mn0);
            float p2 = __expf(s[nt][2] - mn1);
            float p3 = __expf(s[nt][3] - mn1);
            sum0 += p0 + p1; sum1 += p2 + p3;
            __half b0 = __float2half_rn(p0), b1 = __float2half_rn(p1);
            __half b2 = __float2half_rn(p2), b3 = __float2half_rn(p3);
            int j = nt >> 1, hi2 = (nt & 1) * 2;
            __half2 ph0, ph1;
            ph0.x = b0; ph0.y = b1; ph1.x = b2; ph1.y = b3;
            pfh[j][hi2]     = *(uint32_t*)&ph0;
            pfh[j][hi2 + 1] = *(uint32_t*)&ph1;
            pfl[j][hi2]     = pack_hf2(p0 - __half2float(b0), p1 - __half2float(b1));
            pfl[j][hi2 + 1] = pack_hf2(p2 - __half2float(b2), p3 - __half2float(b3));
        }
        #pragma unroll
        for (int o = 1; o <= 2; o <<= 1) {
            sum0 += __shfl_xor_sync(0xffffffffu, sum0, o);
            sum1 += __shfl_xor_sync(0xffffffffu, sum1, o);
        }
        l0 = l0 * cr0 + sum0;
        l1 = l1 * cr1 + sum1;

        // ---- O += (Ph + Pl) V ; V^T tile [128 d][64 keys] ----
        uint32_t vst = st + KMAT;
        #pragma unroll
        for (int ks = 0; ks < 4; ks++) {
            uint32_t lrow = (lane & 7) + ((lane >> 4) << 3);
            uint32_t lcol = (ks * 16 + ((lane >> 3) & 1) * 8) * 2;
            #pragma unroll
            for (int p = 0; p < 8; p++) {
                uint32_t vb[4];
                ldsm4(vb, vst + (p * 16 + lrow) * (VSTR*2) + lcol);
                mma_f16(oacc[2*p],   pfh[ks], &vb[0]);
                mma_f16(oacc[2*p+1], pfh[ks], &vb[2]);
                mma_f16(oacc[2*p],   pfl[ks], &vb[0]);
                mma_f16(oacc[2*p+1], pfl[ks], &vb[2]);
            }
        }

        __syncthreads();
        // prefetch kt+2
        if (kt + 2 < ntiles) {
            uint32_t st2 = sb + QAREA + (kt & 1) * ASTG;
            int kc = (kt + 2) * 64;
            const __half* ksh = kb_g + (size_t)kc * (HK*HD);
            #pragma unroll
            for (int i = 0; i < 4; i++) {
                int idx = t + i * 256;
                int row = idx >> 4, c = idx & 15;
                CP_ASYNC16(st2 + row * (KST*2) + c * 16, ksh + (size_t)row * (HK*HD) + c * 8);
                int vrow = idx >> 3, vc = idx & 7;
                CP_ASYNC16(st2 + KMAT + vrow * (VSTR*2) + vc * 16, vb_g + (size_t)vrow * SS + kc + vc * 8);
            }
        }
        CP_COMMIT();
    }

    // ---- epilogue: normalize, write single fp16 O ----
    float inv0 = 1.f / l0, inv1 = 1.f / l1;
    size_t obase = ((size_t)(b*SS + q0 + w*16 + (lane >> 2)) * H + h) * HD;
    #pragma unroll
    for (int nt = 0; nt < 16; nt++) {
        int d = nt * 8 + gc_base;
        *(uint32_t*)(o16 + obase + d) =
            pack_hf2(oacc[nt][0] * inv0, oacc[nt][1] * inv0);
        *(uint32_t*)(o16 + obase + (size_t)8 * H * HD + d) =
            pack_hf2(oacc[nt][2] * inv1, oacc[nt][3] * inv1);
    }
}

// ---------------- launch ----------------------------------------------------
extern "C" void kernel_launch(void* const* d_in, const int* in_sizes, int n_in,
                              void* d_out, int out_size)
{
    (void)in_sizes; (void)n_in; (void)out_size;
    const float* x  = (const float*)d_in[0];
    const float* wq = (const float*)d_in[1];
    const float* wk = (const float*)d_in[2];
    const float* wv = (const float*)d_in[3];
    const float* wo = (const float*)d_in[4];
    const float* qw = (const float*)d_in[5];
    const float* kw = (const float*)d_in[6];
    float* out = (float*)d_out;

    float *q, *k, *v;
    cudaGetSymbolAddress((void**)&q, g_q);
    cudaGetSymbolAddress((void**)&k, g_k);
    cudaGetSymbolAddress((void**)&v, g_v);

    __half *x16, *wq16, *wk16, *wv16, *wo16, *o16, *qah, *qal, *k16, *vt16;
    cudaGetSymbolAddress((void**)&x16,  g_x16);
    cudaGetSymbolAddress((void**)&wq16, g_wq16); cudaGetSymbolAddress((void**)&wk16, g_wk16);
    cudaGetSymbolAddress((void**)&wv16, g_wv16); cudaGetSymbolAddress((void**)&wo16, g_wo16);
    cudaGetSymbolAddress((void**)&o16,  g_o16);
    cudaGetSymbolAddress((void**)&qah,  g_qah);  cudaGetSymbolAddress((void**)&qal,  g_qal);
    cudaGetSymbolAddress((void**)&k16,  g_k16);  cudaGetSymbolAddress((void**)&vt16, g_vt16);

    cudaFuncSetAttribute(gemm_f16, cudaFuncAttributeMaxDynamicSharedMemorySize, GEMM_SMEM);
    cudaFuncSetAttribute(attn_mma, cudaFuncAttributeMaxDynamicSharedMemorySize, ATT_SMEM);

    // operand conversion (all single fp16)
    conv_fp16<<<(MTOT*DD/4 + 255)/256, 256>>>(x, x16, MTOT*DD/4);
    conv_fp16<<<(H*HD*DD/4 + 255)/256, 256>>>(wq, wq16, H*HD*DD/4);
    conv_fp16<<<(HK*HD*DD/4 + 255)/256, 256>>>(wk, wk16, HK*HD*DD/4);
    conv_fp16<<<(HK*HD*DD/4 + 255)/256, 256>>>(wv, wv16, HK*HD*DD/4);
    conv_fp16<<<(DD*H*HD/4 + 255)/256, 256>>>(wo, wo16, DD*H*HD/4);

    rope_table<<<SS, 64>>>();

    // QKV projections (single-pass fp16)
    gemm_f16<<<dim3((H*HD)/128,  MTOT/128), 256, GEMM_SMEM>>>(x16, wq16, q, H*HD,  DD);
    gemm_f16<<<dim3((HK*HD)/128, MTOT/128), 256, GEMM_SMEM>>>(x16, wk16, k, HK*HD, DD);
    gemm_f16<<<dim3((HK*HD)/128, MTOT/128), 256, GEMM_SMEM>>>(x16, wv16, v, HK*HD, DD);

    // RMSNorm + RoPE: Q -> hi/lo (error hedge), K -> single
    norm_rope_f16<<<(MTOT*H )/8, 256>>>(q, qah, qal, qw, H);
    norm_rope_f16<<<(MTOT*HK)/8, 256>>>(k, k16, nullptr, kw, HK);
    transp_v16<<<dim3(SS/32, HD/32, BB*HK), 256>>>(v, vt16);

    // causal attention on tensor cores (Q and P kept 2-pass)
    attn_mma<<<dim3(SS/128, H, BB), 256, ATT_SMEM>>>(qah, qal, k16, vt16, o16);

    // output projection (single-pass fp16)
    gemm_f16<<<dim3(DD/128, MTOT/128), 256, GEMM_SMEM>>>(o16, wo16, out, DD, H*HD);
}

// round 10
// speedup vs baseline: 5.6101x; 1.1439x over previous
#include <cuda_runtime.h>
#include <cuda_fp16.h>
#include <math.h>
#include <stdint.h>

#define BB 2
#define SS 2048
#define DD 2048
#define H 16
#define HK 8
#define HD 128
#define MTOT (BB*SS)   // 4096

// ---------------- scratch (allocation-free: device globals) ----------------
__device__ float g_q[(size_t)MTOT * H * HD];
__device__ float g_k[(size_t)MTOT * HK * HD];
__device__ float g_v[(size_t)MTOT * HK * HD];
__device__ float g_cos[SS * 64];
__device__ float g_sin[SS * 64];

__device__ __align__(16) __half g_x16[(size_t)MTOT * DD];
__device__ __align__(16) __half g_wq16[(size_t)(H*HD) * DD];
__device__ __align__(16) __half g_wk16[(size_t)(HK*HD) * DD];
__device__ __align__(16) __half g_wv16[(size_t)(HK*HD) * DD];
__device__ __align__(16) __half g_wo16[(size_t)DD * (H*HD)];
__device__ __align__(16) __half g_o16[(size_t)MTOT * (H*HD)];
__device__ __align__(16) __half g_q16[(size_t)MTOT * H * HD];
__device__ __align__(16) __half g_k16[(size_t)MTOT * HK * HD];
__device__ __align__(16) __half g_vt16[(size_t)MTOT * HK * HD];  // [b][hk][d][tok]

// ---------------- asm helpers ----------------------------------------------
__device__ __forceinline__ uint32_t smem_u32(const void* p) {
    uint32_t a;
    asm("{ .reg .u64 t; cvta.to.shared.u64 t, %1; cvt.u32.u64 %0, t; }" : "=r"(a) : "l"(p));
    return a;
}

#define CP_ASYNC16(dst, src) \
    asm volatile("cp.async.cg.shared.global [%0], [%1], 16;" :: "r"(dst), "l"(src))
#define CP_COMMIT() asm volatile("cp.async.commit_group;" ::: "memory")
#define CP_WAIT2()  asm volatile("cp.async.wait_group 2;" ::: "memory")
#define CP_WAIT1()  asm volatile("cp.async.wait_group 1;" ::: "memory")
#define CP_WAIT0()  asm volatile("cp.async.wait_group 0;" ::: "memory")

__device__ __forceinline__ void ldsm4(uint32_t* r, uint32_t a) {
    asm volatile("ldmatrix.sync.aligned.m8n8.x4.shared.b16 {%0,%1,%2,%3}, [%4];"
        : "=r"(r[0]), "=r"(r[1]), "=r"(r[2]), "=r"(r[3]) : "r"(a));
}
__device__ __forceinline__ void ldsm2(uint32_t* r, uint32_t a) {
    asm volatile("ldmatrix.sync.aligned.m8n8.x2.shared.b16 {%0,%1}, [%2];"
        : "=r"(r[0]), "=r"(r[1]) : "r"(a));
}
__device__ __forceinline__ void mma_f16(float* c, const uint32_t* a, const uint32_t* b) {
    asm volatile("mma.sync.aligned.m16n8k16.row.col.f32.f16.f16.f32 "
        "{%0,%1,%2,%3}, {%4,%5,%6,%7}, {%8,%9}, {%0,%1,%2,%3};"
        : "+f"(c[0]), "+f"(c[1]), "+f"(c[2]), "+f"(c[3])
        : "r"(a[0]), "r"(a[1]), "r"(a[2]), "r"(a[3]), "r"(b[0]), "r"(b[1]));
}

__device__ __forceinline__ uint32_t pack_hf2(float a, float b) {
    __half2 t;
    t.x = __float2half_rn(a);
    t.y = __float2half_rn(b);
    return *(uint32_t*)&t;
}

// --------- single-pass fp16 GEMM via mma.sync: C = A * B^T -----------------
// A (M,K) fp16, W (N,K) fp16, C (M,N) fp32. CTA 128x128, BK=32, 256 thr.
// 4-stage cp.async pipeline, smem stride 40 halves (conflict-free ldmatrix).
#define SST 40
#define MATB (128 * SST * 2)      // 10240 B per matrix
#define STG1 (2 * MATB)           // 20480 B per stage (A, B)
#define GEMM_SMEM (4 * STG1)      // 81920 B  -> 2 CTAs/SM

__device__ __forceinline__ void gemm_load_stage(
    uint32_t sbase, int slot,
    const __half* __restrict__ A, const __half* __restrict__ B,
    int m0, int n0, int K, int k0, int t)
{
    uint32_t st = sbase + slot * STG1;
    const __half* gp[2] = { A + (size_t)m0 * K + k0, B + (size_t)n0 * K + k0 };
    #pragma unroll
    for (int mat = 0; mat < 2; mat++) {
        #pragma unroll
        for (int h = 0; h < 2; h++) {
            int c = t + h * 256;          // 0..511
            int row = c >> 2, col16 = c & 3;
            uint32_t dst = st + mat * MATB + row * (SST*2) + col16 * 16;
            const __half* src = gp[mat] + (size_t)row * K + col16 * 8;
            CP_ASYNC16(dst, src);
        }
    }
}

__global__ __launch_bounds__(256, 2)
void gemm_f16(const __half* __restrict__ A, const __half* __restrict__ B,
              float* __restrict__ C, int N, int K)
{
    extern __shared__ char smem[];
    const uint32_t sb = smem_u32(smem);
    const int t = threadIdx.x;
    const int lane = t & 31, wid = t >> 5;
    const int warp_m = wid >> 2;
    const int warp_n = wid & 3;
    const int m0 = blockIdx.y * 128, n0 = blockIdx.x * 128;
    const int niter = K >> 5;

    float acc[4][4][4];
    #pragma unroll
    for (int i = 0; i < 4; i++)
        #pragma unroll
        for (int j = 0; j < 4; j++)
            acc[i][j][0] = acc[i][j][1] = acc[i][j][2] = acc[i][j][3] = 0.f;

    #pragma unroll
    for (int s = 0; s < 3; s++) {
        if (s < niter) gemm_load_stage(sb, s, A, B, m0, n0, K, s * 32, t);
        CP_COMMIT();
    }

    const int arow = warp_m * 64 + (lane & 15);
    const int acolh = (lane >> 4) * 8;
    const int l2 = lane & 15;
    const int brow = warp_n * 32 + (l2 & 7);
    const int bcolh = (l2 >> 3) * 8;

    for (int it = 0; it < niter; it++) {
        int ps = it + 3;
        if (ps < niter)
            gemm_load_stage(sb, ps & 3, A, B, m0, n0, K, ps * 32, t);
        CP_COMMIT();
        CP_WAIT2();
        __syncthreads();

        uint32_t st = sb + (it & 3) * STG1;
        #pragma unroll
        for (int ks = 0; ks < 2; ks++) {
            uint32_t af[4][4], bf[4][2];
            #pragma unroll
            for (int mt = 0; mt < 4; mt++) {
                uint32_t off = ((arow + mt * 16) * SST + ks * 16 + acolh) * 2;
                ldsm4(af[mt], st + off);
            }
            #pragma unroll
            for (int nt = 0; nt < 4; nt++) {
                uint32_t off = ((brow + nt * 8) * SST + ks * 16 + bcolh) * 2;
                ldsm2(bf[nt], st + MATB + off);
            }
            #pragma unroll
            for (int mt = 0; mt < 4; mt++)
                #pragma unroll
                for (int nt = 0; nt < 4; nt++)
                    mma_f16(acc[mt][nt], af[mt], bf[nt]);
        }
        __syncthreads();
    }

    const int r0 = lane >> 2, c0 = (lane & 3) * 2;
    #pragma unroll
    for (int mt = 0; mt < 4; mt++) {
        #pragma unroll
        for (int nt = 0; nt < 4; nt++) {
            int row = m0 + warp_m * 64 + mt * 16 + r0;
            int col = n0 + warp_n * 32 + nt * 8 + c0;
            *(float2*)(C + (size_t)row * N + col) =
                make_float2(acc[mt][nt][0], acc[mt][nt][1]);
            *(float2*)(C + (size_t)(row + 8) * N + col) =
                make_float2(acc[mt][nt][2], acc[mt][nt][3]);
        }
    }
}

// ---------------- fp32 -> fp16 convert -------------------------------------
__global__ __launch_bounds__(256)
void conv_fp16(const float* __restrict__ in, __half* __restrict__ out, int n4)
{
    int i = blockIdx.x * blockDim.x + threadIdx.x;
    if (i >= n4) return;
    float4 v = ((const float4*)in)[i];
    __half2 p0, p1;
    p0.x = __float2half_rn(v.x); p0.y = __float2half_rn(v.y);
    p1.x = __float2half_rn(v.z); p1.y = __float2half_rn(v.w);
    ((__half2*)(out + i * 4))[0] = p0;
    ((__half2*)(out + i * 4))[1] = p1;
}

// ---------------- RoPE table ------------------------------------------------
__global__ void rope_table()
{
    int s = blockIdx.x;
    int j = threadIdx.x;
    double invd = pow(1.0e6, -(double)j / 64.0);
    float  ang  = (float)s * (float)invd;
    float  c, sn;
    sincosf(ang, &sn, &c);
    g_cos[s*64 + j] = c;
    g_sin[s*64 + j] = sn;
}

// -------- fused RMSNorm + RoPE -> single fp16 ------------------------------
__global__ __launch_bounds__(256)
void norm_rope_f16(const float* __restrict__ buf, __half* __restrict__ outh,
                   const float* __restrict__ w, int nheads)
{
    int gw   = (blockIdx.x * blockDim.x + threadIdx.x) >> 5;
    int lane = threadIdx.x & 31;
    int m = gw / nheads;
    int h = gw - m * nheads;
    int s = m & (SS - 1);

    size_t base = ((size_t)m * nheads + h) * HD + lane * 4;
    float4 v = *(const float4*)(buf + base);
    float ss = v.x*v.x + v.y*v.y + v.z*v.z + v.w*v.w;
    #pragma unroll
    for (int o = 16; o; o >>= 1) ss += __shfl_xor_sync(0xffffffffu, ss, o);
    float r = rsqrtf(ss * (1.f/128.f) + 1e-6f);

    const float4 wv = *(const float4*)(w + lane*4);
    v.x *= r * wv.x; v.y *= r * wv.y; v.z *= r * wv.z; v.w *= r * wv.w;

    float4 pr;
    pr.x = __shfl_xor_sync(0xffffffffu, v.x, 16);
    pr.y = __shfl_xor_sync(0xffffffffu, v.y, 16);
    pr.z = __shfl_xor_sync(0xffffffffu, v.z, 16);
    pr.w = __shfl_xor_sync(0xffffffffu, v.w, 16);

    int jbase = (lane & 15) * 4;
    const float* cb = g_cos + s*64 + jbase;
    const float* sb = g_sin + s*64 + jbase;
    float sgn = (lane < 16) ? -1.f : 1.f;

    float o0 = v.x * cb[0] + sgn * pr.x * sb[0];
    float o1 = v.y * cb[1] + sgn * pr.y * sb[1];
    float o2 = v.z * cb[2] + sgn * pr.z * sb[2];
    float o3 = v.w * cb[3] + sgn * pr.w * sb[3];

    __half2 hp0, hp1;
    hp0.x = __float2half_rn(o0); hp0.y = __float2half_rn(o1);
    hp1.x = __float2half_rn(o2); hp1.y = __float2half_rn(o3);
    ((__half2*)(outh + base))[0] = hp0;
    ((__half2*)(outh + base))[1] = hp1;
}

// ---- V transpose: [tok][hk][d] fp32 -> [b][hk][d][tok] fp16 ---------------
__global__ __launch_bounds__(256)
void transp_v16(const float* __restrict__ v, __half* __restrict__ vt)
{
    __shared__ float tile[32][33];
    int t = threadIdx.x;
    int tx = t & 31, ty = t >> 5;
    int tok0 = blockIdx.x * 32, d0 = blockIdx.y * 32;
    int bh = blockIdx.z;
    int b = bh >> 3, hk = bh & 7;

    #pragma unroll
    for (int r = 0; r < 4; r++) {
        int tok = ty + r * 8;
        tile[tok][tx] = v[((size_t)(b*SS + tok0 + tok) * HK + hk) * HD + d0 + tx];
    }
    __syncthreads();
    #pragma unroll
    for (int r = 0; r < 4; r++) {
        int d = ty + r * 8;
        size_t idx = ((size_t)(b*HK + hk) * HD + d0 + d) * SS + tok0 + tx;
        vt[idx] = __float2half_rn(tile[tx][d]);
    }
}

// ---------------- mma.sync flash attention (causal, GQA rep=2) -------------
// All operands single fp16. 128 q rows/CTA, 8 warps x 16 rows, 64-key tiles.
#define KST 136                    // K/Q smem stride (halves)
#define VSTR 72                    // V^T smem stride (halves)
#define KMAT (64 * KST * 2)        // 17408 B (64-row K tile)
#define QMAT (128 * KST * 2)       // 34816 B (Q area)
#define VMAT (128 * VSTR * 2)      // 18432 B
#define ASTG (KMAT + VMAT)         // 35840 B per stage
#define ATT_SMEM (QMAT + 2 * ASTG) // 106496 B

__global__ __launch_bounds__(256, 1)
void attn_mma(const __half* __restrict__ q16, const __half* __restrict__ k16,
              const __half* __restrict__ vt16, __half* __restrict__ o16)
{
    extern __shared__ char smem[];
    const uint32_t sb = smem_u32(smem);
    const int t = threadIdx.x, lane = t & 31, w = t >> 5;
    const int b = blockIdx.z, h = blockIdx.y;
    const int qblk = (int)gridDim.x - 1 - (int)blockIdx.x;   // heavy tiles first
    const int hk = h >> 1, q0 = qblk * 128;
    const int ntiles = 2 * qblk + 2;
    const float scale = 0.08838834764831845f;

    const __half* kb_g = k16 + ((size_t)(b*SS) * HK + hk) * HD;
    const __half* vb_g = vt16 + (size_t)(b*HK + hk) * HD * SS;

    // ---- Q into dedicated area ----
    {
        const __half* qs = q16 + ((size_t)(b*SS + q0) * H + h) * HD;
        #pragma unroll
        for (int i = 0; i < 8; i++) {
            int idx = t + i * 256;            // 0..2047
            int row = idx >> 4, c = idx & 15;
            CP_ASYNC16(sb + row * (KST*2) + c * 16, qs + (size_t)row * (H*HD) + c * 8);
        }
        CP_COMMIT();
    }
    // stage 0 (kt=0)
    {
        uint32_t st = sb + QMAT;
        #pragma unroll
        for (int i = 0; i < 4; i++) {
            int idx = t + i * 256;            // 0..1023
            int row = idx >> 4, c = idx & 15;
            CP_ASYNC16(st + row * (KST*2) + c * 16, kb_g + (size_t)row * (HK*HD) + c * 8);
            int vrow = idx >> 3, vc = idx & 7;
            CP_ASYNC16(st + KMAT + vrow * (VSTR*2) + vc * 16, vb_g + (size_t)vrow * SS + vc * 8);
        }
        CP_COMMIT();
    }
    CP_WAIT1();      // Q group done
    __syncthreads();

    // extract Q fragments
    uint32_t qf[8][4];
    {
        uint32_t roff = (w * 16 + (lane & 15)) * (KST*2) + ((lane >> 4) & 1) * 16;
        #pragma unroll
        for (int ks = 0; ks < 8; ks++)
            ldsm4(qf[ks], sb + roff + ks * 32);
    }
    // stage 1 (kt=1)
    {
        uint32_t st = sb + QMAT + ASTG;
        const __half* ksh = kb_g + (size_t)64 * (HK*HD);
        #pragma unroll
        for (int i = 0; i < 4; i++) {
            int idx = t + i * 256;
            int row = idx >> 4, c = idx & 15;
            CP_ASYNC16(st + row * (KST*2) + c * 16, ksh + (size_t)row * (HK*HD) + c * 8);
            int vrow = idx >> 3, vc = idx & 7;
            CP_ASYNC16(st + KMAT + vrow * (VSTR*2) + vc * 16, vb_g + (size_t)vrow * SS + 64 + vc * 8);
        }
        CP_COMMIT();
    }

    float oacc[16][4];
    #pragma unroll
    for (int i = 0; i < 16; i++) oacc[i][0] = oacc[i][1] = oacc[i][2] = oacc[i][3] = 0.f;
    float m0 = -1e30f, m1 = -1e30f, l0 = 0.f, l1 = 0.f;

    const int gr0 = q0 + w * 16 + (lane >> 2);
    const int gc_base = (lane & 3) * 2;

    for (int kt = 0; kt < ntiles; kt++) {
        if (kt + 1 < ntiles) { CP_WAIT1(); } else { CP_WAIT0(); }
        __syncthreads();
        uint32_t st = sb + QMAT + (kt & 1) * ASTG;

        // ---- S = Q K^T ----
        float s[8][4];
        #pragma unroll
        for (int i = 0; i < 8; i++) s[i][0] = s[i][1] = s[i][2] = s[i][3] = 0.f;

        #pragma unroll
        for (int ks = 0; ks < 8; ks++) {
            uint32_t lrow = (lane & 7) + ((lane >> 4) << 3);
            uint32_t lcol = (ks * 16 + ((lane >> 3) & 1) * 8) * 2;
            #pragma unroll
            for (int p = 0; p < 4; p++) {
                uint32_t kf[4];
                ldsm4(kf, st + (p * 16 + lrow) * (KST*2) + lcol);
                mma_f16(s[2*p],   qf[ks], &kf[0]);
                mma_f16(s[2*p+1], qf[ks], &kf[2]);
            }
        }

        // ---- softmax (fp32, warp-local rows) ----
        const int kc0 = kt * 64;
        bool fullok = (kc0 + 63 <= q0 + w * 16);
        #pragma unroll
        for (int nt = 0; nt < 8; nt++) {
            if (fullok) {
                s[nt][0] *= scale; s[nt][1] *= scale; s[nt][2] *= scale; s[nt][3] *= scale;
            } else {
                int gc = kc0 + nt * 8 + gc_base;
                s[nt][0] = (gc     <= gr0    ) ? s[nt][0] * scale : -1e30f;
                s[nt][1] = (gc + 1 <= gr0    ) ? s[nt][1] * scale : -1e30f;
                s[nt][2] = (gc     <= gr0 + 8) ? s[nt][2] * scale : -1e30f;
                s[nt][3] = (gc + 1 <= gr0 + 8) ? s[nt][3] * scale : -1e30f;
            }
        }
        float mx0 = -1e30f, mx1 = -1e30f;
        #pragma unroll
        for (int nt = 0; nt < 8; nt++) {
            mx0 = fmaxf(mx0, fmaxf(s[nt][0], s[nt][1]));
            mx1 = fmaxf(mx1, fmaxf(s[nt][2], s[nt][3]));
        }
        #pragma unroll
        for (int o = 1; o <= 2; o <<= 1) {
            mx0 = fmaxf(mx0, __shfl_xor_sync(0xffffffffu, mx0, o));
            mx1 = fmaxf(mx1, __shfl_xor_sync(0xffffffffu, mx1, o));
        }
        float mn0 = fmaxf(m0, mx0), mn1 = fmaxf(m1, mx1);
        float cr0 = __expf(m0 - mn0), cr1 = __expf(m1 - mn1);
        m0 = mn0; m1 = mn1;
        #pragma unroll
        for (int nt = 0; nt < 16; nt++) {
            oacc[nt][0] *= cr0; oacc[nt][1] *= cr0;
            oacc[nt][2] *= cr1; oacc[nt][3] *= cr1;
        }

        uint32_t pf[4][4];
        float sum0 = 0.f, sum1 = 0.f;
        #pragma unroll
        for (int nt = 0; nt < 8; nt++) {
            float p0 = __expf(s[nt][0] - mn0);
            float p1 = __expf(s[nt][1] - mn0);
            float p2 = __expf(s[nt][2] - mn1);
            float p3 = __expf(s[nt][3] - mn1);
            sum0 += p0 + p1; sum1 += p2 + p3;
            int j = nt >> 1, hi2 = (nt & 1) * 2;
            pf[j][hi2]     = pack_hf2(p0, p1);
            pf[j][hi2 + 1] = pack_hf2(p2, p3);
        }
        #pragma unroll
        for (int o = 1; o <= 2; o <<= 1) {
            sum0 += __shfl_xor_sync(0xffffffffu, sum0, o);
            sum1 += __shfl_xor_sync(0xffffffffu, sum1, o);
        }
        l0 = l0 * cr0 + sum0;
        l1 = l1 * cr1 + sum1;

        // ---- O += P V ; V^T tile [128 d][64 keys] ----
        uint32_t vst = st + KMAT;
        #pragma unroll
        for (int ks = 0; ks < 4; ks++) {
            uint32_t lrow = (lane & 7) + ((lane >> 4) << 3);
            uint32_t lcol = (ks * 16 + ((lane >> 3) & 1) * 8) * 2;
            #pragma unroll
            for (int p = 0; p < 8; p++) {
                uint32_t vb[4];
                ldsm4(vb, vst + (p * 16 + lrow) * (VSTR*2) + lcol);
                mma_f16(oacc[2*p],   pf[ks], &vb[0]);
                mma_f16(oacc[2*p+1], pf[ks], &vb[2]);
            }
        }

        __syncthreads();
        // prefetch kt+2
        if (kt + 2 < ntiles) {
            uint32_t st2 = sb + QMAT + (kt & 1) * ASTG;
            int kc = (kt + 2) * 64;
            const __half* ksh = kb_g + (size_t)kc * (HK*HD);
            #pragma unroll
            for (int i = 0; i < 4; i++) {
                int idx = t + i * 256;
                int row = idx >> 4, c = idx & 15;
                CP_ASYNC16(st2 + row * (KST*2) + c * 16, ksh + (size_t)row * (HK*HD) + c * 8);
                int vrow = idx >> 3, vc = idx & 7;
                CP_ASYNC16(st2 + KMAT + vrow * (VSTR*2) + vc * 16, vb_g + (size_t)vrow * SS + kc + vc * 8);
            }
        }
        CP_COMMIT();
    }

    // ---- epilogue: normalize, write single fp16 O ----
    float inv0 = 1.f / l0, inv1 = 1.f / l1;
    size_t obase = ((size_t)(b*SS + q0 + w*16 + (lane >> 2)) * H + h) * HD;
    #pragma unroll
    for (int nt = 0; nt < 16; nt++) {
        int d = nt * 8 + gc_base;
        *(uint32_t*)(o16 + obase + d) =
            pack_hf2(oacc[nt][0] * inv0, oacc[nt][1] * inv0);
        *(uint32_t*)(o16 + obase + (size_t)8 * H * HD + d) =
            pack_hf2(oacc[nt][2] * inv1, oacc[nt][3] * inv1);
    }
}

// ---------------- launch ----------------------------------------------------
extern "C" void kernel_launch(void* const* d_in, const int* in_sizes, int n_in,
                              void* d_out, int out_size)
{
    (void)in_sizes; (void)n_in; (void)out_size;
    const float* x  = (const float*)d_in[0];
    const float* wq = (const float*)d_in[1];
    const float* wk = (const float*)d_in[2];
    const float* wv = (const float*)d_in[3];
    const float* wo = (const float*)d_in[4];
    const float* qw = (const float*)d_in[5];
    const float* kw = (const float*)d_in[6];
    float* out = (float*)d_out;

    float *q, *k, *v;
    cudaGetSymbolAddress((void**)&q, g_q);
    cudaGetSymbolAddress((void**)&k, g_k);
    cudaGetSymbolAddress((void**)&v, g_v);

    __half *x16, *wq16, *wk16, *wv16, *wo16, *o16, *q16, *k16, *vt16;
    cudaGetSymbolAddress((void**)&x16,  g_x16);
    cudaGetSymbolAddress((void**)&wq16, g_wq16); cudaGetSymbolAddress((void**)&wk16, g_wk16);
    cudaGetSymbolAddress((void**)&wv16, g_wv16); cudaGetSymbolAddress((void**)&wo16, g_wo16);
    cudaGetSymbolAddress((void**)&o16,  g_o16);  cudaGetSymbolAddress((void**)&q16,  g_q16);
    cudaGetSymbolAddress((void**)&k16,  g_k16);  cudaGetSymbolAddress((void**)&vt16, g_vt16);

    cudaFuncSetAttribute(gemm_f16, cudaFuncAttributeMaxDynamicSharedMemorySize, GEMM_SMEM);
    cudaFuncSetAttribute(attn_mma, cudaFuncAttributeMaxDynamicSharedMemorySize, ATT_SMEM);

    // operand conversion (all single fp16)
    conv_fp16<<<(MTOT*DD/4 + 255)/256, 256>>>(x, x16, MTOT*DD/4);
    conv_fp16<<<(H*HD*DD/4 + 255)/256, 256>>>(wq, wq16, H*HD*DD/4);
    conv_fp16<<<(HK*HD*DD/4 + 255)/256, 256>>>(wk, wk16, HK*HD*DD/4);
    conv_fp16<<<(HK*HD*DD/4 + 255)/256, 256>>>(wv, wv16, HK*HD*DD/4);
    conv_fp16<<<(DD*H*HD/4 + 255)/256, 256>>>(wo, wo16, DD*H*HD/4);

    rope_table<<<SS, 64>>>();

    // QKV projections (single-pass fp16)
    gemm_f16<<<dim3((H*HD)/128,  MTOT/128), 256, GEMM_SMEM>>>(x16, wq16, q, H*HD,  DD);
    gemm_f16<<<dim3((HK*HD)/128, MTOT/128), 256, GEMM_SMEM>>>(x16, wk16, k, HK*HD, DD);
    gemm_f16<<<dim3((HK*HD)/128, MTOT/128), 256, GEMM_SMEM>>>(x16, wv16, v, HK*HD, DD);

    // RMSNorm + RoPE -> single fp16
    norm_rope_f16<<<(MTOT*H )/8, 256>>>(q, q16, qw, H);
    norm_rope_f16<<<(MTOT*HK)/8, 256>>>(k, k16, kw, HK);
    transp_v16<<<dim3(SS/32, HD/32, BB*HK), 256>>>(v, vt16);

    // causal attention on tensor cores (single-pass fp16)
    attn_mma<<<dim3(SS/128, H, BB), 256, ATT_SMEM>>>(q16, k16, vt16, o16);

    // output projection (single-pass fp16)
    gemm_f16<<<dim3(DD/128, MTOT/128), 256, GEMM_SMEM>>>(o16, wo16, out, DD, H*HD);
}

// round 11
// speedup vs baseline: 6.0215x; 1.0733x over previous
#include <cuda_runtime.h>
#include <cuda_fp16.h>
#include <math.h>
#include <stdint.h>

#define BB 2
#define SS 2048
#define DD 2048
#define H 16
#define HK 8
#define HD 128
#define MTOT (BB*SS)   // 4096

// ---------------- scratch (allocation-free: device globals) ----------------
__device__ float g_q[(size_t)MTOT * H * HD];
__device__ float g_k[(size_t)MTOT * HK * HD];
__device__ float g_v[(size_t)MTOT * HK * HD];
__device__ float g_cos[SS * 64];
__device__ float g_sin[SS * 64];

__device__ __align__(16) __half g_x16[(size_t)MTOT * DD];
__device__ __align__(16) __half g_wq16[(size_t)(H*HD) * DD];
__device__ __align__(16) __half g_wk16[(size_t)(HK*HD) * DD];
__device__ __align__(16) __half g_wv16[(size_t)(HK*HD) * DD];
__device__ __align__(16) __half g_wo16[(size_t)DD * (H*HD)];
__device__ __align__(16) __half g_o16[(size_t)MTOT * (H*HD)];
__device__ __align__(16) __half g_q16[(size_t)MTOT * H * HD];
__device__ __align__(16) __half g_k16[(size_t)MTOT * HK * HD];
__device__ __align__(16) __half g_vt16[(size_t)MTOT * HK * HD];  // [b][hk][d][tok]

// ---------------- asm helpers ----------------------------------------------
__device__ __forceinline__ uint32_t smem_u32(const void* p) {
    uint32_t a;
    asm("{ .reg .u64 t; cvta.to.shared.u64 t, %1; cvt.u32.u64 %0, t; }" : "=r"(a) : "l"(p));
    return a;
}

#define CP_ASYNC16(dst, src) \
    asm volatile("cp.async.cg.shared.global [%0], [%1], 16;" :: "r"(dst), "l"(src))
#define CP_COMMIT() asm volatile("cp.async.commit_group;" ::: "memory")
#define CP_WAIT2()  asm volatile("cp.async.wait_group 2;" ::: "memory")
#define CP_WAIT1()  asm volatile("cp.async.wait_group 1;" ::: "memory")
#define CP_WAIT0()  asm volatile("cp.async.wait_group 0;" ::: "memory")

__device__ __forceinline__ void ldsm4(uint32_t* r, uint32_t a) {
    asm volatile("ldmatrix.sync.aligned.m8n8.x4.shared.b16 {%0,%1,%2,%3}, [%4];"
        : "=r"(r[0]), "=r"(r[1]), "=r"(r[2]), "=r"(r[3]) : "r"(a));
}
__device__ __forceinline__ void ldsm2(uint32_t* r, uint32_t a) {
    asm volatile("ldmatrix.sync.aligned.m8n8.x2.shared.b16 {%0,%1}, [%2];"
        : "=r"(r[0]), "=r"(r[1]) : "r"(a));
}
__device__ __forceinline__ void mma_f16(float* c, const uint32_t* a, const uint32_t* b) {
    asm volatile("mma.sync.aligned.m16n8k16.row.col.f32.f16.f16.f32 "
        "{%0,%1,%2,%3}, {%4,%5,%6,%7}, {%8,%9}, {%0,%1,%2,%3};"
        : "+f"(c[0]), "+f"(c[1]), "+f"(c[2]), "+f"(c[3])
        : "r"(a[0]), "r"(a[1]), "r"(a[2]), "r"(a[3]), "r"(b[0]), "r"(b[1]));
}

__device__ __forceinline__ uint32_t pack_hf2(float a, float b) {
    __half2 t;
    t.x = __float2half_rn(a);
    t.y = __float2half_rn(b);
    return *(uint32_t*)&t;
}

// --------- single-pass fp16 GEMM body: C = A * B^T -------------------------
// A (M,K) fp16, W (N,K) fp16, C (M,N) fp32. CTA 128x128, BK=32, 256 thr.
// 4-stage cp.async pipeline, smem stride 40 halves (conflict-free ldmatrix).
#define SST 40
#define MATB (128 * SST * 2)      // 10240 B per matrix
#define STG1 (2 * MATB)           // 20480 B per stage (A, B)
#define GEMM_SMEM (4 * STG1)      // 81920 B  -> 2 CTAs/SM

__device__ __forceinline__ void gemm_load_stage(
    uint32_t sbase, int slot,
    const __half* __restrict__ A, const __half* __restrict__ B,
    int m0, int n0, int K, int k0, int t)
{
    uint32_t st = sbase + slot * STG1;
    const __half* gp[2] = { A + (size_t)m0 * K + k0, B + (size_t)n0 * K + k0 };
    #pragma unroll
    for (int mat = 0; mat < 2; mat++) {
        #pragma unroll
        for (int h = 0; h < 2; h++) {
            int c = t + h * 256;          // 0..511
            int row = c >> 2, col16 = c & 3;
            uint32_t dst = st + mat * MATB + row * (SST*2) + col16 * 16;
            const __half* src = gp[mat] + (size_t)row * K + col16 * 8;
            CP_ASYNC16(dst, src);
        }
    }
}

__device__ __forceinline__ void gemm_body(
    uint32_t sb, const __half* __restrict__ A, const __half* __restrict__ B,
    float* __restrict__ C, int N, int K, int m0, int n0, int t)
{
    const int lane = t & 31, wid = t >> 5;
    const int warp_m = wid >> 2;
    const int warp_n = wid & 3;
    const int niter = K >> 5;

    float acc[4][4][4];
    #pragma unroll
    for (int i = 0; i < 4; i++)
        #pragma unroll
        for (int j = 0; j < 4; j++)
            acc[i][j][0] = acc[i][j][1] = acc[i][j][2] = acc[i][j][3] = 0.f;

    #pragma unroll
    for (int s = 0; s < 3; s++) {
        if (s < niter) gemm_load_stage(sb, s, A, B, m0, n0, K, s * 32, t);
        CP_COMMIT();
    }

    const int arow = warp_m * 64 + (lane & 15);
    const int acolh = (lane >> 4) * 8;
    const int l2 = lane & 15;
    const int brow = warp_n * 32 + (l2 & 7);
    const int bcolh = (l2 >> 3) * 8;

    for (int it = 0; it < niter; it++) {
        int ps = it + 3;
        if (ps < niter)
            gemm_load_stage(sb, ps & 3, A, B, m0, n0, K, ps * 32, t);
        CP_COMMIT();
        CP_WAIT2();
        __syncthreads();

        uint32_t st = sb + (it & 3) * STG1;
        #pragma unroll
        for (int ks = 0; ks < 2; ks++) {
            uint32_t af[4][4], bf[4][2];
            #pragma unroll
            for (int mt = 0; mt < 4; mt++) {
                uint32_t off = ((arow + mt * 16) * SST + ks * 16 + acolh) * 2;
                ldsm4(af[mt], st + off);
            }
            #pragma unroll
            for (int nt = 0; nt < 4; nt++) {
                uint32_t off = ((brow + nt * 8) * SST + ks * 16 + bcolh) * 2;
                ldsm2(bf[nt], st + MATB + off);
            }
            #pragma unroll
            for (int mt = 0; mt < 4; mt++)
                #pragma unroll
                for (int nt = 0; nt < 4; nt++)
                    mma_f16(acc[mt][nt], af[mt], bf[nt]);
        }
        __syncthreads();
    }

    const int r0 = lane >> 2, c0 = (lane & 3) * 2;
    #pragma unroll
    for (int mt = 0; mt < 4; mt++) {
        #pragma unroll
        for (int nt = 0; nt < 4; nt++) {
            int row = m0 + warp_m * 64 + mt * 16 + r0;
            int col = n0 + warp_n * 32 + nt * 8 + c0;
            *(float2*)(C + (size_t)row * N + col) =
                make_float2(acc[mt][nt][0], acc[mt][nt][1]);
            *(float2*)(C + (size_t)(row + 8) * N + col) =
                make_float2(acc[mt][nt][2], acc[mt][nt][3]);
        }
    }
}

// out-projection (single GEMM)
__global__ __launch_bounds__(256, 2)
void gemm_f16(const __half* __restrict__ A, const __half* __restrict__ B,
              float* __restrict__ C, int N, int K)
{
    extern __shared__ char smem[];
    gemm_body(smem_u32(smem), A, B, C, N, K,
              blockIdx.y * 128, blockIdx.x * 128, threadIdx.x);
}

// fused QKV: one launch, 1024 CTAs decode {Q:512, K:256, V:256}
__global__ __launch_bounds__(256, 2)
void gemm_qkv(const __half* __restrict__ x16,
              const __half* __restrict__ wq16, const __half* __restrict__ wk16,
              const __half* __restrict__ wv16,
              float* __restrict__ q, float* __restrict__ k, float* __restrict__ v)
{
    extern __shared__ char smem[];
    int bid = blockIdx.x;
    const __half* B;
    float* C;
    int N, m0, n0;
    if (bid < 512) {                 // Q: 16 n-tiles x 32 m-tiles
        B = wq16; C = q; N = H*HD;
        n0 = (bid & 15) * 128; m0 = (bid >> 4) * 128;
    } else if (bid < 768) {          // K: 8 x 32
        int b2 = bid - 512;
        B = wk16; C = k; N = HK*HD;
        n0 = (b2 & 7) * 128; m0 = (b2 >> 3) * 128;
    } else {                         // V: 8 x 32
        int b2 = bid - 768;
        B = wv16; C = v; N = HK*HD;
        n0 = (b2 & 7) * 128; m0 = (b2 >> 3) * 128;
    }
    gemm_body(smem_u32(smem), x16, B, C, N, DD, m0, n0, threadIdx.x);
}

// ------- fused fp32 -> fp16 conversion of all 5 tensors in one launch ------
#define N4_X  (MTOT*DD/4)          // 2097152
#define N4_WQ (H*HD*DD/4)          // 1048576
#define N4_WK (HK*HD*DD/4)         //  524288
#define N4_WV (HK*HD*DD/4)         //  524288
#define N4_WO (DD*H*HD/4)          // 1048576
#define N4_TOT (N4_X + N4_WQ + N4_WK + N4_WV + N4_WO)

__global__ __launch_bounds__(256)
void conv_all(const float* __restrict__ x,  const float* __restrict__ wq,
              const float* __restrict__ wk, const float* __restrict__ wv,
              const float* __restrict__ wo,
              __half* __restrict__ x16,  __half* __restrict__ wq16,
              __half* __restrict__ wk16, __half* __restrict__ wv16,
              __half* __restrict__ wo16)
{
    int i = blockIdx.x * blockDim.x + threadIdx.x;
    if (i >= N4_TOT) return;
    const float* src;
    __half* dst;
    int j = i;
    if (j < N4_X)                        { src = x;  dst = x16; }
    else if ((j -= N4_X)  < N4_WQ)       { src = wq; dst = wq16; }
    else if ((j -= N4_WQ) < N4_WK)       { src = wk; dst = wk16; }
    else if ((j -= N4_WK) < N4_WV)       { src = wv; dst = wv16; }
    else { j -= N4_WV;                     src = wo; dst = wo16; }
    float4 vv = ((const float4*)src)[j];
    __half2 p0, p1;
    p0.x = __float2half_rn(vv.x); p0.y = __float2half_rn(vv.y);
    p1.x = __float2half_rn(vv.z); p1.y = __float2half_rn(vv.w);
    ((__half2*)(dst + (size_t)j * 4))[0] = p0;
    ((__half2*)(dst + (size_t)j * 4))[1] = p1;
}

// ---------------- RoPE table ------------------------------------------------
__global__ void rope_table()
{
    int s = blockIdx.x;
    int j = threadIdx.x;
    double invd = pow(1.0e6, -(double)j / 64.0);
    float  ang  = (float)s * (float)invd;
    float  c, sn;
    sincosf(ang, &sn, &c);
    g_cos[s*64 + j] = c;
    g_sin[s*64 + j] = sn;
}

// -------- fused RMSNorm + RoPE -> single fp16 ------------------------------
__global__ __launch_bounds__(256)
void norm_rope_f16(const float* __restrict__ buf, __half* __restrict__ outh,
                   const float* __restrict__ w, int nheads)
{
    int gw   = (blockIdx.x * blockDim.x + threadIdx.x) >> 5;
    int lane = threadIdx.x & 31;
    int m = gw / nheads;
    int h = gw - m * nheads;
    int s = m & (SS - 1);

    size_t base = ((size_t)m * nheads + h) * HD + lane * 4;
    float4 v = *(const float4*)(buf + base);
    float ss = v.x*v.x + v.y*v.y + v.z*v.z + v.w*v.w;
    #pragma unroll
    for (int o = 16; o; o >>= 1) ss += __shfl_xor_sync(0xffffffffu, ss, o);
    float r = rsqrtf(ss * (1.f/128.f) + 1e-6f);

    const float4 wv = *(const float4*)(w + lane*4);
    v.x *= r * wv.x; v.y *= r * wv.y; v.z *= r * wv.z; v.w *= r * wv.w;

    float4 pr;
    pr.x = __shfl_xor_sync(0xffffffffu, v.x, 16);
    pr.y = __shfl_xor_sync(0xffffffffu, v.y, 16);
    pr.z = __shfl_xor_sync(0xffffffffu, v.z, 16);
    pr.w = __shfl_xor_sync(0xffffffffu, v.w, 16);

    int jbase = (lane & 15) * 4;
    const float* cb = g_cos + s*64 + jbase;
    const float* sb = g_sin + s*64 + jbase;
    float sgn = (lane < 16) ? -1.f : 1.f;

    float o0 = v.x * cb[0] + sgn * pr.x * sb[0];
    float o1 = v.y * cb[1] + sgn * pr.y * sb[1];
    float o2 = v.z * cb[2] + sgn * pr.z * sb[2];
    float o3 = v.w * cb[3] + sgn * pr.w * sb[3];

    __half2 hp0, hp1;
    hp0.x = __float2half_rn(o0); hp0.y = __float2half_rn(o1);
    hp1.x = __float2half_rn(o2); hp1.y = __float2half_rn(o3);
    ((__half2*)(outh + base))[0] = hp0;
    ((__half2*)(outh + base))[1] = hp1;
}

// ---- V transpose: [tok][hk][d] fp32 -> [b][hk][d][tok] fp16 ---------------
__global__ __launch_bounds__(256)
void transp_v16(const float* __restrict__ v, __half* __restrict__ vt)
{
    __shared__ float tile[32][33];
    int t = threadIdx.x;
    int tx = t & 31, ty = t >> 5;
    int tok0 = blockIdx.x * 32, d0 = blockIdx.y * 32;
    int bh = blockIdx.z;
    int b = bh >> 3, hk = bh & 7;

    #pragma unroll
    for (int r = 0; r < 4; r++) {
        int tok = ty + r * 8;
        tile[tok][tx] = v[((size_t)(b*SS + tok0 + tok) * HK + hk) * HD + d0 + tx];
    }
    __syncthreads();
    #pragma unroll
    for (int r = 0; r < 4; r++) {
        int d = ty + r * 8;
        size_t idx = ((size_t)(b*HK + hk) * HD + d0 + d) * SS + tok0 + tx;
        vt[idx] = __float2half_rn(tile[tx][d]);
    }
}

// ---------------- mma.sync flash attention (causal, GQA rep=2) -------------
// All operands single fp16. 128 q rows/CTA, 8 warps x 16 rows, 64-key tiles.
#define KST 136                    // K/Q smem stride (halves)
#define VSTR 72                    // V^T smem stride (halves)
#define KMAT (64 * KST * 2)        // 17408 B (64-row K tile)
#define QMAT (128 * KST * 2)       // 34816 B (Q area)
#define VMAT (128 * VSTR * 2)      // 18432 B
#define ASTG (KMAT + VMAT)         // 35840 B per stage
#define ATT_SMEM (QMAT + 2 * ASTG) // 106496 B

__global__ __launch_bounds__(256, 1)
void attn_mma(const __half* __restrict__ q16, const __half* __restrict__ k16,
              const __half* __restrict__ vt16, __half* __restrict__ o16)
{
    extern __shared__ char smem[];
    const uint32_t sb = smem_u32(smem);
    const int t = threadIdx.x, lane = t & 31, w = t >> 5;
    const int b = blockIdx.z, h = blockIdx.y;
    const int qblk = (int)gridDim.x - 1 - (int)blockIdx.x;   // heavy tiles first
    const int hk = h >> 1, q0 = qblk * 128;
    const int ntiles = 2 * qblk + 2;
    const float scale = 0.08838834764831845f;

    const __half* kb_g = k16 + ((size_t)(b*SS) * HK + hk) * HD;
    const __half* vb_g = vt16 + (size_t)(b*HK + hk) * HD * SS;

    // ---- Q into dedicated area ----
    {
        const __half* qs = q16 + ((size_t)(b*SS + q0) * H + h) * HD;
        #pragma unroll
        for (int i = 0; i < 8; i++) {
            int idx = t + i * 256;            // 0..2047
            int row = idx >> 4, c = idx & 15;
            CP_ASYNC16(sb + row * (KST*2) + c * 16, qs + (size_t)row * (H*HD) + c * 8);
        }
        CP_COMMIT();
    }
    // stage 0 (kt=0)
    {
        uint32_t st = sb + QMAT;
        #pragma unroll
        for (int i = 0; i < 4; i++) {
            int idx = t + i * 256;            // 0..1023
            int row = idx >> 4, c = idx & 15;
            CP_ASYNC16(st + row * (KST*2) + c * 16, kb_g + (size_t)row * (HK*HD) + c * 8);
            int vrow = idx >> 3, vc = idx & 7;
            CP_ASYNC16(st + KMAT + vrow * (VSTR*2) + vc * 16, vb_g + (size_t)vrow * SS + vc * 8);
        }
        CP_COMMIT();
    }
    CP_WAIT1();      // Q group done
    __syncthreads();

    // extract Q fragments
    uint32_t qf[8][4];
    {
        uint32_t roff = (w * 16 + (lane & 15)) * (KST*2) + ((lane >> 4) & 1) * 16;
        #pragma unroll
        for (int ks = 0; ks < 8; ks++)
            ldsm4(qf[ks], sb + roff + ks * 32);
    }
    // stage 1 (kt=1)
    {
        uint32_t st = sb + QMAT + ASTG;
        const __half* ksh = kb_g + (size_t)64 * (HK*HD);
        #pragma unroll
        for (int i = 0; i < 4; i++) {
            int idx = t + i * 256;
            int row = idx >> 4, c = idx & 15;
            CP_ASYNC16(st + row * (KST*2) + c * 16, ksh + (size_t)row * (HK*HD) + c * 8);
            int vrow = idx >> 3, vc = idx & 7;
            CP_ASYNC16(st + KMAT + vrow * (VSTR*2) + vc * 16, vb_g + (size_t)vrow * SS + 64 + vc * 8);
        }
        CP_COMMIT();
    }

    float oacc[16][4];
    #pragma unroll
    for (int i = 0; i < 16; i++) oacc[i][0] = oacc[i][1] = oacc[i][2] = oacc[i][3] = 0.f;
    float m0 = -1e30f, m1 = -1e30f, l0 = 0.f, l1 = 0.f;

    const int gr0 = q0 + w * 16 + (lane >> 2);
    const int gc_base = (lane & 3) * 2;

    for (int kt = 0; kt < ntiles; kt++) {
        if (kt + 1 < ntiles) { CP_WAIT1(); } else { CP_WAIT0(); }
        __syncthreads();
        uint32_t st = sb + QMAT + (kt & 1) * ASTG;

        // ---- S = Q K^T ----
        float s[8][4];
        #pragma unroll
        for (int i = 0; i < 8; i++) s[i][0] = s[i][1] = s[i][2] = s[i][3] = 0.f;

        #pragma unroll
        for (int ks = 0; ks < 8; ks++) {
            uint32_t lrow = (lane & 7) + ((lane >> 4) << 3);
            uint32_t lcol = (ks * 16 + ((lane >> 3) & 1) * 8) * 2;
            #pragma unroll
            for (int p = 0; p < 4; p++) {
                uint32_t kf[4];
                ldsm4(kf, st + (p * 16 + lrow) * (KST*2) + lcol);
                mma_f16(s[2*p],   qf[ks], &kf[0]);
                mma_f16(s[2*p+1], qf[ks], &kf[2]);
            }
        }

        // ---- softmax (fp32, warp-local rows) ----
        const int kc0 = kt * 64;
        bool fullok = (kc0 + 63 <= q0 + w * 16);
        #pragma unroll
        for (int nt = 0; nt < 8; nt++) {
            if (fullok) {
                s[nt][0] *= scale; s[nt][1] *= scale; s[nt][2] *= scale; s[nt][3] *= scale;
            } else {
                int gc = kc0 + nt * 8 + gc_base;
                s[nt][0] = (gc     <= gr0    ) ? s[nt][0] * scale : -1e30f;
                s[nt][1] = (gc + 1 <= gr0    ) ? s[nt][1] * scale : -1e30f;
                s[nt][2] = (gc     <= gr0 + 8) ? s[nt][2] * scale : -1e30f;
                s[nt][3] = (gc + 1 <= gr0 + 8) ? s[nt][3] * scale : -1e30f;
            }
        }
        float mx0 = -1e30f, mx1 = -1e30f;
        #pragma unroll
        for (int nt = 0; nt < 8; nt++) {
            mx0 = fmaxf(mx0, fmaxf(s[nt][0], s[nt][1]));
            mx1 = fmaxf(mx1, fmaxf(s[nt][2], s[nt][3]));
        }
        #pragma unroll
        for (int o = 1; o <= 2; o <<= 1) {
            mx0 = fmaxf(mx0, __shfl_xor_sync(0xffffffffu, mx0, o));
            mx1 = fmaxf(mx1, __shfl_xor_sync(0xffffffffu, mx1, o));
        }
        float mn0 = fmaxf(m0, mx0), mn1 = fmaxf(m1, mx1);
        float cr0 = __expf(m0 - mn0), cr1 = __expf(m1 - mn1);
        m0 = mn0; m1 = mn1;
        #pragma unroll
        for (int nt = 0; nt < 16; nt++) {
            oacc[nt][0] *= cr0; oacc[nt][1] *= cr0;
            oacc[nt][2] *= cr1; oacc[nt][3] *= cr1;
        }

        uint32_t pf[4][4];
        float sum0 = 0.f, sum1 = 0.f;
        #pragma unroll
        for (int nt = 0; nt < 8; nt++) {
            float p0 = __expf(s[nt][0] - mn0);
            float p1 = __expf(s[nt][1] - mn0);
            float p2 = __expf(s[nt][2] - mn1);
            float p3 = __expf(s[nt][3] - mn1);
            sum0 += p0 + p1; sum1 += p2 + p3;
            int j = nt >> 1, hi2 = (nt & 1) * 2;
            pf[j][hi2]     = pack_hf2(p0, p1);
            pf[j][hi2 + 1] = pack_hf2(p2, p3);
        }
        #pragma unroll
        for (int o = 1; o <= 2; o <<= 1) {
            sum0 += __shfl_xor_sync(0xffffffffu, sum0, o);
            sum1 += __shfl_xor_sync(0xffffffffu, sum1, o);
        }
        l0 = l0 * cr0 + sum0;
        l1 = l1 * cr1 + sum1;

        // ---- O += P V ; V^T tile [128 d][64 keys] ----
        uint32_t vst = st + KMAT;
        #pragma unroll
        for (int ks = 0; ks < 4; ks++) {
            uint32_t lrow = (lane & 7) + ((lane >> 4) << 3);
            uint32_t lcol = (ks * 16 + ((lane >> 3) & 1) * 8) * 2;
            #pragma unroll
            for (int p = 0; p < 8; p++) {
                uint32_t vb[4];
                ldsm4(vb, vst + (p * 16 + lrow) * (VSTR*2) + lcol);
                mma_f16(oacc[2*p],   pf[ks], &vb[0]);
                mma_f16(oacc[2*p+1], pf[ks], &vb[2]);
            }
        }

        __syncthreads();
        // prefetch kt+2
        if (kt + 2 < ntiles) {
            uint32_t st2 = sb + QMAT + (kt & 1) * ASTG;
            int kc = (kt + 2) * 64;
            const __half* ksh = kb_g + (size_t)kc * (HK*HD);
            #pragma unroll
            for (int i = 0; i < 4; i++) {
                int idx = t + i * 256;
                int row = idx >> 4, c = idx & 15;
                CP_ASYNC16(st2 + row * (KST*2) + c * 16, ksh + (size_t)row * (HK*HD) + c * 8);
                int vrow = idx >> 3, vc = idx & 7;
                CP_ASYNC16(st2 + KMAT + vrow * (VSTR*2) + vc * 16, vb_g + (size_t)vrow * SS + kc + vc * 8);
            }
        }
        CP_COMMIT();
    }

    // ---- epilogue: normalize, write single fp16 O ----
    float inv0 = 1.f / l0, inv1 = 1.f / l1;
    size_t obase = ((size_t)(b*SS + q0 + w*16 + (lane >> 2)) * H + h) * HD;
    #pragma unroll
    for (int nt = 0; nt < 16; nt++) {
        int d = nt * 8 + gc_base;
        *(uint32_t*)(o16 + obase + d) =
            pack_hf2(oacc[nt][0] * inv0, oacc[nt][1] * inv0);
        *(uint32_t*)(o16 + obase + (size_t)8 * H * HD + d) =
            pack_hf2(oacc[nt][2] * inv1, oacc[nt][3] * inv1);
    }
}

// ---------------- launch ----------------------------------------------------
extern "C" void kernel_launch(void* const* d_in, const int* in_sizes, int n_in,
                              void* d_out, int out_size)
{
    (void)in_sizes; (void)n_in; (void)out_size;
    const float* x  = (const float*)d_in[0];
    const float* wq = (const float*)d_in[1];
    const float* wk = (const float*)d_in[2];
    const float* wv = (const float*)d_in[3];
    const float* wo = (const float*)d_in[4];
    const float* qw = (const float*)d_in[5];
    const float* kw = (const float*)d_in[6];
    float* out = (float*)d_out;

    float *q, *k, *v;
    cudaGetSymbolAddress((void**)&q, g_q);
    cudaGetSymbolAddress((void**)&k, g_k);
    cudaGetSymbolAddress((void**)&v, g_v);

    __half *x16, *wq16, *wk16, *wv16, *wo16, *o16, *q16, *k16, *vt16;
    cudaGetSymbolAddress((void**)&x16,  g_x16);
    cudaGetSymbolAddress((void**)&wq16, g_wq16); cudaGetSymbolAddress((void**)&wk16, g_wk16);
    cudaGetSymbolAddress((void**)&wv16, g_wv16); cudaGetSymbolAddress((void**)&wo16, g_wo16);
    cudaGetSymbolAddress((void**)&o16,  g_o16);  cudaGetSymbolAddress((void**)&q16,  g_q16);
    cudaGetSymbolAddress((void**)&k16,  g_k16);  cudaGetSymbolAddress((void**)&vt16, g_vt16);

    cudaFuncSetAttribute(gemm_f16, cudaFuncAttributeMaxDynamicSharedMemorySize, GEMM_SMEM);
    cudaFuncSetAttribute(gemm_qkv, cudaFuncAttributeMaxDynamicSharedMemorySize, GEMM_SMEM);
    cudaFuncSetAttribute(attn_mma, cudaFuncAttributeMaxDynamicSharedMemorySize, ATT_SMEM);

    // all fp32->fp16 conversions in one launch
    conv_all<<<(N4_TOT + 255)/256, 256>>>(x, wq, wk, wv, wo,
                                          x16, wq16, wk16, wv16, wo16);
    rope_table<<<SS, 64>>>();

    // fused QKV projections (one launch, no inter-GEMM wave quantization)
    gemm_qkv<<<1024, 256, GEMM_SMEM>>>(x16, wq16, wk16, wv16, q, k, v);

    // RMSNorm + RoPE -> single fp16
    norm_rope_f16<<<(MTOT*H )/8, 256>>>(q, q16, qw, H);
    norm_rope_f16<<<(MTOT*HK)/8, 256>>>(k, k16, kw, HK);
    transp_v16<<<dim3(SS/32, HD/32, BB*HK), 256>>>(v, vt16);

    // causal attention on tensor cores
    attn_mma<<<dim3(SS/128, H, BB), 256, ATT_SMEM>>>(q16, k16, vt16, o16);

    // output projection
    gemm_f16<<<dim3(DD/128, MTOT/128), 256, GEMM_SMEM>>>(o16, wo16, out, DD, H*HD);
}

// round 12
// speedup vs baseline: 6.0218x; 1.0001x over previous
#include <cuda_runtime.h>
#include <cuda_fp16.h>
#include <math.h>
#include <stdint.h>

#define BB 2
#define SS 2048
#define DD 2048
#define H 16
#define HK 8
#define HD 128
#define MTOT (BB*SS)   // 4096

// ---------------- scratch (allocation-free: device globals) ----------------
__device__ float g_q[(size_t)MTOT * H * HD];
__device__ float g_k[(size_t)MTOT * HK * HD];
__device__ float g_v[(size_t)MTOT * HK * HD];
__device__ float g_cos[SS * 64];
__device__ float g_sin[SS * 64];

__device__ __align__(16) __half g_x16[(size_t)MTOT * DD];
__device__ __align__(16) __half g_wq16[(size_t)(H*HD) * DD];
__device__ __align__(16) __half g_wk16[(size_t)(HK*HD) * DD];
__device__ __align__(16) __half g_wv16[(size_t)(HK*HD) * DD];
__device__ __align__(16) __half g_wo16[(size_t)DD * (H*HD)];
__device__ __align__(16) __half g_o16[(size_t)MTOT * (H*HD)];
__device__ __align__(16) __half g_q16[(size_t)MTOT * H * HD];
__device__ __align__(16) __half g_k16[(size_t)MTOT * HK * HD];
__device__ __align__(16) __half g_vt16[(size_t)MTOT * HK * HD];  // [b][hk][d][tok]

// ---------------- asm helpers ----------------------------------------------
__device__ __forceinline__ uint32_t smem_u32(const void* p) {
    uint32_t a;
    asm("{ .reg .u64 t; cvta.to.shared.u64 t, %1; cvt.u32.u64 %0, t; }" : "=r"(a) : "l"(p));
    return a;
}

#define CP_ASYNC16(dst, src) \
    asm volatile("cp.async.cg.shared.global [%0], [%1], 16;" :: "r"(dst), "l"(src))
#define CP_COMMIT() asm volatile("cp.async.commit_group;" ::: "memory")
#define CP_WAIT2()  asm volatile("cp.async.wait_group 2;" ::: "memory")
#define CP_WAIT1()  asm volatile("cp.async.wait_group 1;" ::: "memory")
#define CP_WAIT0()  asm volatile("cp.async.wait_group 0;" ::: "memory")

__device__ __forceinline__ void ldsm4(uint32_t* r, uint32_t a) {
    asm volatile("ldmatrix.sync.aligned.m8n8.x4.shared.b16 {%0,%1,%2,%3}, [%4];"
        : "=r"(r[0]), "=r"(r[1]), "=r"(r[2]), "=r"(r[3]) : "r"(a));
}
__device__ __forceinline__ void ldsm2(uint32_t* r, uint32_t a) {
    asm volatile("ldmatrix.sync.aligned.m8n8.x2.shared.b16 {%0,%1}, [%2];"
        : "=r"(r[0]), "=r"(r[1]) : "r"(a));
}
__device__ __forceinline__ void mma_f16(float* c, const uint32_t* a, const uint32_t* b) {
    asm volatile("mma.sync.aligned.m16n8k16.row.col.f32.f16.f16.f32 "
        "{%0,%1,%2,%3}, {%4,%5,%6,%7}, {%8,%9}, {%0,%1,%2,%3};"
        : "+f"(c[0]), "+f"(c[1]), "+f"(c[2]), "+f"(c[3])
        : "r"(a[0]), "r"(a[1]), "r"(a[2]), "r"(a[3]), "r"(b[0]), "r"(b[1]));
}

__device__ __forceinline__ uint32_t pack_hf2(float a, float b) {
    __half2 t;
    t.x = __float2half_rn(a);
    t.y = __float2half_rn(b);
    return *(uint32_t*)&t;
}

// --------- single-pass fp16 GEMM body: C = A * B^T -------------------------
// A (M,K) fp16, W (N,K) fp16, C (M,N) fp32. CTA 128x128, BK=32, 256 thr.
// 4-stage cp.async pipeline, smem stride 40 halves (conflict-free ldmatrix).
#define SST 40
#define MATB (128 * SST * 2)      // 10240 B per matrix
#define STG1 (2 * MATB)           // 20480 B per stage (A, B)
#define GEMM_SMEM (4 * STG1)      // 81920 B  -> 2 CTAs/SM

__device__ __forceinline__ void gemm_load_stage(
    uint32_t sbase, int slot,
    const __half* __restrict__ A, const __half* __restrict__ B,
    int m0, int n0, int K, int k0, int t)
{
    uint32_t st = sbase + slot * STG1;
    const __half* gp[2] = { A + (size_t)m0 * K + k0, B + (size_t)n0 * K + k0 };
    #pragma unroll
    for (int mat = 0; mat < 2; mat++) {
        #pragma unroll
        for (int h = 0; h < 2; h++) {
            int c = t + h * 256;          // 0..511
            int row = c >> 2, col16 = c & 3;
            uint32_t dst = st + mat * MATB + row * (SST*2) + col16 * 16;
            const __half* src = gp[mat] + (size_t)row * K + col16 * 8;
            CP_ASYNC16(dst, src);
        }
    }
}

__device__ __forceinline__ void gemm_body(
    uint32_t sb, const __half* __restrict__ A, const __half* __restrict__ B,
    float* __restrict__ C, int N, int K, int m0, int n0, int t)
{
    const int lane = t & 31, wid = t >> 5;
    const int warp_m = wid >> 2;
    const int warp_n = wid & 3;
    const int niter = K >> 5;

    float acc[4][4][4];
    #pragma unroll
    for (int i = 0; i < 4; i++)
        #pragma unroll
        for (int j = 0; j < 4; j++)
            acc[i][j][0] = acc[i][j][1] = acc[i][j][2] = acc[i][j][3] = 0.f;

    #pragma unroll
    for (int s = 0; s < 3; s++) {
        if (s < niter) gemm_load_stage(sb, s, A, B, m0, n0, K, s * 32, t);
        CP_COMMIT();
    }

    const int arow = warp_m * 64 + (lane & 15);
    const int acolh = (lane >> 4) * 8;
    const int l2 = lane & 15;
    const int brow = warp_n * 32 + (l2 & 7);
    const int bcolh = (l2 >> 3) * 8;

    for (int it = 0; it < niter; it++) {
        int ps = it + 3;
        if (ps < niter)
            gemm_load_stage(sb, ps & 3, A, B, m0, n0, K, ps * 32, t);
        CP_COMMIT();
        CP_WAIT2();
        __syncthreads();

        uint32_t st = sb + (it & 3) * STG1;
        #pragma unroll
        for (int ks = 0; ks < 2; ks++) {
            uint32_t af[4][4], bf[4][2];
            #pragma unroll
            for (int mt = 0; mt < 4; mt++) {
                uint32_t off = ((arow + mt * 16) * SST + ks * 16 + acolh) * 2;
                ldsm4(af[mt], st + off);
            }
            #pragma unroll
            for (int nt = 0; nt < 4; nt++) {
                uint32_t off = ((brow + nt * 8) * SST + ks * 16 + bcolh) * 2;
                ldsm2(bf[nt], st + MATB + off);
            }
            #pragma unroll
            for (int mt = 0; mt < 4; mt++)
                #pragma unroll
                for (int nt = 0; nt < 4; nt++)
                    mma_f16(acc[mt][nt], af[mt], bf[nt]);
        }
        __syncthreads();
    }

    const int r0 = lane >> 2, c0 = (lane & 3) * 2;
    #pragma unroll
    for (int mt = 0; mt < 4; mt++) {
        #pragma unroll
        for (int nt = 0; nt < 4; nt++) {
            int row = m0 + warp_m * 64 + mt * 16 + r0;
            int col = n0 + warp_n * 32 + nt * 8 + c0;
            *(float2*)(C + (size_t)row * N + col) =
                make_float2(acc[mt][nt][0], acc[mt][nt][1]);
            *(float2*)(C + (size_t)(row + 8) * N + col) =
                make_float2(acc[mt][nt][2], acc[mt][nt][3]);
        }
    }
}

// out-projection (single GEMM)
__global__ __launch_bounds__(256, 2)
void gemm_f16(const __half* __restrict__ A, const __half* __restrict__ B,
              float* __restrict__ C, int N, int K)
{
    extern __shared__ char smem[];
    gemm_body(smem_u32(smem), A, B, C, N, K,
              blockIdx.y * 128, blockIdx.x * 128, threadIdx.x);
}

// fused QKV: one launch, 1024 CTAs decode {Q:512, K:256, V:256}
__global__ __launch_bounds__(256, 2)
void gemm_qkv(const __half* __restrict__ x16,
              const __half* __restrict__ wq16, const __half* __restrict__ wk16,
              const __half* __restrict__ wv16,
              float* __restrict__ q, float* __restrict__ k, float* __restrict__ v)
{
    extern __shared__ char smem[];
    int bid = blockIdx.x;
    const __half* B;
    float* C;
    int N, m0, n0;
    if (bid < 512) {                 // Q: 16 n-tiles x 32 m-tiles
        B = wq16; C = q; N = H*HD;
        n0 = (bid & 15) * 128; m0 = (bid >> 4) * 128;
    } else if (bid < 768) {          // K: 8 x 32
        int b2 = bid - 512;
        B = wk16; C = k; N = HK*HD;
        n0 = (b2 & 7) * 128; m0 = (b2 >> 3) * 128;
    } else {                         // V: 8 x 32
        int b2 = bid - 768;
        B = wv16; C = v; N = HK*HD;
        n0 = (b2 & 7) * 128; m0 = (b2 >> 3) * 128;
    }
    gemm_body(smem_u32(smem), x16, B, C, N, DD, m0, n0, threadIdx.x);
}

// ------- fused fp32 -> fp16 conversion of all 5 tensors in one launch ------
#define N4_X  (MTOT*DD/4)          // 2097152
#define N4_WQ (H*HD*DD/4)          // 1048576
#define N4_WK (HK*HD*DD/4)         //  524288
#define N4_WV (HK*HD*DD/4)         //  524288
#define N4_WO (DD*H*HD/4)          // 1048576
#define N4_TOT (N4_X + N4_WQ + N4_WK + N4_WV + N4_WO)

__global__ __launch_bounds__(256)
void conv_all(const float* __restrict__ x,  const float* __restrict__ wq,
              const float* __restrict__ wk, const float* __restrict__ wv,
              const float* __restrict__ wo,
              __half* __restrict__ x16,  __half* __restrict__ wq16,
              __half* __restrict__ wk16, __half* __restrict__ wv16,
              __half* __restrict__ wo16)
{
    int i = blockIdx.x * blockDim.x + threadIdx.x;
    if (i >= N4_TOT) return;
    const float* src;
    __half* dst;
    int j = i;
    if (j < N4_X)                        { src = x;  dst = x16; }
    else if ((j -= N4_X)  < N4_WQ)       { src = wq; dst = wq16; }
    else if ((j -= N4_WQ) < N4_WK)       { src = wk; dst = wk16; }
    else if ((j -= N4_WK) < N4_WV)       { src = wv; dst = wv16; }
    else { j -= N4_WV;                     src = wo; dst = wo16; }
    float4 vv = ((const float4*)src)[j];
    __half2 p0, p1;
    p0.x = __float2half_rn(vv.x); p0.y = __float2half_rn(vv.y);
    p1.x = __float2half_rn(vv.z); p1.y = __float2half_rn(vv.w);
    ((__half2*)(dst + (size_t)j * 4))[0] = p0;
    ((__half2*)(dst + (size_t)j * 4))[1] = p1;
}

// ---------------- RoPE table ------------------------------------------------
__global__ void rope_table()
{
    int s = blockIdx.x;
    int j = threadIdx.x;
    double invd = pow(1.0e6, -(double)j / 64.0);
    float  ang  = (float)s * (float)invd;
    float  c, sn;
    sincosf(ang, &sn, &c);
    g_cos[s*64 + j] = c;
    g_sin[s*64 + j] = sn;
}

// -------- fused RMSNorm + RoPE -> single fp16 ------------------------------
__global__ __launch_bounds__(256)
void norm_rope_f16(const float* __restrict__ buf, __half* __restrict__ outh,
                   const float* __restrict__ w, int nheads)
{
    int gw   = (blockIdx.x * blockDim.x + threadIdx.x) >> 5;
    int lane = threadIdx.x & 31;
    int m = gw / nheads;
    int h = gw - m * nheads;
    int s = m & (SS - 1);

    size_t base = ((size_t)m * nheads + h) * HD + lane * 4;
    float4 v = *(const float4*)(buf + base);
    float ss = v.x*v.x + v.y*v.y + v.z*v.z + v.w*v.w;
    #pragma unroll
    for (int o = 16; o; o >>= 1) ss += __shfl_xor_sync(0xffffffffu, ss, o);
    float r = rsqrtf(ss * (1.f/128.f) + 1e-6f);

    const float4 wv = *(const float4*)(w + lane*4);
    v.x *= r * wv.x; v.y *= r * wv.y; v.z *= r * wv.z; v.w *= r * wv.w;

    float4 pr;
    pr.x = __shfl_xor_sync(0xffffffffu, v.x, 16);
    pr.y = __shfl_xor_sync(0xffffffffu, v.y, 16);
    pr.z = __shfl_xor_sync(0xffffffffu, v.z, 16);
    pr.w = __shfl_xor_sync(0xffffffffu, v.w, 16);

    int jbase = (lane & 15) * 4;
    const float* cb = g_cos + s*64 + jbase;
    const float* sb = g_sin + s*64 + jbase;
    float sgn = (lane < 16) ? -1.f : 1.f;

    float o0 = v.x * cb[0] + sgn * pr.x * sb[0];
    float o1 = v.y * cb[1] + sgn * pr.y * sb[1];
    float o2 = v.z * cb[2] + sgn * pr.z * sb[2];
    float o3 = v.w * cb[3] + sgn * pr.w * sb[3];

    __half2 hp0, hp1;
    hp0.x = __float2half_rn(o0); hp0.y = __float2half_rn(o1);
    hp1.x = __float2half_rn(o2); hp1.y = __float2half_rn(o3);
    ((__half2*)(outh + base))[0] = hp0;
    ((__half2*)(outh + base))[1] = hp1;
}

// ---- V transpose: [tok][hk][d] fp32 -> [b][hk][d][tok] fp16 ---------------
__global__ __launch_bounds__(256)
void transp_v16(const float* __restrict__ v, __half* __restrict__ vt)
{
    __shared__ float tile[32][33];
    int t = threadIdx.x;
    int tx = t & 31, ty = t >> 5;
    int tok0 = blockIdx.x * 32, d0 = blockIdx.y * 32;
    int bh = blockIdx.z;
    int b = bh >> 3, hk = bh & 7;

    #pragma unroll
    for (int r = 0; r < 4; r++) {
        int tok = ty + r * 8;
        tile[tok][tx] = v[((size_t)(b*SS + tok0 + tok) * HK + hk) * HD + d0 + tx];
    }
    __syncthreads();
    #pragma unroll
    for (int r = 0; r < 4; r++) {
        int d = ty + r * 8;
        size_t idx = ((size_t)(b*HK + hk) * HD + d0 + d) * SS + tok0 + tx;
        vt[idx] = __float2half_rn(tile[tx][d]);
    }
}

// ---------------- mma.sync flash attention (causal, GQA rep=2) -------------
// All operands single fp16. 128 q rows/CTA, 8 warps x 16 rows, 64-key tiles.
#define KST 136                    // K/Q smem stride (halves)
#define VSTR 72                    // V^T smem stride (halves)
#define KMAT (64 * KST * 2)        // 17408 B (64-row K tile)
#define QMAT (128 * KST * 2)       // 34816 B (Q area)
#define VMAT (128 * VSTR * 2)      // 18432 B
#define ASTG (KMAT + VMAT)         // 35840 B per stage
#define ATT_SMEM (QMAT + 2 * ASTG) // 106496 B

__global__ __launch_bounds__(256, 1)
void attn_mma(const __half* __restrict__ q16, const __half* __restrict__ k16,
              const __half* __restrict__ vt16, __half* __restrict__ o16)
{
    extern __shared__ char smem[];
    const uint32_t sb = smem_u32(smem);
    const int t = threadIdx.x, lane = t & 31, w = t >> 5;
    const int b = blockIdx.z, h = blockIdx.y;
    const int qblk = (int)gridDim.x - 1 - (int)blockIdx.x;   // heavy tiles first
    const int hk = h >> 1, q0 = qblk * 128;
    const int ntiles = 2 * qblk + 2;
    const float scale = 0.08838834764831845f;

    const __half* kb_g = k16 + ((size_t)(b*SS) * HK + hk) * HD;
    const __half* vb_g = vt16 + (size_t)(b*HK + hk) * HD * SS;

    // ---- Q into dedicated area ----
    {
        const __half* qs = q16 + ((size_t)(b*SS + q0) * H + h) * HD;
        #pragma unroll
        for (int i = 0; i < 8; i++) {
            int idx = t + i * 256;            // 0..2047
            int row = idx >> 4, c = idx & 15;
            CP_ASYNC16(sb + row * (KST*2) + c * 16, qs + (size_t)row * (H*HD) + c * 8);
        }
        CP_COMMIT();
    }
    // stage 0 (kt=0)
    {
        uint32_t st = sb + QMAT;
        #pragma unroll
        for (int i = 0; i < 4; i++) {
            int idx = t + i * 256;            // 0..1023
            int row = idx >> 4, c = idx & 15;
            CP_ASYNC16(st + row * (KST*2) + c * 16, kb_g + (size_t)row * (HK*HD) + c * 8);
            int vrow = idx >> 3, vc = idx & 7;
            CP_ASYNC16(st + KMAT + vrow * (VSTR*2) + vc * 16, vb_g + (size_t)vrow * SS + vc * 8);
        }
        CP_COMMIT();
    }
    CP_WAIT1();      // Q group done
    __syncthreads();

    // extract Q fragments
    uint32_t qf[8][4];
    {
        uint32_t roff = (w * 16 + (lane & 15)) * (KST*2) + ((lane >> 4) & 1) * 16;
        #pragma unroll
        for (int ks = 0; ks < 8; ks++)
            ldsm4(qf[ks], sb + roff + ks * 32);
    }
    // stage 1 (kt=1)
    {
        uint32_t st = sb + QMAT + ASTG;
        const __half* ksh = kb_g + (size_t)64 * (HK*HD);
        #pragma unroll
        for (int i = 0; i < 4; i++) {
            int idx = t + i * 256;
            int row = idx >> 4, c = idx & 15;
            CP_ASYNC16(st + row * (KST*2) + c * 16, ksh + (size_t)row * (HK*HD) + c * 8);
            int vrow = idx >> 3, vc = idx & 7;
            CP_ASYNC16(st + KMAT + vrow * (VSTR*2) + vc * 16, vb_g + (size_t)vrow * SS + 64 + vc * 8);
        }
        CP_COMMIT();
    }

    float oacc[16][4];
    #pragma unroll
    for (int i = 0; i < 16; i++) oacc[i][0] = oacc[i][1] = oacc[i][2] = oacc[i][3] = 0.f;
    float m0 = -1e30f, m1 = -1e30f, l0 = 0.f, l1 = 0.f;

    const int gr0 = q0 + w * 16 + (lane >> 2);
    const int gc_base = (lane & 3) * 2;

    for (int kt = 0; kt < ntiles; kt++) {
        if (kt + 1 < ntiles) { CP_WAIT1(); } else { CP_WAIT0(); }
        __syncthreads();
        uint32_t st = sb + QMAT + (kt & 1) * ASTG;

        // ---- S = Q K^T ----
        float s[8][4];
        #pragma unroll
        for (int i = 0; i < 8; i++) s[i][0] = s[i][1] = s[i][2] = s[i][3] = 0.f;

        #pragma unroll
        for (int ks = 0; ks < 8; ks++) {
            uint32_t lrow = (lane & 7) + ((lane >> 4) << 3);
            uint32_t lcol = (ks * 16 + ((lane >> 3) & 1) * 8) * 2;
            #pragma unroll
            for (int p = 0; p < 4; p++) {
                uint32_t kf[4];
                ldsm4(kf, st + (p * 16 + lrow) * (KST*2) + lcol);
                mma_f16(s[2*p],   qf[ks], &kf[0]);
                mma_f16(s[2*p+1], qf[ks], &kf[2]);
            }
        }

        // ---- softmax (fp32, warp-local rows) ----
        const int kc0 = kt * 64;
        bool fullok = (kc0 + 63 <= q0 + w * 16);
        #pragma unroll
        for (int nt = 0; nt < 8; nt++) {
            if (fullok) {
                s[nt][0] *= scale; s[nt][1] *= scale; s[nt][2] *= scale; s[nt][3] *= scale;
            } else {
                int gc = kc0 + nt * 8 + gc_base;
                s[nt][0] = (gc     <= gr0    ) ? s[nt][0] * scale : -1e30f;
                s[nt][1] = (gc + 1 <= gr0    ) ? s[nt][1] * scale : -1e30f;
                s[nt][2] = (gc     <= gr0 + 8) ? s[nt][2] * scale : -1e30f;
                s[nt][3] = (gc + 1 <= gr0 + 8) ? s[nt][3] * scale : -1e30f;
            }
        }
        float mx0 = -1e30f, mx1 = -1e30f;
        #pragma unroll
        for (int nt = 0; nt < 8; nt++) {
            mx0 = fmaxf(mx0, fmaxf(s[nt][0], s[nt][1]));
            mx1 = fmaxf(mx1, fmaxf(s[nt][2], s[nt][3]));
        }
        #pragma unroll
        for (int o = 1; o <= 2; o <<= 1) {
            mx0 = fmaxf(mx0, __shfl_xor_sync(0xffffffffu, mx0, o));
            mx1 = fmaxf(mx1, __shfl_xor_sync(0xffffffffu, mx1, o));
        }
        float mn0 = fmaxf(m0, mx0), mn1 = fmaxf(m1, mx1);
        float cr0 = __expf(m0 - mn0), cr1 = __expf(m1 - mn1);
        m0 = mn0; m1 = mn1;
        #pragma unroll
        for (int nt = 0; nt < 16; nt++) {
            oacc[nt][0] *= cr0; oacc[nt][1] *= cr0;
            oacc[nt][2] *= cr1; oacc[nt][3] *= cr1;
        }

        uint32_t pf[4][4];
        float sum0 = 0.f, sum1 = 0.f;
        #pragma unroll
        for (int nt = 0; nt < 8; nt++) {
            float p0 = __expf(s[nt][0] - mn0);
            float p1 = __expf(s[nt][1] - mn0);
            float p2 = __expf(s[nt][2] - mn1);
            float p3 = __expf(s[nt][3] - mn1);
            sum0 += p0 + p1; sum1 += p2 + p3;
            int j = nt >> 1, hi2 = (nt & 1) * 2;
            pf[j][hi2]     = pack_hf2(p0, p1);
            pf[j][hi2 + 1] = pack_hf2(p2, p3);
        }
        #pragma unroll
        for (int o = 1; o <= 2; o <<= 1) {
            sum0 += __shfl_xor_sync(0xffffffffu, sum0, o);
            sum1 += __shfl_xor_sync(0xffffffffu, sum1, o);
        }
        l0 = l0 * cr0 + sum0;
        l1 = l1 * cr1 + sum1;

        // ---- O += P V ; V^T tile [128 d][64 keys] ----
        uint32_t vst = st + KMAT;
        #pragma unroll
        for (int ks = 0; ks < 4; ks++) {
            uint32_t lrow = (lane & 7) + ((lane >> 4) << 3);
            uint32_t lcol = (ks * 16 + ((lane >> 3) & 1) * 8) * 2;
            #pragma unroll
            for (int p = 0; p < 8; p++) {
                uint32_t vb[4];
                ldsm4(vb, vst + (p * 16 + lrow) * (VSTR*2) + lcol);
                mma_f16(oacc[2*p],   pf[ks], &vb[0]);
                mma_f16(oacc[2*p+1], pf[ks], &vb[2]);
            }
        }

        __syncthreads();
        // prefetch kt+2
        if (kt + 2 < ntiles) {
            uint32_t st2 = sb + QMAT + (kt & 1) * ASTG;
            int kc = (kt + 2) * 64;
            const __half* ksh = kb_g + (size_t)kc * (HK*HD);
            #pragma unroll
            for (int i = 0; i < 4; i++) {
                int idx = t + i * 256;
                int row = idx >> 4, c = idx & 15;
                CP_ASYNC16(st2 + row * (KST*2) + c * 16, ksh + (size_t)row * (HK*HD) + c * 8);
                int vrow = idx >> 3, vc = idx & 7;
                CP_ASYNC16(st2 + KMAT + vrow * (VSTR*2) + vc * 16, vb_g + (size_t)vrow * SS + kc + vc * 8);
            }
        }
        CP_COMMIT();
    }

    // ---- epilogue: normalize, write single fp16 O ----
    float inv0 = 1.f / l0, inv1 = 1.f / l1;
    size_t obase = ((size_t)(b*SS + q0 + w*16 + (lane >> 2)) * H + h) * HD;
    #pragma unroll
    for (int nt = 0; nt < 16; nt++) {
        int d = nt * 8 + gc_base;
        *(uint32_t*)(o16 + obase + d) =
            pack_hf2(oacc[nt][0] * inv0, oacc[nt][1] * inv0);
        *(uint32_t*)(o16 + obase + (size_t)8 * H * HD + d) =
            pack_hf2(oacc[nt][2] * inv1, oacc[nt][3] * inv1);
    }
}

// ---------------- launch ----------------------------------------------------
extern "C" void kernel_launch(void* const* d_in, const int* in_sizes, int n_in,
                              void* d_out, int out_size)
{
    (void)in_sizes; (void)n_in; (void)out_size;
    const float* x  = (const float*)d_in[0];
    const float* wq = (const float*)d_in[1];
    const float* wk = (const float*)d_in[2];
    const float* wv = (const float*)d_in[3];
    const float* wo = (const float*)d_in[4];
    const float* qw = (const float*)d_in[5];
    const float* kw = (const float*)d_in[6];
    float* out = (float*)d_out;

    float *q, *k, *v;
    cudaGetSymbolAddress((void**)&q, g_q);
    cudaGetSymbolAddress((void**)&k, g_k);
    cudaGetSymbolAddress((void**)&v, g_v);

    __half *x16, *wq16, *wk16, *wv16, *wo16, *o16, *q16, *k16, *vt16;
    cudaGetSymbolAddress((void**)&x16,  g_x16);
    cudaGetSymbolAddress((void**)&wq16, g_wq16); cudaGetSymbolAddress((void**)&wk16, g_wk16);
    cudaGetSymbolAddress((void**)&wv16, g_wv16); cudaGetSymbolAddress((void**)&wo16, g_wo16);
    cudaGetSymbolAddress((void**)&o16,  g_o16);  cudaGetSymbolAddress((void**)&q16,  g_q16);
    cudaGetSymbolAddress((void**)&k16,  g_k16);  cudaGetSymbolAddress((void**)&vt16, g_vt16);

    cudaFuncSetAttribute(gemm_f16, cudaFuncAttributeMaxDynamicSharedMemorySize, GEMM_SMEM);
    cudaFuncSetAttribute(gemm_qkv, cudaFuncAttributeMaxDynamicSharedMemorySize, GEMM_SMEM);
    cudaFuncSetAttribute(attn_mma, cudaFuncAttributeMaxDynamicSharedMemorySize, ATT_SMEM);

    // all fp32->fp16 conversions in one launch
    conv_all<<<(N4_TOT + 255)/256, 256>>>(x, wq, wk, wv, wo,
                                          x16, wq16, wk16, wv16, wo16);
    rope_table<<<SS, 64>>>();

    // fused QKV projections (one launch, no inter-GEMM wave quantization)
    gemm_qkv<<<1024, 256, GEMM_SMEM>>>(x16, wq16, wk16, wv16, q, k, v);

    // RMSNorm + RoPE -> single fp16
    norm_rope_f16<<<(MTOT*H )/8, 256>>>(q, q16, qw, H);
    norm_rope_f16<<<(MTOT*HK)/8, 256>>>(k, k16, kw, HK);
    transp_v16<<<dim3(SS/32, HD/32, BB*HK), 256>>>(v, vt16);

    // causal attention on tensor cores
    attn_mma<<<dim3(SS/128, H, BB), 256, ATT_SMEM>>>(q16, k16, vt16, o16);

    // output projection
    gemm_f16<<<dim3(DD/128, MTOT/128), 256, GEMM_SMEM>>>(o16, wo16, out, DD, H*HD);
}